// round 1
// baseline (speedup 1.0000x reference)
#include <cuda_runtime.h>
#include <math.h>

#define NB 64
#define NS 512
#define NH 1024
#define NM 26
#define NE 676
#define NR (NB*NM)          // 1664 node rows total
#define NOFF (NM-1)         // 25 offsets per batch

// ---------------- scratch (device globals; no allocation allowed) ----------------
__device__ int   g_off[NB*NOFF];
__device__ int   g_count[NB];
__device__ float g_cls[NB*NH];
__device__ float g_node[NR*NH];       // node_full
__device__ float g_naf[NB*NH];
__device__ float g_cdact[NB*NH];
__device__ float g_Wbig[NH*3072];     // [W_nd | W1+W3 | W2-W3]
__device__ float g_ND[NR*NH];         // tanh(node_full @ W_nd + b_nd)
__device__ float g_A[NR*NH];          // node_full @ (W1+W3)
__device__ float g_Bm[NR*NH];         // node_full @ (W2-W3)
__device__ float g_cvec[2];           // logits of an all-zero edge row

// ---------------- small helpers ----------------
__device__ __forceinline__ void block_reduce2_store(float s0, float s1,
                                                    float* o0, float* o1,
                                                    float add0, float add1) {
    __shared__ float red[16];
    #pragma unroll
    for (int o = 16; o > 0; o >>= 1) {
        s0 += __shfl_down_sync(0xffffffffu, s0, o);
        s1 += __shfl_down_sync(0xffffffffu, s1, o);
    }
    int t = threadIdx.x;
    if ((t & 31) == 0) { red[t >> 5] = s0; red[8 + (t >> 5)] = s1; }
    __syncthreads();
    if (t == 0) {
        float a = 0.f, b = 0.f;
        #pragma unroll
        for (int w = 0; w < 8; w++) { a += red[w]; b += red[8 + w]; }
        *o0 = a + add0;
        *o1 = b + add1;
    }
}

// ---------------- kernel 0: decode proof_offsets (int32 vs int64 robust) ----------------
__global__ void k_decode_off(const int* __restrict__ po) {
    // int64 little-endian with values < 512 => every odd 32-bit word is 0.
    // True int32 layout has po[1],po[3],po[5] > 0 (c >= 5 offsets guaranteed).
    bool wide = (po[1] == 0 && po[3] == 0 && po[5] == 0);
    int idx = blockIdx.x * 256 + threadIdx.x;
    if (idx < NB * NOFF) g_off[idx] = wide ? po[idx * 2] : po[idx];
}

// ---------------- kernel 1: build combined weight [W_nd | W1+W3 | W2-W3] ----------------
__global__ void k_prep_weights(const float* __restrict__ Wnd,
                               const float* __restrict__ Wed) {
    int n = blockIdx.x * 256 + threadIdx.x;   // 0..3071
    int k = blockIdx.y;                       // 0..1023
    float v;
    if (n < 1024) {
        v = Wnd[k * 1024 + n];
    } else if (n < 2048) {
        int c = n - 1024;
        v = Wed[k * 1024 + c] + Wed[(2048 + k) * 1024 + c];
    } else {
        int c = n - 2048;
        v = Wed[(1024 + k) * 1024 + c] - Wed[(2048 + k) * 1024 + c];
    }
    g_Wbig[k * 3072 + n] = v;
}

// ---------------- kernel 2: cls copy + count ----------------
__global__ void k_prep_cls(const float* __restrict__ seq) {
    int b = blockIdx.x, t = threadIdx.x;
    ((float4*)(g_cls + (size_t)b * NH))[t] =
        ((const float4*)(seq + (size_t)b * NS * NH))[t];
    if (t == 0) {
        int c = 0;
        #pragma unroll
        for (int m = 0; m < NOFF; m++) c += (g_off[b * NOFF + m] > 0);
        g_count[b] = c;
    }
}

// ---------------- kernel 3: segment means -> node_full ----------------
__global__ void k_segments(const float* __restrict__ seq) {
    int m = blockIdx.x, b = blockIdx.y, t = threadIdx.x;
    float4 acc = make_float4(0.f, 0.f, 0.f, 0.f);
    float scale = 0.f;
    if (m < NOFF) {
        int off = g_off[b * NOFF + m];
        if (off > 0) {
            int prev = (m == 0) ? 0 : g_off[b * NOFF + m - 1];
            const float4* base = (const float4*)(seq + (size_t)b * NS * NH);
            for (int s = prev + 1; s <= off; s++) {
                float4 v = base[(size_t)s * (NH / 4) + t];
                acc.x += v.x; acc.y += v.y; acc.z += v.z; acc.w += v.w;
            }
            scale = 1.f / (float)(off - prev);
        }
    }
    acc.x *= scale; acc.y *= scale; acc.z *= scale; acc.w *= scale;
    ((float4*)(g_node + (size_t)(b * NM + m) * NH))[t] = acc;
}

// ---------------- kernel 4: GEMM1  cls(64x1024) @ [W_naf | W_cd] ----------------
__global__ __launch_bounds__(256) void k_gemm1(const float* __restrict__ Wnaf,
                                               const float* __restrict__ Wcd,
                                               const float* __restrict__ bnaf,
                                               const float* __restrict__ bcd) {
    __shared__ float Xs[16 * 68];
    __shared__ float Ws[16 * 64];
    int n0 = blockIdx.x * 64;
    const float* W = (n0 < 1024) ? Wnaf : Wcd;
    int nc0 = (n0 < 1024) ? n0 : n0 - 1024;
    int t = threadIdx.x;
    int tx = t & 15, ty = t >> 4;
    float acc[4][4] = {};
    for (int kt = 0; kt < 1024; kt += 16) {
        {
            int ml = t >> 2, k4 = t & 3;
            float4 x = *(const float4*)(g_cls + (size_t)ml * NH + kt + k4 * 4);
            Xs[(k4 * 4 + 0) * 68 + ml] = x.x;
            Xs[(k4 * 4 + 1) * 68 + ml] = x.y;
            Xs[(k4 * 4 + 2) * 68 + ml] = x.z;
            Xs[(k4 * 4 + 3) * 68 + ml] = x.w;
            int kl = t >> 4, n4 = t & 15;
            float4 w = *(const float4*)(W + (size_t)(kt + kl) * 1024 + nc0 + n4 * 4);
            *(float4*)(Ws + kl * 64 + n4 * 4) = w;
        }
        __syncthreads();
        #pragma unroll
        for (int k = 0; k < 16; k++) {
            float a[4], bb[4];
            *(float4*)a  = *(const float4*)(Xs + k * 68 + ty * 4);
            *(float4*)bb = *(const float4*)(Ws + k * 64 + tx * 4);
            #pragma unroll
            for (int i = 0; i < 4; i++)
                #pragma unroll
                for (int j = 0; j < 4; j++)
                    acc[i][j] += a[i] * bb[j];
        }
        __syncthreads();
    }
    #pragma unroll
    for (int i = 0; i < 4; i++) {
        int m = ty * 4 + i;
        #pragma unroll
        for (int j = 0; j < 4; j++) {
            int n = tx * 4 + j;
            float v = acc[i][j];
            if (n0 < 1024) g_naf[(size_t)m * NH + n0 + n] = v + bnaf[n0 + n];
            else {
                int c = nc0 + n;
                g_cdact[(size_t)m * NH + c] = tanhf(v + bcd[c]);
            }
        }
    }
}

// ---------------- kernel 5: logits ----------------
__global__ void k_logits(const float* __restrict__ Wco,
                         const float* __restrict__ bco,
                         float* __restrict__ out) {
    int b = blockIdx.x, t = threadIdx.x;
    const float2* w = (const float2*)Wco;
    float s0 = 0.f, s1 = 0.f;
    for (int h = t; h < NH; h += 256) {
        float x = g_cdact[(size_t)b * NH + h];
        float2 ww = w[h];
        s0 += x * ww.x; s1 += x * ww.y;
    }
    block_reduce2_store(s0, s1, out + b * 2, out + b * 2 + 1, bco[0], bco[1]);
}

// ---------------- kernel 6: add naf at row count[b] ----------------
__global__ void k_add_naf() {
    int b = blockIdx.x, t = threadIdx.x;
    int cnt = g_count[b];
    float4* dst = (float4*)(g_node + (size_t)(b * NM + cnt) * NH);
    const float4* src = (const float4*)(g_naf + (size_t)b * NH);
    float4 d = dst[t], s = src[t];
    d.x += s.x; d.y += s.y; d.z += s.z; d.w += s.w;
    dst[t] = d;
}

// ---------------- kernel 7: big GEMM  node(1664x1024) @ Wbig(1024x3072) ----------------
__global__ __launch_bounds__(256, 2) void k_biggemm(const float* __restrict__ bnd) {
    __shared__ float Xs[2][16 * 132];
    __shared__ float Ws[2][16 * 128];
    int m0 = blockIdx.y * 128;
    int n0 = blockIdx.x * 128;
    int t = threadIdx.x;
    int tx = t & 15, ty = t >> 4;
    float acc[8][8] = {};

    int xm0 = t >> 2,          xk0 = (t & 3) * 4;
    int xm1 = (t + 256) >> 2,  xk1 = ((t + 256) & 3) * 4;
    int wk0 = t >> 5,          wn0 = (t & 31) * 4;
    int wk1 = (t + 256) >> 5,  wn1 = ((t + 256) & 31) * 4;

    float4 xr0, xr1, wr0, wr1;

    auto ldg = [&](int kt) {
        xr0 = *(const float4*)(g_node + (size_t)(m0 + xm0) * NH + kt + xk0);
        xr1 = *(const float4*)(g_node + (size_t)(m0 + xm1) * NH + kt + xk1);
        wr0 = *(const float4*)(g_Wbig + (size_t)(kt + wk0) * 3072 + n0 + wn0);
        wr1 = *(const float4*)(g_Wbig + (size_t)(kt + wk1) * 3072 + n0 + wn1);
    };
    auto sts = [&](int buf) {
        Xs[buf][(xk0 + 0) * 132 + xm0] = xr0.x;
        Xs[buf][(xk0 + 1) * 132 + xm0] = xr0.y;
        Xs[buf][(xk0 + 2) * 132 + xm0] = xr0.z;
        Xs[buf][(xk0 + 3) * 132 + xm0] = xr0.w;
        Xs[buf][(xk1 + 0) * 132 + xm1] = xr1.x;
        Xs[buf][(xk1 + 1) * 132 + xm1] = xr1.y;
        Xs[buf][(xk1 + 2) * 132 + xm1] = xr1.z;
        Xs[buf][(xk1 + 3) * 132 + xm1] = xr1.w;
        *(float4*)&Ws[buf][wk0 * 128 + wn0] = wr0;
        *(float4*)&Ws[buf][wk1 * 128 + wn1] = wr1;
    };

    ldg(0); sts(0); __syncthreads();
    for (int it = 0; it < 64; it++) {
        int buf = it & 1;
        if (it < 63) ldg((it + 1) * 16);
        #pragma unroll
        for (int k = 0; k < 16; k++) {
            float a[8], bb[8];
            *(float4*)&a[0]  = *(const float4*)&Xs[buf][k * 132 + ty * 8];
            *(float4*)&a[4]  = *(const float4*)&Xs[buf][k * 132 + ty * 8 + 4];
            *(float4*)&bb[0] = *(const float4*)&Ws[buf][k * 128 + tx * 8];
            *(float4*)&bb[4] = *(const float4*)&Ws[buf][k * 128 + tx * 8 + 4];
            #pragma unroll
            for (int i = 0; i < 8; i++)
                #pragma unroll
                for (int j = 0; j < 8; j++)
                    acc[i][j] += a[i] * bb[j];
        }
        if (it < 63) { sts(buf ^ 1); __syncthreads(); }
    }

    int sec = n0 >> 10;          // 0: W_nd, 1: WA, 2: WB
    int ncol = n0 & 1023;
    #pragma unroll
    for (int i = 0; i < 8; i++) {
        int m = m0 + ty * 8 + i;
        #pragma unroll
        for (int jv = 0; jv < 2; jv++) {
            int n = ncol + tx * 8 + jv * 4;
            float4 v = make_float4(acc[i][jv * 4 + 0], acc[i][jv * 4 + 1],
                                   acc[i][jv * 4 + 2], acc[i][jv * 4 + 3]);
            if (sec == 0) {
                v.x = tanhf(v.x + bnd[n + 0]);
                v.y = tanhf(v.y + bnd[n + 1]);
                v.z = tanhf(v.z + bnd[n + 2]);
                v.w = tanhf(v.w + bnd[n + 3]);
                *(float4*)(g_ND + (size_t)m * NH + n) = v;
            } else if (sec == 1) {
                *(float4*)(g_A + (size_t)m * NH + n) = v;
            } else {
                *(float4*)(g_Bm + (size_t)m * NH + n) = v;
            }
        }
    }
}

// ---------------- kernel 8: node logits ----------------
__global__ void k_node_logits(const float* __restrict__ Wno,
                              const float* __restrict__ bno,
                              float* __restrict__ out) {
    int r = blockIdx.x, t = threadIdx.x;
    const float2* w = (const float2*)Wno;
    float s0 = 0.f, s1 = 0.f;
    for (int h = t; h < NH; h += 256) {
        float x = g_ND[(size_t)r * NH + h];
        float2 ww = w[h];
        s0 += x * ww.x; s1 += x * ww.y;
    }
    float* o = out + 128 + (size_t)r * 2;
    block_reduce2_store(s0, s1, o, o + 1, bno[0], bno[1]);
}

// ---------------- kernel 9: constant logits for invalid edges ----------------
__global__ void k_cvec(const float* __restrict__ bed,
                       const float* __restrict__ Weo,
                       const float* __restrict__ beo) {
    int t = threadIdx.x;
    const float2* w = (const float2*)Weo;
    float s0 = 0.f, s1 = 0.f;
    for (int h = t; h < NH; h += 256) {
        float v = tanhf(bed[h]);
        float2 ww = w[h];
        s0 += v * ww.x; s1 += v * ww.y;
    }
    block_reduce2_store(s0, s1, &g_cvec[0], &g_cvec[1], beo[0], beo[1]);
}

// ---------------- kernel 10: edge logits ----------------
__global__ void k_edges(const float* __restrict__ bed,
                        const float* __restrict__ Weo,
                        const float* __restrict__ beo,
                        float* __restrict__ out) {
    int k = blockIdx.x, b = blockIdx.y, t = threadIdx.x;
    int n = g_count[b] + 1;
    float* o = out + 128 + NR * 2 + (size_t)(b * NE + k) * 2;
    if (k >= n * n) {
        if (t < 2) o[t] = g_cvec[t];
        return;
    }
    int i = k / n, j = k % n;
    const float* Ar = g_A  + (size_t)(b * NM + j) * NH;
    const float* Br = g_Bm + (size_t)(b * NM + i) * NH;
    const float2* w = (const float2*)Weo;
    float s0 = 0.f, s1 = 0.f;
    for (int h = t; h < NH; h += 256) {
        float v = tanhf(Ar[h] + Br[h] + bed[h]);
        float2 ww = w[h];
        s0 += v * ww.x; s1 += v * ww.y;
    }
    block_reduce2_store(s0, s1, o, o + 1, beo[0], beo[1]);
}

// ---------------- launch ----------------
extern "C" void kernel_launch(void* const* d_in, const int* in_sizes, int n_in,
                              void* d_out, int out_size) {
    const float* seq  = (const float*)d_in[0];
    const int*   po   = (const int*)  d_in[1];
    // d_in[2] node_labels, d_in[3] edge_labels: unused by the reference math
    const float* Wnaf = (const float*)d_in[4];
    const float* bnaf = (const float*)d_in[5];
    const float* Wcd  = (const float*)d_in[6];
    const float* bcd  = (const float*)d_in[7];
    const float* Wco  = (const float*)d_in[8];
    const float* bco  = (const float*)d_in[9];
    const float* Wnd  = (const float*)d_in[10];
    const float* bnd  = (const float*)d_in[11];
    const float* Wno  = (const float*)d_in[12];
    const float* bno  = (const float*)d_in[13];
    const float* Wed  = (const float*)d_in[14];
    const float* bed  = (const float*)d_in[15];
    const float* Weo  = (const float*)d_in[16];
    const float* beo  = (const float*)d_in[17];
    float* out = (float*)d_out;

    k_decode_off<<<7, 256>>>(po);
    k_prep_weights<<<dim3(12, 1024), 256>>>(Wnd, Wed);
    k_prep_cls<<<NB, 256>>>(seq);
    k_segments<<<dim3(NM, NB), 256>>>(seq);
    k_gemm1<<<32, 256>>>(Wnaf, Wcd, bnaf, bcd);
    k_logits<<<NB, 256>>>(Wco, bco, out);
    k_add_naf<<<NB, 256>>>();
    k_biggemm<<<dim3(24, 13), 256>>>(bnd);
    k_node_logits<<<NR, 256>>>(Wno, bno, out);
    k_cvec<<<1, 256>>>(bed, Weo, beo);
    k_edges<<<dim3(NE, NB), 256>>>(bed, Weo, beo, out);
}

// round 3
// speedup vs baseline: 1.9006x; 1.9006x over previous
#include <cuda_runtime.h>
#include <cuda_bf16.h>
#include <math.h>
#include <stdint.h>

#define NB 64
#define NS 512
#define NH 1024
#define NM 26
#define NE 676
#define NR (NB*NM)          // 1664 node rows total
#define NOFF (NM-1)         // 25 offsets per batch
#define NST 8               // S tiles of 64 rows

// ---------------- scratch (device globals; no allocation allowed) ----------------
__device__ int   g_off[NB*NOFF];
__device__ int   g_count[NB];
__device__ __align__(16) float g_cls[NB*NH];
__device__ __align__(16) float g_node[NR*NH];        // node_full (fp32)
__device__ __align__(16) float g_naf[NB*NH];
__device__ __align__(16) float g_cdact[NB*NH];
__device__ __align__(16) float g_part[NB*NST*NM*NH]; // segment tile partials
__device__ __align__(16) float g_ND[NR*NH];          // tanh(node_full @ W_nd + b_nd)
__device__ __align__(16) float g_A[NR*NH];           // node_full @ (W1+W3)
__device__ __align__(16) float g_Bm[NR*NH];          // node_full @ (W2-W3)
__device__ float g_cvec[2];
// bf16 split operands for tensor-core GEMM
__device__ __align__(16) __nv_bfloat16 g_nodeH[NR*NH];
__device__ __align__(16) __nv_bfloat16 g_nodeL[NR*NH];
__device__ __align__(16) __nv_bfloat16 g_WTh[3072*NH];  // W^T (N-major, K cols), hi
__device__ __align__(16) __nv_bfloat16 g_WTl[3072*NH];  // lo

// ============================================================================
// portable PTX helpers (no sm_103a-only features!)
// ============================================================================
__device__ __forceinline__ uint32_t smem_to_u32(const void* p) {
    uint32_t a;
    asm("{ .reg .u64 t; cvta.to.shared.u64 t, %1; cvt.u32.u64 %0, t; }" : "=r"(a) : "l"(p));
    return a;
}
__device__ __forceinline__ void ldsm_x4(uint32_t (&r)[4], uint32_t addr) {
    asm volatile("ldmatrix.sync.aligned.m8n8.x4.shared.b16 {%0,%1,%2,%3}, [%4];"
        : "=r"(r[0]), "=r"(r[1]), "=r"(r[2]), "=r"(r[3]) : "r"(addr));
}
__device__ __forceinline__ void ldsm_x2(uint32_t (&r)[2], uint32_t addr) {
    asm volatile("ldmatrix.sync.aligned.m8n8.x2.shared.b16 {%0,%1}, [%2];"
        : "=r"(r[0]), "=r"(r[1]) : "r"(addr));
}
__device__ __forceinline__ void mma16816(float (&c)[4], const uint32_t (&a)[4],
                                         const uint32_t (&b)[2]) {
    asm volatile("mma.sync.aligned.m16n8k16.row.col.f32.bf16.bf16.f32 "
        "{%0,%1,%2,%3}, {%4,%5,%6,%7}, {%8,%9}, {%0,%1,%2,%3};"
        : "+f"(c[0]), "+f"(c[1]), "+f"(c[2]), "+f"(c[3])
        : "r"(a[0]), "r"(a[1]), "r"(a[2]), "r"(a[3]), "r"(b[0]), "r"(b[1]));
}
__device__ __forceinline__ void cp16(uint32_t dst, const void* src) {
    asm volatile("cp.async.cg.shared.global [%0], [%1], 16;" :: "r"(dst), "l"(src));
}
#define CP_COMMIT() asm volatile("cp.async.commit_group;" ::: "memory")
#define CP_WAIT1()  asm volatile("cp.async.wait_group 1;" ::: "memory")
#define CP_WAIT0()  asm volatile("cp.async.wait_group 0;" ::: "memory")

// ---------------- small helpers ----------------
__device__ __forceinline__ void block_reduce2_store(float s0, float s1,
                                                    float* o0, float* o1,
                                                    float add0, float add1) {
    __shared__ float red[16];
    #pragma unroll
    for (int o = 16; o > 0; o >>= 1) {
        s0 += __shfl_down_sync(0xffffffffu, s0, o);
        s1 += __shfl_down_sync(0xffffffffu, s1, o);
    }
    int t = threadIdx.x;
    if ((t & 31) == 0) { red[t >> 5] = s0; red[8 + (t >> 5)] = s1; }
    __syncthreads();
    if (t == 0) {
        float a = 0.f, b = 0.f;
        #pragma unroll
        for (int w = 0; w < 8; w++) { a += red[w]; b += red[8 + w]; }
        *o0 = a + add0;
        *o1 = b + add1;
    }
}

// ---------------- kernel: decode proof_offsets (int32 vs int64 robust) ----------------
__global__ void k_decode_off(const int* __restrict__ po) {
    bool wide = (po[1] == 0 && po[3] == 0);
    int idx = blockIdx.x * 256 + threadIdx.x;
    if (idx < NB * NOFF) g_off[idx] = wide ? po[idx * 2] : po[idx];
}

// ---------------- kernel: W^T build + bf16 split ----------------
__global__ void k_prep_weights(const float* __restrict__ Wnd,
                               const float* __restrict__ Wed) {
    __shared__ float tile[32][33];
    int n0 = blockIdx.x * 32;
    int k0 = blockIdx.y * 32;
    int tx = threadIdx.x, ty = threadIdx.y;
    #pragma unroll
    for (int kk = 0; kk < 32; kk += 8) {
        int k = k0 + kk + ty;
        int n = n0 + tx;
        float v;
        if (n < 1024) v = Wnd[(size_t)k * 1024 + n];
        else if (n < 2048) { int c = n - 1024; v = Wed[(size_t)k * 1024 + c] + Wed[(size_t)(2048 + k) * 1024 + c]; }
        else { int c = n - 2048; v = Wed[(size_t)(1024 + k) * 1024 + c] - Wed[(size_t)(2048 + k) * 1024 + c]; }
        tile[kk + ty][tx] = v;
    }
    __syncthreads();
    #pragma unroll
    for (int kk = 0; kk < 32; kk += 8) {
        int n = n0 + kk + ty;
        int k = k0 + tx;
        float v = tile[tx][kk + ty];
        __nv_bfloat16 h = __float2bfloat16(v);
        g_WTh[(size_t)n * NH + k] = h;
        g_WTl[(size_t)n * NH + k] = __float2bfloat16(v - __bfloat162float(h));
    }
}

// ---------------- kernel: cls copy + count ----------------
__global__ void k_prep_cls(const float* __restrict__ seq) {
    int b = blockIdx.x, t = threadIdx.x;
    ((float4*)(g_cls + (size_t)b * NH))[t] =
        ((const float4*)(seq + (size_t)b * NS * NH))[t];
    if (t == 0) {
        int c = 0;
        #pragma unroll
        for (int m = 0; m < NOFF; m++) c += (g_off[b * NOFF + m] > 0);
        g_count[b] = c;
    }
}

// ---------------- kernel: segment partial sums over 64-row S tiles ----------------
__global__ void k_segsum(const float* __restrict__ seq) {
    int st = blockIdx.x;          // 0..7
    int b  = blockIdx.y;          // 0..63
    int hc = blockIdx.z;          // 0..3
    int t  = threadIdx.x;         // 0..63
    int s0 = st * 64;
    int sEnd = s0 + 63;
    int cnt = g_count[b];
    const float4* base = (const float4*)(seq + (size_t)b * NS * NH + hc * 256) + t;
    int prev = 0;
    for (int m = 0; m < cnt; m++) {
        int off = g_off[b * NOFF + m];
        int lo = prev + 1;
        if (lo < s0) lo = s0;
        int hi = off < sEnd ? off : sEnd;
        if (lo <= hi) {
            float4 a0 = make_float4(0.f,0.f,0.f,0.f), a1 = a0, a2 = a0, a3 = a0;
            int s = lo;
            for (; s + 3 <= hi; s += 4) {
                float4 v0 = base[(size_t)(s + 0) * 256];
                float4 v1 = base[(size_t)(s + 1) * 256];
                float4 v2 = base[(size_t)(s + 2) * 256];
                float4 v3 = base[(size_t)(s + 3) * 256];
                a0.x += v0.x; a0.y += v0.y; a0.z += v0.z; a0.w += v0.w;
                a1.x += v1.x; a1.y += v1.y; a1.z += v1.z; a1.w += v1.w;
                a2.x += v2.x; a2.y += v2.y; a2.z += v2.z; a2.w += v2.w;
                a3.x += v3.x; a3.y += v3.y; a3.z += v3.z; a3.w += v3.w;
            }
            for (; s <= hi; s++) {
                float4 v = base[(size_t)s * 256];
                a0.x += v.x; a0.y += v.y; a0.z += v.z; a0.w += v.w;
            }
            a0.x += a1.x + a2.x + a3.x;
            a0.y += a1.y + a2.y + a3.y;
            a0.z += a1.z + a2.z + a3.z;
            a0.w += a1.w + a2.w + a3.w;
            ((float4*)(g_part + (((size_t)(b * NST + st) * NM) + m) * NH + hc * 256))[t] = a0;
        }
        prev = off;
        if (prev >= sEnd) break;
    }
}

// ---------------- kernel: finalize node_full ----------------
__global__ void k_finalize(void) {
    int m = blockIdx.x, b = blockIdx.y, t = threadIdx.x;
    int cnt = g_count[b];
    float4 o = make_float4(0.f, 0.f, 0.f, 0.f);
    if (m < cnt) {
        int off  = g_off[b * NOFF + m];
        int prev = (m == 0) ? 0 : g_off[b * NOFF + m - 1];
        int stLo = (prev + 1) >> 6, stHi = off >> 6;
        for (int st = stLo; st <= stHi; st++) {
            float4 p = ((const float4*)(g_part + (((size_t)(b * NST + st) * NM) + m) * NH))[t];
            o.x += p.x; o.y += p.y; o.z += p.z; o.w += p.w;
        }
        float sc = 1.f / (float)(off - prev);
        o.x *= sc; o.y *= sc; o.z *= sc; o.w *= sc;
    } else if (m == cnt) {
        o = ((const float4*)(g_naf + (size_t)b * NH))[t];
    }
    ((float4*)(g_node + (size_t)(b * NM + m) * NH))[t] = o;
}

// ---------------- kernel: bf16 hi/lo split of node rows ----------------
__global__ void k_split_node(void) {
    int row = blockIdx.x, t = threadIdx.x;
    float4 x = ((const float4*)(g_node + (size_t)row * NH))[t];
    __nv_bfloat16 h0 = __float2bfloat16(x.x), h1 = __float2bfloat16(x.y);
    __nv_bfloat16 h2 = __float2bfloat16(x.z), h3 = __float2bfloat16(x.w);
    __nv_bfloat16 l0 = __float2bfloat16(x.x - __bfloat162float(h0));
    __nv_bfloat16 l1 = __float2bfloat16(x.y - __bfloat162float(h1));
    __nv_bfloat16 l2 = __float2bfloat16(x.z - __bfloat162float(h2));
    __nv_bfloat16 l3 = __float2bfloat16(x.w - __bfloat162float(h3));
    __nv_bfloat162 hA = __halves2bfloat162(h0, h1), hB = __halves2bfloat162(h2, h3);
    __nv_bfloat162 lA = __halves2bfloat162(l0, l1), lB = __halves2bfloat162(l2, l3);
    uint2 hv, lv;
    hv.x = *(uint32_t*)&hA; hv.y = *(uint32_t*)&hB;
    lv.x = *(uint32_t*)&lA; lv.y = *(uint32_t*)&lB;
    ((uint2*)(g_nodeH + (size_t)row * NH))[t] = hv;
    ((uint2*)(g_nodeL + (size_t)row * NH))[t] = lv;
}

// ---------------- kernel: GEMM1  cls(64x1024) @ [W_naf | W_cd] (SIMT, small) -------
__global__ __launch_bounds__(256) void k_gemm1(const float* __restrict__ Wnaf,
                                               const float* __restrict__ Wcd,
                                               const float* __restrict__ bnaf,
                                               const float* __restrict__ bcd) {
    __shared__ float Xs[16 * 68];
    __shared__ float Ws[16 * 64];
    int n0 = blockIdx.x * 64;
    const float* W = (n0 < 1024) ? Wnaf : Wcd;
    int nc0 = (n0 < 1024) ? n0 : n0 - 1024;
    int t = threadIdx.x;
    int tx = t & 15, ty = t >> 4;
    float acc[4][4] = {};
    for (int kt = 0; kt < 1024; kt += 16) {
        {
            int ml = t >> 2, k4 = t & 3;
            float4 x = *(const float4*)(g_cls + (size_t)ml * NH + kt + k4 * 4);
            Xs[(k4 * 4 + 0) * 68 + ml] = x.x;
            Xs[(k4 * 4 + 1) * 68 + ml] = x.y;
            Xs[(k4 * 4 + 2) * 68 + ml] = x.z;
            Xs[(k4 * 4 + 3) * 68 + ml] = x.w;
            int kl = t >> 4, n4 = t & 15;
            float4 w = *(const float4*)(W + (size_t)(kt + kl) * 1024 + nc0 + n4 * 4);
            *(float4*)(Ws + kl * 64 + n4 * 4) = w;
        }
        __syncthreads();
        #pragma unroll
        for (int k = 0; k < 16; k++) {
            float a[4], bb[4];
            *(float4*)a  = *(const float4*)(Xs + k * 68 + ty * 4);
            *(float4*)bb = *(const float4*)(Ws + k * 64 + tx * 4);
            #pragma unroll
            for (int i = 0; i < 4; i++)
                #pragma unroll
                for (int j = 0; j < 4; j++)
                    acc[i][j] += a[i] * bb[j];
        }
        __syncthreads();
    }
    #pragma unroll
    for (int i = 0; i < 4; i++) {
        int m = ty * 4 + i;
        #pragma unroll
        for (int j = 0; j < 4; j++) {
            int n = tx * 4 + j;
            float v = acc[i][j];
            if (n0 < 1024) g_naf[(size_t)m * NH + n0 + n] = v + bnaf[n0 + n];
            else {
                int c = nc0 + n;
                g_cdact[(size_t)m * NH + c] = tanhf(v + bcd[c]);
            }
        }
    }
}

// ---------------- kernel: cls logits ----------------
__global__ void k_logits(const float* __restrict__ Wco,
                         const float* __restrict__ bco,
                         float* __restrict__ out) {
    int b = blockIdx.x, t = threadIdx.x;
    const float2* w = (const float2*)Wco;
    float s0 = 0.f, s1 = 0.f;
    for (int h = t; h < NH; h += 256) {
        float x = g_cdact[(size_t)b * NH + h];
        float2 ww = w[h];
        s0 += x * ww.x; s1 += x * ww.y;
    }
    block_reduce2_store(s0, s1, out + b * 2, out + b * 2 + 1, bco[0], bco[1]);
}

// ============================================================================
// HMMA GEMM: D(1664x3072) = node(1664x1024) @ WT^T, bf16 3-term split.
// CTA tile 128x128, K-tile 64, 2-stage cp.async, 8 warps (2m x 4n), warp 64x32.
// SMEM/stage: Ah,Al,Bh,Bl each 128x64 bf16 (16KB) = 64KB; 2 stages = 128KB.
// ============================================================================
#define TILE_B 16384
#define STAGE_B (4*TILE_B)
#define GEMM_SMEM (2*STAGE_B)

__global__ __launch_bounds__(256, 1) void k_mmagemm(const float* __restrict__ bnd) {
    extern __shared__ char smem[];
    uint32_t sb = smem_to_u32(smem);
    const int t = threadIdx.x;
    const int lane = t & 31, wid = t >> 5;
    const int wm = wid >> 2, wn = wid & 3;
    const int m0 = blockIdx.y * 128, n0 = blockIdx.x * 128;

    // ---- copy geometry: per tile, 4 x 16B chunks per thread ----
    uint32_t swo[4];
    uint32_t gOffA[4], gOffB[4];   // bf16-element offsets (without k-chunk)
    #pragma unroll
    for (int j = 0; j < 4; j++) {
        int u = j * 256 + t;
        int r = u >> 3, c = u & 7;
        uint32_t o = (uint32_t)r * 128 + (uint32_t)c * 16;
        swo[j] = o ^ ((o >> 3) & 0x70);
        gOffA[j] = (uint32_t)(m0 + r) * NH + c * 8;
        gOffB[j] = (uint32_t)(n0 + r) * NH + c * 8;
    }

    auto issue = [&](int kc) {
        int buf = kc & 1;
        uint32_t kk = (uint32_t)kc * 64;
        uint32_t d = sb + buf * STAGE_B;
        #pragma unroll
        for (int j = 0; j < 4; j++) {
            cp16(d + 0 * TILE_B + swo[j], g_nodeH + gOffA[j] + kk);
            cp16(d + 1 * TILE_B + swo[j], g_nodeL + gOffA[j] + kk);
            cp16(d + 2 * TILE_B + swo[j], g_WTh   + gOffB[j] + kk);
            cp16(d + 3 * TILE_B + swo[j], g_WTl   + gOffB[j] + kk);
        }
        CP_COMMIT();
    };

    float acc[4][4][4] = {};

    // ldmatrix address geometry (per ks recomputed with constants folded)
    const uint32_t aRow = (uint32_t)(wm * 64 + (lane & 15));
    const uint32_t aKhalf = (uint32_t)((lane >> 4) * 16);       // bytes
    const uint32_t bRow = (uint32_t)(wn * 32 + (lane & 7));
    const uint32_t bKhalf = (uint32_t)(((lane >> 3) & 1) * 16); // bytes

    issue(0);
    issue(1);

    for (int kc = 0; kc < 16; kc++) {
        if (kc == 15) { CP_WAIT0(); } else { CP_WAIT1(); }
        __syncthreads();
        uint32_t base = sb + (kc & 1) * STAGE_B;

        #pragma unroll
        for (int ks = 0; ks < 4; ks++) {
            uint32_t aH[4][4], aL[4][4], bH[4][2], bL[4][2];
            #pragma unroll
            for (int mt = 0; mt < 4; mt++) {
                uint32_t o = (aRow + mt * 16) * 128 + ks * 32 + aKhalf;
                o ^= (o >> 3) & 0x70;
                ldsm_x4(aH[mt], base + o);
                ldsm_x4(aL[mt], base + TILE_B + o);
            }
            #pragma unroll
            for (int nt = 0; nt < 4; nt++) {
                uint32_t o = (bRow + nt * 8) * 128 + ks * 32 + bKhalf;
                o ^= (o >> 3) & 0x70;
                ldsm_x2(bH[nt], base + 2 * TILE_B + o);
                ldsm_x2(bL[nt], base + 3 * TILE_B + o);
            }
            #pragma unroll
            for (int mt = 0; mt < 4; mt++)
                #pragma unroll
                for (int nt = 0; nt < 4; nt++) {
                    mma16816(acc[mt][nt], aH[mt], bH[nt]);
                    mma16816(acc[mt][nt], aH[mt], bL[nt]);
                    mma16816(acc[mt][nt], aL[mt], bH[nt]);
                }
        }
        __syncthreads();
        if (kc + 2 < 16) issue(kc + 2);
    }

    // ---- epilogue ----
    int sec  = n0 >> 10;                  // 0: W_nd(tanh), 1: WA, 2: WB
    int ncol = n0 & 1023;
    float* dst = (sec == 0) ? g_ND : ((sec == 1) ? g_A : g_Bm);
    int g = lane >> 2, tq = lane & 3;
    #pragma unroll
    for (int mt = 0; mt < 4; mt++) {
        int m = m0 + wm * 64 + mt * 16 + g;
        #pragma unroll
        for (int nt = 0; nt < 4; nt++) {
            int n = ncol + wn * 32 + nt * 8 + tq * 2;
            float2 v0 = make_float2(acc[mt][nt][0], acc[mt][nt][1]);
            float2 v1 = make_float2(acc[mt][nt][2], acc[mt][nt][3]);
            if (sec == 0) {
                float b0 = bnd[n], b1 = bnd[n + 1];
                v0.x = tanhf(v0.x + b0); v0.y = tanhf(v0.y + b1);
                v1.x = tanhf(v1.x + b0); v1.y = tanhf(v1.y + b1);
            }
            *(float2*)(dst + (size_t)m * NH + n) = v0;
            *(float2*)(dst + (size_t)(m + 8) * NH + n) = v1;
        }
    }
}

// ---------------- kernel: node logits ----------------
__global__ void k_node_logits(const float* __restrict__ Wno,
                              const float* __restrict__ bno,
                              float* __restrict__ out) {
    int r = blockIdx.x, t = threadIdx.x;
    const float2* w = (const float2*)Wno;
    float s0 = 0.f, s1 = 0.f;
    for (int h = t; h < NH; h += 256) {
        float x = g_ND[(size_t)r * NH + h];
        float2 ww = w[h];
        s0 += x * ww.x; s1 += x * ww.y;
    }
    float* o = out + 128 + (size_t)r * 2;
    block_reduce2_store(s0, s1, o, o + 1, bno[0], bno[1]);
}

// ---------------- kernel: constant logits for invalid edges ----------------
__global__ void k_cvec(const float* __restrict__ bed,
                       const float* __restrict__ Weo,
                       const float* __restrict__ beo) {
    int t = threadIdx.x;
    const float2* w = (const float2*)Weo;
    float s0 = 0.f, s1 = 0.f;
    for (int h = t; h < NH; h += 256) {
        float v = tanhf(bed[h]);
        float2 ww = w[h];
        s0 += v * ww.x; s1 += v * ww.y;
    }
    block_reduce2_store(s0, s1, &g_cvec[0], &g_cvec[1], beo[0], beo[1]);
}

// ---------------- kernel: edge logits ----------------
__global__ void k_edges(const float* __restrict__ bed,
                        const float* __restrict__ Weo,
                        const float* __restrict__ beo,
                        float* __restrict__ out) {
    int k = blockIdx.x, b = blockIdx.y, t = threadIdx.x;
    int n = g_count[b] + 1;
    float* o = out + 128 + NR * 2 + (size_t)(b * NE + k) * 2;
    if (k >= n * n) {
        if (t < 2) o[t] = g_cvec[t];
        return;
    }
    int i = k / n, j = k % n;
    const float* Ar = g_A  + (size_t)(b * NM + j) * NH;
    const float* Br = g_Bm + (size_t)(b * NM + i) * NH;
    const float2* w = (const float2*)Weo;
    float s0 = 0.f, s1 = 0.f;
    for (int h = t; h < NH; h += 256) {
        float v = tanhf(Ar[h] + Br[h] + bed[h]);
        float2 ww = w[h];
        s0 += v * ww.x; s1 += v * ww.y;
    }
    block_reduce2_store(s0, s1, o, o + 1, beo[0], beo[1]);
}

// ---------------- launch ----------------
extern "C" void kernel_launch(void* const* d_in, const int* in_sizes, int n_in,
                              void* d_out, int out_size) {
    const float* seq  = (const float*)d_in[0];
    const int*   po   = (const int*)  d_in[1];
    const float* Wnaf = (const float*)d_in[4];
    const float* bnaf = (const float*)d_in[5];
    const float* Wcd  = (const float*)d_in[6];
    const float* bcd  = (const float*)d_in[7];
    const float* Wco  = (const float*)d_in[8];
    const float* bco  = (const float*)d_in[9];
    const float* Wnd  = (const float*)d_in[10];
    const float* bnd  = (const float*)d_in[11];
    const float* Wno  = (const float*)d_in[12];
    const float* bno  = (const float*)d_in[13];
    const float* Wed  = (const float*)d_in[14];
    const float* bed  = (const float*)d_in[15];
    const float* Weo  = (const float*)d_in[16];
    const float* beo  = (const float*)d_in[17];
    float* out = (float*)d_out;

    static bool attr_done = false;
    if (!attr_done) {
        cudaFuncSetAttribute(k_mmagemm, cudaFuncAttributeMaxDynamicSharedMemorySize, GEMM_SMEM);
        attr_done = true;
    }

    k_decode_off<<<7, 256>>>(po);
    k_prep_weights<<<dim3(96, 32), dim3(32, 8)>>>(Wnd, Wed);
    k_prep_cls<<<NB, 256>>>(seq);
    k_segsum<<<dim3(NST, NB, 4), 64>>>(seq);
    k_gemm1<<<32, 256>>>(Wnaf, Wcd, bnaf, bcd);
    k_logits<<<NB, 256>>>(Wco, bco, out);
    k_finalize<<<dim3(NM, NB), 256>>>();
    k_split_node<<<NR, 256>>>();
    k_mmagemm<<<dim3(24, 13), 256, GEMM_SMEM>>>(bnd);
    k_node_logits<<<NR, 256>>>(Wno, bno, out);
    k_cvec<<<1, 256>>>(bed, Weo, beo);
    k_edges<<<dim3(NE, NB), 256>>>(bed, Weo, beo, out);
}

// round 4
// speedup vs baseline: 1.9015x; 1.0004x over previous
#include <cuda_runtime.h>
#include <cuda_bf16.h>
#include <math.h>
#include <stdint.h>

#define NB 64
#define NS 512
#define NH 1024
#define NM 26
#define NE 676
#define NR (NB*NM)          // 1664 node rows total
#define NOFF (NM-1)         // 25 offsets per batch
#define NST 8               // S tiles of 64 rows

// ---------------- scratch (device globals; no allocation allowed) ----------------
__device__ int   g_off[NB*NOFF];
__device__ int   g_count[NB];
__device__ __align__(16) float g_cls[NB*NH];
__device__ __align__(16) float g_naf[NB*NH];
__device__ __align__(16) float g_cdact[NB*NH];
__device__ __align__(16) float g_part[NB*NST*NM*NH]; // segment tile partials
__device__ __align__(16) float g_ND[NR*NH];          // tanh(node_full @ W_nd + b_nd)
__device__ __align__(16) float g_A[NR*NH];           // node_full @ (W1+W3)
__device__ __align__(16) float g_Bm[NR*NH];          // node_full @ (W2-W3)
__device__ float g_cvec[2];
// bf16 split operands for tensor-core GEMM
__device__ __align__(16) __nv_bfloat16 g_nodeH[NR*NH];
__device__ __align__(16) __nv_bfloat16 g_nodeL[NR*NH];
__device__ __align__(16) __nv_bfloat16 g_WTh[3072*NH];  // W^T (N-major, K cols), hi
__device__ __align__(16) __nv_bfloat16 g_WTl[3072*NH];  // lo

// ============================================================================
// portable PTX helpers (no sm_103a-only features)
// ============================================================================
__device__ __forceinline__ uint32_t smem_to_u32(const void* p) {
    uint32_t a;
    asm("{ .reg .u64 t; cvta.to.shared.u64 t, %1; cvt.u32.u64 %0, t; }" : "=r"(a) : "l"(p));
    return a;
}
__device__ __forceinline__ void ldsm_x4(uint32_t (&r)[4], uint32_t addr) {
    asm volatile("ldmatrix.sync.aligned.m8n8.x4.shared.b16 {%0,%1,%2,%3}, [%4];"
        : "=r"(r[0]), "=r"(r[1]), "=r"(r[2]), "=r"(r[3]) : "r"(addr));
}
__device__ __forceinline__ void mma16816(float (&c)[4], const uint32_t (&a)[4],
                                         uint32_t b0, uint32_t b1) {
    asm volatile("mma.sync.aligned.m16n8k16.row.col.f32.bf16.bf16.f32 "
        "{%0,%1,%2,%3}, {%4,%5,%6,%7}, {%8,%9}, {%0,%1,%2,%3};"
        : "+f"(c[0]), "+f"(c[1]), "+f"(c[2]), "+f"(c[3])
        : "r"(a[0]), "r"(a[1]), "r"(a[2]), "r"(a[3]), "r"(b0), "r"(b1));
}
__device__ __forceinline__ void cp16(uint32_t dst, const void* src) {
    asm volatile("cp.async.cg.shared.global [%0], [%1], 16;" :: "r"(dst), "l"(src));
}
#define CP_COMMIT() asm volatile("cp.async.commit_group;" ::: "memory")
#define CP_WAIT1()  asm volatile("cp.async.wait_group 1;" ::: "memory")
#define CP_WAIT0()  asm volatile("cp.async.wait_group 0;" ::: "memory")

// ---------------- small helpers ----------------
__device__ __forceinline__ void block_reduce2_store(float s0, float s1,
                                                    float* o0, float* o1,
                                                    float add0, float add1) {
    __shared__ float red[16];
    #pragma unroll
    for (int o = 16; o > 0; o >>= 1) {
        s0 += __shfl_down_sync(0xffffffffu, s0, o);
        s1 += __shfl_down_sync(0xffffffffu, s1, o);
    }
    int t = threadIdx.x;
    if ((t & 31) == 0) { red[t >> 5] = s0; red[8 + (t >> 5)] = s1; }
    __syncthreads();
    if (t == 0) {
        float a = 0.f, b = 0.f;
        #pragma unroll
        for (int w = 0; w < 8; w++) { a += red[w]; b += red[8 + w]; }
        *o0 = a + add0;
        *o1 = b + add1;
    }
}

// ---------------- kernel: W^T build + bf16 split ----------------
__global__ void k_prep_weights(const float* __restrict__ Wnd,
                               const float* __restrict__ Wed) {
    __shared__ float tile[32][33];
    int n0 = blockIdx.x * 32;
    int k0 = blockIdx.y * 32;
    int tx = threadIdx.x, ty = threadIdx.y;
    #pragma unroll
    for (int kk = 0; kk < 32; kk += 8) {
        int k = k0 + kk + ty;
        int n = n0 + tx;
        float v;
        if (n < 1024) v = Wnd[(size_t)k * 1024 + n];
        else if (n < 2048) { int c = n - 1024; v = Wed[(size_t)k * 1024 + c] + Wed[(size_t)(2048 + k) * 1024 + c]; }
        else { int c = n - 2048; v = Wed[(size_t)(1024 + k) * 1024 + c] - Wed[(size_t)(2048 + k) * 1024 + c]; }
        tile[kk + ty][tx] = v;
    }
    __syncthreads();
    #pragma unroll
    for (int kk = 0; kk < 32; kk += 8) {
        int n = n0 + kk + ty;
        int k = k0 + tx;
        float v = tile[tx][kk + ty];
        __nv_bfloat16 h = __float2bfloat16(v);
        g_WTh[(size_t)n * NH + k] = h;
        g_WTl[(size_t)n * NH + k] = __float2bfloat16(v - __bfloat162float(h));
    }
}

// ---------------- kernel: decode offsets + count + cls copy (fused) ----------------
__global__ void k_prep_cls(const float* __restrict__ seq, const int* __restrict__ po) {
    int b = blockIdx.x, t = threadIdx.x;
    bool wide = (po[1] == 0 && po[3] == 0);
    int val = 0;
    if (t < NOFF) {
        val = wide ? po[(b * NOFF + t) * 2] : po[b * NOFF + t];
        g_off[b * NOFF + t] = val;
    }
    if (t < 32) {
        unsigned mask = __ballot_sync(0xffffffffu, (t < NOFF) && (val > 0));
        if (t == 0) g_count[b] = __popc(mask);
    }
    ((float4*)(g_cls + (size_t)b * NH))[t] =
        ((const float4*)(seq + (size_t)b * NS * NH))[t];
}

// ---------------- kernel: segment partial sums over 64-row S tiles ----------------
__global__ void k_segsum(const float* __restrict__ seq) {
    int st = blockIdx.x;          // 0..7
    int b  = blockIdx.y;          // 0..63
    int hc = blockIdx.z;          // 0..3
    int t  = threadIdx.x;         // 0..63
    int s0 = st * 64;
    int sEnd = s0 + 63;
    int cnt = g_count[b];
    const float4* base = (const float4*)(seq + (size_t)b * NS * NH + hc * 256) + t;
    int prev = 0;
    for (int m = 0; m < cnt; m++) {
        int off = g_off[b * NOFF + m];
        int lo = prev + 1;
        if (lo < s0) lo = s0;
        int hi = off < sEnd ? off : sEnd;
        if (lo <= hi) {
            float4 a0 = make_float4(0.f,0.f,0.f,0.f), a1 = a0, a2 = a0, a3 = a0;
            int s = lo;
            for (; s + 3 <= hi; s += 4) {
                float4 v0 = base[(size_t)(s + 0) * 256];
                float4 v1 = base[(size_t)(s + 1) * 256];
                float4 v2 = base[(size_t)(s + 2) * 256];
                float4 v3 = base[(size_t)(s + 3) * 256];
                a0.x += v0.x; a0.y += v0.y; a0.z += v0.z; a0.w += v0.w;
                a1.x += v1.x; a1.y += v1.y; a1.z += v1.z; a1.w += v1.w;
                a2.x += v2.x; a2.y += v2.y; a2.z += v2.z; a2.w += v2.w;
                a3.x += v3.x; a3.y += v3.y; a3.z += v3.z; a3.w += v3.w;
            }
            for (; s <= hi; s++) {
                float4 v = base[(size_t)s * 256];
                a0.x += v.x; a0.y += v.y; a0.z += v.z; a0.w += v.w;
            }
            a0.x += a1.x + a2.x + a3.x;
            a0.y += a1.y + a2.y + a3.y;
            a0.z += a1.z + a2.z + a3.z;
            a0.w += a1.w + a2.w + a3.w;
            ((float4*)(g_part + (((size_t)(b * NST + st) * NM) + m) * NH + hc * 256))[t] = a0;
        }
        prev = off;
        if (prev >= sEnd) break;
    }
}

// ---------------- kernel: finalize node_full + bf16 hi/lo split (fused) ----------------
__global__ void k_finalize(void) {
    int m = blockIdx.x, b = blockIdx.y, t = threadIdx.x;
    int cnt = g_count[b];
    float4 o = make_float4(0.f, 0.f, 0.f, 0.f);
    if (m < cnt) {
        int off  = g_off[b * NOFF + m];
        int prev = (m == 0) ? 0 : g_off[b * NOFF + m - 1];
        int stLo = (prev + 1) >> 6, stHi = off >> 6;
        for (int st = stLo; st <= stHi; st++) {
            float4 p = ((const float4*)(g_part + (((size_t)(b * NST + st) * NM) + m) * NH))[t];
            o.x += p.x; o.y += p.y; o.z += p.z; o.w += p.w;
        }
        float sc = 1.f / (float)(off - prev);
        o.x *= sc; o.y *= sc; o.z *= sc; o.w *= sc;
    } else if (m == cnt) {
        o = ((const float4*)(g_naf + (size_t)b * NH))[t];
    }
    size_t row = (size_t)(b * NM + m);
    __nv_bfloat16 h0 = __float2bfloat16(o.x), h1 = __float2bfloat16(o.y);
    __nv_bfloat16 h2 = __float2bfloat16(o.z), h3 = __float2bfloat16(o.w);
    __nv_bfloat16 l0 = __float2bfloat16(o.x - __bfloat162float(h0));
    __nv_bfloat16 l1 = __float2bfloat16(o.y - __bfloat162float(h1));
    __nv_bfloat16 l2 = __float2bfloat16(o.z - __bfloat162float(h2));
    __nv_bfloat16 l3 = __float2bfloat16(o.w - __bfloat162float(h3));
    __nv_bfloat162 hA = __halves2bfloat162(h0, h1), hB = __halves2bfloat162(h2, h3);
    __nv_bfloat162 lA = __halves2bfloat162(l0, l1), lB = __halves2bfloat162(l2, l3);
    uint2 hv, lv;
    hv.x = *(uint32_t*)&hA; hv.y = *(uint32_t*)&hB;
    lv.x = *(uint32_t*)&lA; lv.y = *(uint32_t*)&lB;
    ((uint2*)(g_nodeH + row * NH))[t] = hv;
    ((uint2*)(g_nodeL + row * NH))[t] = lv;
}

// ---------------- kernel: GEMM1  cls(64x1024) @ [W_naf | W_cd] (SIMT, small) -------
__global__ __launch_bounds__(256) void k_gemm1(const float* __restrict__ Wnaf,
                                               const float* __restrict__ Wcd,
                                               const float* __restrict__ bnaf,
                                               const float* __restrict__ bcd) {
    __shared__ float Xs[16 * 68];
    __shared__ float Ws[16 * 64];
    int n0 = blockIdx.x * 64;
    const float* W = (n0 < 1024) ? Wnaf : Wcd;
    int nc0 = (n0 < 1024) ? n0 : n0 - 1024;
    int t = threadIdx.x;
    int tx = t & 15, ty = t >> 4;
    float acc[4][4] = {};
    for (int kt = 0; kt < 1024; kt += 16) {
        {
            int ml = t >> 2, k4 = t & 3;
            float4 x = *(const float4*)(g_cls + (size_t)ml * NH + kt + k4 * 4);
            Xs[(k4 * 4 + 0) * 68 + ml] = x.x;
            Xs[(k4 * 4 + 1) * 68 + ml] = x.y;
            Xs[(k4 * 4 + 2) * 68 + ml] = x.z;
            Xs[(k4 * 4 + 3) * 68 + ml] = x.w;
            int kl = t >> 4, n4 = t & 15;
            float4 w = *(const float4*)(W + (size_t)(kt + kl) * 1024 + nc0 + n4 * 4);
            *(float4*)(Ws + kl * 64 + n4 * 4) = w;
        }
        __syncthreads();
        #pragma unroll
        for (int k = 0; k < 16; k++) {
            float a[4], bb[4];
            *(float4*)a  = *(const float4*)(Xs + k * 68 + ty * 4);
            *(float4*)bb = *(const float4*)(Ws + k * 64 + tx * 4);
            #pragma unroll
            for (int i = 0; i < 4; i++)
                #pragma unroll
                for (int j = 0; j < 4; j++)
                    acc[i][j] += a[i] * bb[j];
        }
        __syncthreads();
    }
    #pragma unroll
    for (int i = 0; i < 4; i++) {
        int m = ty * 4 + i;
        #pragma unroll
        for (int j = 0; j < 4; j++) {
            int n = tx * 4 + j;
            float v = acc[i][j];
            if (n0 < 1024) g_naf[(size_t)m * NH + n0 + n] = v + bnaf[n0 + n];
            else {
                int c = nc0 + n;
                g_cdact[(size_t)m * NH + c] = tanhf(v + bcd[c]);
            }
        }
    }
}

// ---------------- kernel: cls logits ----------------
__global__ void k_logits(const float* __restrict__ Wco,
                         const float* __restrict__ bco,
                         float* __restrict__ out) {
    int b = blockIdx.x, t = threadIdx.x;
    const float2* w = (const float2*)Wco;
    float s0 = 0.f, s1 = 0.f;
    for (int h = t; h < NH; h += 256) {
        float x = g_cdact[(size_t)b * NH + h];
        float2 ww = w[h];
        s0 += x * ww.x; s1 += x * ww.y;
    }
    block_reduce2_store(s0, s1, out + b * 2, out + b * 2 + 1, bco[0], bco[1]);
}

// ============================================================================
// HMMA GEMM: D(1664x3072) = node(1664x1024) @ WT^T, bf16 3-term split.
// CTA 128x128, K-tile 32, 3-stage cp.async (32KB/stage, 96KB total -> 2 CTA/SM).
// 8 warps (2m x 4n), warp tile 64x32. SW64 swizzle (64B rows).
// ============================================================================
#define TILE_B 8192
#define STAGE_B (4*TILE_B)
#define GEMM_SMEM (3*STAGE_B)

__global__ __launch_bounds__(256, 2) void k_mmagemm(const float* __restrict__ bnd) {
    extern __shared__ char smem[];
    uint32_t sb = smem_to_u32(smem);
    const int t = threadIdx.x;
    const int lane = t & 31, wid = t >> 5;
    const int wm = wid >> 2, wn = wid & 3;
    const int m0 = blockIdx.y * 128, n0 = blockIdx.x * 128;

    // ---- copy geometry: 2 x 16B chunks per thread per tile (8KB tile) ----
    uint32_t swo[2], gOffA[2], gOffB[2];
    #pragma unroll
    for (int j = 0; j < 2; j++) {
        int u = j * 256 + t;
        int r = u >> 2, c = u & 3;
        uint32_t o = (uint32_t)r * 64 + (uint32_t)c * 16;
        swo[j] = o ^ ((o >> 3) & 0x30);
        gOffA[j] = (uint32_t)(m0 + r) * NH + c * 8;
        gOffB[j] = (uint32_t)(n0 + r) * NH + c * 8;
    }

    auto issue = [&](int kc) {
        uint32_t kk = (uint32_t)kc * 32;
        uint32_t d = sb + (kc % 3) * STAGE_B;
        #pragma unroll
        for (int j = 0; j < 2; j++) {
            cp16(d + 0 * TILE_B + swo[j], g_nodeH + gOffA[j] + kk);
            cp16(d + 1 * TILE_B + swo[j], g_nodeL + gOffA[j] + kk);
            cp16(d + 2 * TILE_B + swo[j], g_WTh   + gOffB[j] + kk);
            cp16(d + 3 * TILE_B + swo[j], g_WTl   + gOffB[j] + kk);
        }
        CP_COMMIT();
    };

    float acc[4][4][4] = {};

    // ldmatrix geometry
    const uint32_t aRow = (uint32_t)(wm * 64 + (lane & 15));
    const uint32_t aKhalf = (uint32_t)((lane >> 4) * 16);                 // bytes
    const uint32_t bRowBase = (uint32_t)(wn * 32 + ((lane >> 4) & 1) * 8 + (lane & 7));
    const uint32_t bCol = (uint32_t)(((lane >> 3) & 1) * 16);             // bytes

    issue(0);
    issue(1);

    for (int kc = 0; kc < 32; kc++) {
        if (kc == 31) { CP_WAIT0(); } else { CP_WAIT1(); }
        __syncthreads();
        if (kc + 2 < 32) issue(kc + 2);   // targets stage (kc-1)%3, drained at barrier
        uint32_t base = sb + (kc % 3) * STAGE_B;

        #pragma unroll
        for (int ks = 0; ks < 2; ks++) {
            uint32_t bH[2][4], bL[2][4];
            #pragma unroll
            for (int p = 0; p < 2; p++) {
                uint32_t o = (bRowBase + p * 16) * 64 + ks * 32 + bCol;
                o ^= (o >> 3) & 0x30;
                ldsm_x4(bH[p], base + 2 * TILE_B + o);
                ldsm_x4(bL[p], base + 3 * TILE_B + o);
            }
            #pragma unroll
            for (int mt = 0; mt < 4; mt++) {
                uint32_t aH[4], aL[4];
                uint32_t o = (aRow + mt * 16) * 64 + ks * 32 + aKhalf;
                o ^= (o >> 3) & 0x30;
                ldsm_x4(aH, base + o);
                ldsm_x4(aL, base + TILE_B + o);
                #pragma unroll
                for (int nt = 0; nt < 4; nt++) {
                    int p = nt >> 1, q = (nt & 1) * 2;
                    mma16816(acc[mt][nt], aH, bH[p][q], bH[p][q + 1]);
                    mma16816(acc[mt][nt], aH, bL[p][q], bL[p][q + 1]);
                    mma16816(acc[mt][nt], aL, bH[p][q], bH[p][q + 1]);
                }
            }
        }
    }

    // ---- epilogue ----
    int sec  = n0 >> 10;                  // 0: W_nd(tanh), 1: WA, 2: WB
    int ncol = n0 & 1023;
    float* dst = (sec == 0) ? g_ND : ((sec == 1) ? g_A : g_Bm);
    int g = lane >> 2, tq = lane & 3;
    #pragma unroll
    for (int mt = 0; mt < 4; mt++) {
        int m = m0 + wm * 64 + mt * 16 + g;
        #pragma unroll
        for (int nt = 0; nt < 4; nt++) {
            int n = ncol + wn * 32 + nt * 8 + tq * 2;
            float2 v0 = make_float2(acc[mt][nt][0], acc[mt][nt][1]);
            float2 v1 = make_float2(acc[mt][nt][2], acc[mt][nt][3]);
            if (sec == 0) {
                float b0 = bnd[n], b1 = bnd[n + 1];
                v0.x = tanhf(v0.x + b0); v0.y = tanhf(v0.y + b1);
                v1.x = tanhf(v1.x + b0); v1.y = tanhf(v1.y + b1);
            }
            *(float2*)(dst + (size_t)m * NH + n) = v0;
            *(float2*)(dst + (size_t)(m + 8) * NH + n) = v1;
        }
    }
}

// ---------------- kernel: node logits ----------------
__global__ void k_node_logits(const float* __restrict__ Wno,
                              const float* __restrict__ bno,
                              float* __restrict__ out) {
    int r = blockIdx.x, t = threadIdx.x;
    const float2* w = (const float2*)Wno;
    float s0 = 0.f, s1 = 0.f;
    for (int h = t; h < NH; h += 256) {
        float x = g_ND[(size_t)r * NH + h];
        float2 ww = w[h];
        s0 += x * ww.x; s1 += x * ww.y;
    }
    float* o = out + 128 + (size_t)r * 2;
    block_reduce2_store(s0, s1, o, o + 1, bno[0], bno[1]);
}

// ---------------- kernel: constant logits for invalid edges ----------------
__global__ void k_cvec(const float* __restrict__ bed,
                       const float* __restrict__ Weo,
                       const float* __restrict__ beo) {
    int t = threadIdx.x;
    const float2* w = (const float2*)Weo;
    float s0 = 0.f, s1 = 0.f;
    for (int h = t; h < NH; h += 256) {
        float v = tanhf(bed[h]);
        float2 ww = w[h];
        s0 += v * ww.x; s1 += v * ww.y;
    }
    block_reduce2_store(s0, s1, &g_cvec[0], &g_cvec[1], beo[0], beo[1]);
}

// ---------------- kernel: edge logits ----------------
__global__ void k_edges(const float* __restrict__ bed,
                        const float* __restrict__ Weo,
                        const float* __restrict__ beo,
                        float* __restrict__ out) {
    int k = blockIdx.x, b = blockIdx.y, t = threadIdx.x;
    int n = g_count[b] + 1;
    float* o = out + 128 + NR * 2 + (size_t)(b * NE + k) * 2;
    if (k >= n * n) {
        if (t < 2) o[t] = g_cvec[t];
        return;
    }
    int i = k / n, j = k % n;
    const float* Ar = g_A  + (size_t)(b * NM + j) * NH;
    const float* Br = g_Bm + (size_t)(b * NM + i) * NH;
    const float2* w = (const float2*)Weo;
    float s0 = 0.f, s1 = 0.f;
    for (int h = t; h < NH; h += 256) {
        float v = tanhf(Ar[h] + Br[h] + bed[h]);
        float2 ww = w[h];
        s0 += v * ww.x; s1 += v * ww.y;
    }
    block_reduce2_store(s0, s1, o, o + 1, beo[0], beo[1]);
}

// ---------------- launch ----------------
extern "C" void kernel_launch(void* const* d_in, const int* in_sizes, int n_in,
                              void* d_out, int out_size) {
    const float* seq  = (const float*)d_in[0];
    const int*   po   = (const int*)  d_in[1];
    const float* Wnaf = (const float*)d_in[4];
    const float* bnaf = (const float*)d_in[5];
    const float* Wcd  = (const float*)d_in[6];
    const float* bcd  = (const float*)d_in[7];
    const float* Wco  = (const float*)d_in[8];
    const float* bco  = (const float*)d_in[9];
    const float* Wnd  = (const float*)d_in[10];
    const float* bnd  = (const float*)d_in[11];
    const float* Wno  = (const float*)d_in[12];
    const float* bno  = (const float*)d_in[13];
    const float* Wed  = (const float*)d_in[14];
    const float* bed  = (const float*)d_in[15];
    const float* Weo  = (const float*)d_in[16];
    const float* beo  = (const float*)d_in[17];
    float* out = (float*)d_out;

    static bool attr_done = false;
    if (!attr_done) {
        cudaFuncSetAttribute(k_mmagemm, cudaFuncAttributeMaxDynamicSharedMemorySize, GEMM_SMEM);
        attr_done = true;
    }

    k_prep_weights<<<dim3(96, 32), dim3(32, 8)>>>(Wnd, Wed);
    k_prep_cls<<<NB, 256>>>(seq, po);
    k_segsum<<<dim3(NST, NB, 4), 64>>>(seq);
    k_gemm1<<<32, 256>>>(Wnaf, Wcd, bnaf, bcd);
    k_logits<<<NB, 256>>>(Wco, bco, out);
    k_finalize<<<dim3(NM, NB), 256>>>();
    k_mmagemm<<<dim3(24, 13), 256, GEMM_SMEM>>>(bnd);
    k_node_logits<<<NR, 256>>>(Wno, bno, out);
    k_cvec<<<1, 256>>>(bed, Weo, beo);
    k_edges<<<dim3(NE, NB), 256>>>(bed, Weo, beo, out);
}

// round 5
// speedup vs baseline: 2.3544x; 1.2382x over previous
#include <cuda_runtime.h>
#include <cuda_bf16.h>
#include <math.h>
#include <stdint.h>

#define NB 64
#define NS 512
#define NH 1024
#define NM 26
#define NE 676
#define NR (NB*NM)          // 1664 node rows total
#define NOFF (NM-1)         // 25 offsets per batch
#define NST 8               // S tiles of 64 rows
#define KSPLIT 8            // gemm1 K splits

// ---------------- scratch (device globals; no allocation allowed) ----------------
__device__ int   g_off[NB*NOFF];
__device__ int   g_count[NB];
__device__ __align__(16) float g_cls[NB*NH];
__device__ __align__(16) float g_naf[NB*NH];
__device__ __align__(16) float g_cdact[NB*NH];
__device__ __align__(16) float g_g1p[KSPLIT*NB*2048];  // gemm1 split-K partials
__device__ __align__(16) float g_part[NB*NST*NM*NH];   // segment tile partials
__device__ __align__(16) float g_ND[NR*NH];            // tanh(node_full @ W_nd + b_nd)
__device__ __align__(16) float g_A[NR*NH];             // node_full @ (W1+W3)
__device__ __align__(16) float g_Bm[NR*NH];            // node_full @ (W2-W3)
__device__ float g_cvec[2];
// bf16 split operands for tensor-core GEMM
__device__ __align__(16) __nv_bfloat16 g_nodeH[NR*NH];
__device__ __align__(16) __nv_bfloat16 g_nodeL[NR*NH];
__device__ __align__(16) __nv_bfloat16 g_WTh[3072*NH];  // W^T (N-major, K cols), hi
__device__ __align__(16) __nv_bfloat16 g_WTl[3072*NH];  // lo

// ============================================================================
// portable PTX helpers (no sm_103a-only features)
// ============================================================================
__device__ __forceinline__ uint32_t smem_to_u32(const void* p) {
    uint32_t a;
    asm("{ .reg .u64 t; cvta.to.shared.u64 t, %1; cvt.u32.u64 %0, t; }" : "=r"(a) : "l"(p));
    return a;
}
__device__ __forceinline__ void ldsm_x4(uint32_t (&r)[4], uint32_t addr) {
    asm volatile("ldmatrix.sync.aligned.m8n8.x4.shared.b16 {%0,%1,%2,%3}, [%4];"
        : "=r"(r[0]), "=r"(r[1]), "=r"(r[2]), "=r"(r[3]) : "r"(addr));
}
__device__ __forceinline__ void mma16816(float (&c)[4], const uint32_t (&a)[4],
                                         uint32_t b0, uint32_t b1) {
    asm volatile("mma.sync.aligned.m16n8k16.row.col.f32.bf16.bf16.f32 "
        "{%0,%1,%2,%3}, {%4,%5,%6,%7}, {%8,%9}, {%0,%1,%2,%3};"
        : "+f"(c[0]), "+f"(c[1]), "+f"(c[2]), "+f"(c[3])
        : "r"(a[0]), "r"(a[1]), "r"(a[2]), "r"(a[3]), "r"(b0), "r"(b1));
}
__device__ __forceinline__ void cp16(uint32_t dst, const void* src) {
    asm volatile("cp.async.cg.shared.global [%0], [%1], 16;" :: "r"(dst), "l"(src));
}
#define CP_COMMIT() asm volatile("cp.async.commit_group;" ::: "memory")
#define CP_WAIT1()  asm volatile("cp.async.wait_group 1;" ::: "memory")
#define CP_WAIT0()  asm volatile("cp.async.wait_group 0;" ::: "memory")

// ---------------- small helpers ----------------
__device__ __forceinline__ void block_reduce2_store(float s0, float s1,
                                                    float* o0, float* o1,
                                                    float add0, float add1) {
    __shared__ float red[16];
    #pragma unroll
    for (int o = 16; o > 0; o >>= 1) {
        s0 += __shfl_down_sync(0xffffffffu, s0, o);
        s1 += __shfl_down_sync(0xffffffffu, s1, o);
    }
    int t = threadIdx.x;
    if ((t & 31) == 0) { red[t >> 5] = s0; red[8 + (t >> 5)] = s1; }
    __syncthreads();
    if (t == 0) {
        float a = 0.f, b = 0.f;
        #pragma unroll
        for (int w = 0; w < 8; w++) { a += red[w]; b += red[8 + w]; }
        *o0 = a + add0;
        *o1 = b + add1;
    }
}

// ---------------- kernel: W^T build + bf16 split ----------------
__global__ void k_prep_weights(const float* __restrict__ Wnd,
                               const float* __restrict__ Wed) {
    __shared__ float tile[32][33];
    int n0 = blockIdx.x * 32;
    int k0 = blockIdx.y * 32;
    int tx = threadIdx.x, ty = threadIdx.y;
    #pragma unroll
    for (int kk = 0; kk < 32; kk += 8) {
        int k = k0 + kk + ty;
        int n = n0 + tx;
        float v;
        if (n < 1024) v = Wnd[(size_t)k * 1024 + n];
        else if (n < 2048) { int c = n - 1024; v = Wed[(size_t)k * 1024 + c] + Wed[(size_t)(2048 + k) * 1024 + c]; }
        else { int c = n - 2048; v = Wed[(size_t)(1024 + k) * 1024 + c] - Wed[(size_t)(2048 + k) * 1024 + c]; }
        tile[kk + ty][tx] = v;
    }
    __syncthreads();
    #pragma unroll
    for (int kk = 0; kk < 32; kk += 8) {
        int n = n0 + kk + ty;
        int k = k0 + tx;
        float v = tile[tx][kk + ty];
        __nv_bfloat16 h = __float2bfloat16(v);
        g_WTh[(size_t)n * NH + k] = h;
        g_WTl[(size_t)n * NH + k] = __float2bfloat16(v - __bfloat162float(h));
    }
}

// ---------------- kernel: decode offsets + count + cls copy (fused) ----------------
__global__ void k_prep_cls(const float* __restrict__ seq, const int* __restrict__ po) {
    int b = blockIdx.x, t = threadIdx.x;
    bool wide = (po[1] == 0 && po[3] == 0);
    int val = 0;
    if (t < NOFF) {
        val = wide ? po[(b * NOFF + t) * 2] : po[b * NOFF + t];
        g_off[b * NOFF + t] = val;
    }
    if (t < 32) {
        unsigned mask = __ballot_sync(0xffffffffu, (t < NOFF) && (val > 0));
        if (t == 0) g_count[b] = __popc(mask);
    }
    ((float4*)(g_cls + (size_t)b * NH))[t] =
        ((const float4*)(seq + (size_t)b * NS * NH))[t];
}

// ---------------- kernel: segment partial sums over 64-row S tiles ----------------
__global__ void k_segsum(const float* __restrict__ seq) {
    int st = blockIdx.x;          // 0..7
    int b  = blockIdx.y;          // 0..63
    int hc = blockIdx.z;          // 0..3
    int t  = threadIdx.x;         // 0..63
    int s0 = st * 64;
    int sEnd = s0 + 63;
    int cnt = g_count[b];
    const float4* base = (const float4*)(seq + (size_t)b * NS * NH + hc * 256) + t;
    int prev = 0;
    for (int m = 0; m < cnt; m++) {
        int off = g_off[b * NOFF + m];
        int lo = prev + 1;
        if (lo < s0) lo = s0;
        int hi = off < sEnd ? off : sEnd;
        if (lo <= hi) {
            float4 a0 = make_float4(0.f,0.f,0.f,0.f), a1 = a0, a2 = a0, a3 = a0;
            int s = lo;
            for (; s + 3 <= hi; s += 4) {
                float4 v0 = base[(size_t)(s + 0) * 256];
                float4 v1 = base[(size_t)(s + 1) * 256];
                float4 v2 = base[(size_t)(s + 2) * 256];
                float4 v3 = base[(size_t)(s + 3) * 256];
                a0.x += v0.x; a0.y += v0.y; a0.z += v0.z; a0.w += v0.w;
                a1.x += v1.x; a1.y += v1.y; a1.z += v1.z; a1.w += v1.w;
                a2.x += v2.x; a2.y += v2.y; a2.z += v2.z; a2.w += v2.w;
                a3.x += v3.x; a3.y += v3.y; a3.z += v3.z; a3.w += v3.w;
            }
            for (; s <= hi; s++) {
                float4 v = base[(size_t)s * 256];
                a0.x += v.x; a0.y += v.y; a0.z += v.z; a0.w += v.w;
            }
            a0.x += a1.x + a2.x + a3.x;
            a0.y += a1.y + a2.y + a3.y;
            a0.z += a1.z + a2.z + a3.z;
            a0.w += a1.w + a2.w + a3.w;
            ((float4*)(g_part + (((size_t)(b * NST + st) * NM) + m) * NH + hc * 256))[t] = a0;
        }
        prev = off;
        if (prev >= sEnd) break;
    }
}

// ---------------- kernel: finalize node_full + bf16 hi/lo split (fused) ----------------
__global__ void k_finalize(void) {
    int m = blockIdx.x, b = blockIdx.y, t = threadIdx.x;
    int cnt = g_count[b];
    float4 o = make_float4(0.f, 0.f, 0.f, 0.f);
    if (m < cnt) {
        int off  = g_off[b * NOFF + m];
        int prev = (m == 0) ? 0 : g_off[b * NOFF + m - 1];
        int stLo = (prev + 1) >> 6, stHi = off >> 6;
        for (int st = stLo; st <= stHi; st++) {
            float4 p = ((const float4*)(g_part + (((size_t)(b * NST + st) * NM) + m) * NH))[t];
            o.x += p.x; o.y += p.y; o.z += p.z; o.w += p.w;
        }
        float sc = 1.f / (float)(off - prev);
        o.x *= sc; o.y *= sc; o.z *= sc; o.w *= sc;
    } else if (m == cnt) {
        o = ((const float4*)(g_naf + (size_t)b * NH))[t];
    }
    size_t row = (size_t)(b * NM + m);
    __nv_bfloat16 h0 = __float2bfloat16(o.x), h1 = __float2bfloat16(o.y);
    __nv_bfloat16 h2 = __float2bfloat16(o.z), h3 = __float2bfloat16(o.w);
    __nv_bfloat16 l0 = __float2bfloat16(o.x - __bfloat162float(h0));
    __nv_bfloat16 l1 = __float2bfloat16(o.y - __bfloat162float(h1));
    __nv_bfloat16 l2 = __float2bfloat16(o.z - __bfloat162float(h2));
    __nv_bfloat16 l3 = __float2bfloat16(o.w - __bfloat162float(h3));
    __nv_bfloat162 hA = __halves2bfloat162(h0, h1), hB = __halves2bfloat162(h2, h3);
    __nv_bfloat162 lA = __halves2bfloat162(l0, l1), lB = __halves2bfloat162(l2, l3);
    uint2 hv, lv;
    hv.x = *(uint32_t*)&hA; hv.y = *(uint32_t*)&hB;
    lv.x = *(uint32_t*)&lA; lv.y = *(uint32_t*)&lB;
    ((uint2*)(g_nodeH + row * NH))[t] = hv;
    ((uint2*)(g_nodeL + row * NH))[t] = lv;
}

// ---------------- kernel: GEMM1 split-K partial  cls(64x[128]) @ W[128,64] ----------
__global__ __launch_bounds__(256) void k_gemm1p(const float* __restrict__ Wnaf,
                                                const float* __restrict__ Wcd) {
    __shared__ float Xs[16 * 68];
    __shared__ float Ws[16 * 64];
    int n0 = blockIdx.x * 64;                 // 0..2047
    int ks0 = blockIdx.y * (NH / KSPLIT);     // K chunk start (128)
    const float* W = (n0 < 1024) ? Wnaf : Wcd;
    int nc0 = (n0 < 1024) ? n0 : n0 - 1024;
    int t = threadIdx.x;
    int tx = t & 15, ty = t >> 4;
    float acc[4][4] = {};
    for (int kt = ks0; kt < ks0 + NH / KSPLIT; kt += 16) {
        {
            int ml = t >> 2, k4 = t & 3;
            float4 x = *(const float4*)(g_cls + (size_t)ml * NH + kt + k4 * 4);
            Xs[(k4 * 4 + 0) * 68 + ml] = x.x;
            Xs[(k4 * 4 + 1) * 68 + ml] = x.y;
            Xs[(k4 * 4 + 2) * 68 + ml] = x.z;
            Xs[(k4 * 4 + 3) * 68 + ml] = x.w;
            int kl = t >> 4, n4 = t & 15;
            float4 w = *(const float4*)(W + (size_t)(kt + kl) * 1024 + nc0 + n4 * 4);
            *(float4*)(Ws + kl * 64 + n4 * 4) = w;
        }
        __syncthreads();
        #pragma unroll
        for (int k = 0; k < 16; k++) {
            float a[4], bb[4];
            *(float4*)a  = *(const float4*)(Xs + k * 68 + ty * 4);
            *(float4*)bb = *(const float4*)(Ws + k * 64 + tx * 4);
            #pragma unroll
            for (int i = 0; i < 4; i++)
                #pragma unroll
                for (int j = 0; j < 4; j++)
                    acc[i][j] += a[i] * bb[j];
        }
        __syncthreads();
    }
    float* dst = g_g1p + (size_t)blockIdx.y * NB * 2048;
    #pragma unroll
    for (int i = 0; i < 4; i++) {
        int m = ty * 4 + i;
        #pragma unroll
        for (int j = 0; j < 4; j++)
            dst[(size_t)m * 2048 + n0 + tx * 4 + j] = acc[i][j];
    }
}

// ---------------- kernel: GEMM1 reduce + bias + tanh ----------------
__global__ void k_gemm1r(const float* __restrict__ bnaf,
                         const float* __restrict__ bcd) {
    int idx = blockIdx.x * 256 + threadIdx.x;   // 0 .. 64*2048-1
    int m = idx >> 11, n = idx & 2047;
    float s = 0.f;
    #pragma unroll
    for (int ks = 0; ks < KSPLIT; ks++)
        s += g_g1p[(size_t)ks * NB * 2048 + idx];
    if (n < 1024) g_naf[(size_t)m * NH + n] = s + bnaf[n];
    else {
        int c = n - 1024;
        g_cdact[(size_t)m * NH + c] = tanhf(s + bcd[c]);
    }
}

// ---------------- kernel: cls logits ----------------
__global__ void k_logits(const float* __restrict__ Wco,
                         const float* __restrict__ bco,
                         float* __restrict__ out) {
    int b = blockIdx.x, t = threadIdx.x;
    const float2* w = (const float2*)Wco;
    float s0 = 0.f, s1 = 0.f;
    for (int h = t; h < NH; h += 256) {
        float x = g_cdact[(size_t)b * NH + h];
        float2 ww = w[h];
        s0 += x * ww.x; s1 += x * ww.y;
    }
    block_reduce2_store(s0, s1, out + b * 2, out + b * 2 + 1, bco[0], bco[1]);
}

// ============================================================================
// HMMA GEMM: D(1664x3072) = node(1664x1024) @ WT^T, bf16 3-term split.
// CTA 128x128, K-tile 32, 3-stage cp.async (32KB/stage, 96KB -> 2 CTA/SM).
// ============================================================================
#define TILE_B 8192
#define STAGE_B (4*TILE_B)
#define GEMM_SMEM (3*STAGE_B)

__global__ __launch_bounds__(256, 2) void k_mmagemm(const float* __restrict__ bnd) {
    extern __shared__ char smem[];
    uint32_t sb = smem_to_u32(smem);
    const int t = threadIdx.x;
    const int lane = t & 31, wid = t >> 5;
    const int wm = wid >> 2, wn = wid & 3;
    const int m0 = blockIdx.y * 128, n0 = blockIdx.x * 128;

    uint32_t swo[2], gOffA[2], gOffB[2];
    #pragma unroll
    for (int j = 0; j < 2; j++) {
        int u = j * 256 + t;
        int r = u >> 2, c = u & 3;
        uint32_t o = (uint32_t)r * 64 + (uint32_t)c * 16;
        swo[j] = o ^ ((o >> 3) & 0x30);
        gOffA[j] = (uint32_t)(m0 + r) * NH + c * 8;
        gOffB[j] = (uint32_t)(n0 + r) * NH + c * 8;
    }

    auto issue = [&](int kc) {
        uint32_t kk = (uint32_t)kc * 32;
        uint32_t d = sb + (kc % 3) * STAGE_B;
        #pragma unroll
        for (int j = 0; j < 2; j++) {
            cp16(d + 0 * TILE_B + swo[j], g_nodeH + gOffA[j] + kk);
            cp16(d + 1 * TILE_B + swo[j], g_nodeL + gOffA[j] + kk);
            cp16(d + 2 * TILE_B + swo[j], g_WTh   + gOffB[j] + kk);
            cp16(d + 3 * TILE_B + swo[j], g_WTl   + gOffB[j] + kk);
        }
        CP_COMMIT();
    };

    float acc[4][4][4] = {};

    const uint32_t aRow = (uint32_t)(wm * 64 + (lane & 15));
    const uint32_t aKhalf = (uint32_t)((lane >> 4) * 16);
    const uint32_t bRowBase = (uint32_t)(wn * 32 + ((lane >> 4) & 1) * 8 + (lane & 7));
    const uint32_t bCol = (uint32_t)(((lane >> 3) & 1) * 16);

    issue(0);
    issue(1);

    for (int kc = 0; kc < 32; kc++) {
        if (kc == 31) { CP_WAIT0(); } else { CP_WAIT1(); }
        __syncthreads();
        if (kc + 2 < 32) issue(kc + 2);
        uint32_t base = sb + (kc % 3) * STAGE_B;

        #pragma unroll
        for (int ks = 0; ks < 2; ks++) {
            uint32_t bH[2][4], bL[2][4];
            #pragma unroll
            for (int p = 0; p < 2; p++) {
                uint32_t o = (bRowBase + p * 16) * 64 + ks * 32 + bCol;
                o ^= (o >> 3) & 0x30;
                ldsm_x4(bH[p], base + 2 * TILE_B + o);
                ldsm_x4(bL[p], base + 3 * TILE_B + o);
            }
            #pragma unroll
            for (int mt = 0; mt < 4; mt++) {
                uint32_t aH[4], aL[4];
                uint32_t o = (aRow + mt * 16) * 64 + ks * 32 + aKhalf;
                o ^= (o >> 3) & 0x30;
                ldsm_x4(aH, base + o);
                ldsm_x4(aL, base + TILE_B + o);
                #pragma unroll
                for (int nt = 0; nt < 4; nt++) {
                    int p = nt >> 1, q = (nt & 1) * 2;
                    mma16816(acc[mt][nt], aH, bH[p][q], bH[p][q + 1]);
                    mma16816(acc[mt][nt], aH, bL[p][q], bL[p][q + 1]);
                    mma16816(acc[mt][nt], aL, bH[p][q], bH[p][q + 1]);
                }
            }
        }
    }

    int sec  = n0 >> 10;
    int ncol = n0 & 1023;
    float* dst = (sec == 0) ? g_ND : ((sec == 1) ? g_A : g_Bm);
    int g = lane >> 2, tq = lane & 3;
    #pragma unroll
    for (int mt = 0; mt < 4; mt++) {
        int m = m0 + wm * 64 + mt * 16 + g;
        #pragma unroll
        for (int nt = 0; nt < 4; nt++) {
            int n = ncol + wn * 32 + nt * 8 + tq * 2;
            float2 v0 = make_float2(acc[mt][nt][0], acc[mt][nt][1]);
            float2 v1 = make_float2(acc[mt][nt][2], acc[mt][nt][3]);
            if (sec == 0) {
                float b0 = bnd[n], b1 = bnd[n + 1];
                v0.x = tanhf(v0.x + b0); v0.y = tanhf(v0.y + b1);
                v1.x = tanhf(v1.x + b0); v1.y = tanhf(v1.y + b1);
            }
            *(float2*)(dst + (size_t)m * NH + n) = v0;
            *(float2*)(dst + (size_t)(m + 8) * NH + n) = v1;
        }
    }
}

// ---------------- kernel: node logits ----------------
__global__ void k_node_logits(const float* __restrict__ Wno,
                              const float* __restrict__ bno,
                              float* __restrict__ out) {
    int r = blockIdx.x, t = threadIdx.x;
    const float2* w = (const float2*)Wno;
    float s0 = 0.f, s1 = 0.f;
    for (int h = t; h < NH; h += 256) {
        float x = g_ND[(size_t)r * NH + h];
        float2 ww = w[h];
        s0 += x * ww.x; s1 += x * ww.y;
    }
    float* o = out + 128 + (size_t)r * 2;
    block_reduce2_store(s0, s1, o, o + 1, bno[0], bno[1]);
}

// ---------------- kernel: constant logits for invalid edges ----------------
__global__ void k_cvec(const float* __restrict__ bed,
                       const float* __restrict__ Weo,
                       const float* __restrict__ beo) {
    int t = threadIdx.x;
    const float2* w = (const float2*)Weo;
    float s0 = 0.f, s1 = 0.f;
    for (int h = t; h < NH; h += 256) {
        float v = tanhf(bed[h]);
        float2 ww = w[h];
        s0 += v * ww.x; s1 += v * ww.y;
    }
    block_reduce2_store(s0, s1, &g_cvec[0], &g_cvec[1], beo[0], beo[1]);
}

// ---------------- kernel: edge logits ----------------
__global__ void k_edges(const float* __restrict__ bed,
                        const float* __restrict__ Weo,
                        const float* __restrict__ beo,
                        float* __restrict__ out) {
    int k = blockIdx.x, b = blockIdx.y, t = threadIdx.x;
    int n = g_count[b] + 1;
    float* o = out + 128 + NR * 2 + (size_t)(b * NE + k) * 2;
    if (k >= n * n) {
        if (t < 2) o[t] = g_cvec[t];
        return;
    }
    int i = k / n, j = k % n;
    const float* Ar = g_A  + (size_t)(b * NM + j) * NH;
    const float* Br = g_Bm + (size_t)(b * NM + i) * NH;
    const float2* w = (const float2*)Weo;
    float s0 = 0.f, s1 = 0.f;
    for (int h = t; h < NH; h += 256) {
        float v = tanhf(Ar[h] + Br[h] + bed[h]);
        float2 ww = w[h];
        s0 += v * ww.x; s1 += v * ww.y;
    }
    block_reduce2_store(s0, s1, o, o + 1, beo[0], beo[1]);
}

// ---------------- launch ----------------
extern "C" void kernel_launch(void* const* d_in, const int* in_sizes, int n_in,
                              void* d_out, int out_size) {
    const float* seq  = (const float*)d_in[0];
    const int*   po   = (const int*)  d_in[1];
    const float* Wnaf = (const float*)d_in[4];
    const float* bnaf = (const float*)d_in[5];
    const float* Wcd  = (const float*)d_in[6];
    const float* bcd  = (const float*)d_in[7];
    const float* Wco  = (const float*)d_in[8];
    const float* bco  = (const float*)d_in[9];
    const float* Wnd  = (const float*)d_in[10];
    const float* bnd  = (const float*)d_in[11];
    const float* Wno  = (const float*)d_in[12];
    const float* bno  = (const float*)d_in[13];
    const float* Wed  = (const float*)d_in[14];
    const float* bed  = (const float*)d_in[15];
    const float* Weo  = (const float*)d_in[16];
    const float* beo  = (const float*)d_in[17];
    float* out = (float*)d_out;

    static bool attr_done = false;
    if (!attr_done) {
        cudaFuncSetAttribute(k_mmagemm, cudaFuncAttributeMaxDynamicSharedMemorySize, GEMM_SMEM);
        attr_done = true;
    }

    // launch #4 is the one ncu captures -> place k_prep_weights there this round
    k_prep_cls<<<NB, 256>>>(seq, po);                       // 1
    k_gemm1p<<<dim3(32, KSPLIT), 256>>>(Wnaf, Wcd);         // 2
    k_gemm1r<<<512, 256>>>(bnaf, bcd);                      // 3
    k_prep_weights<<<dim3(96, 32), dim3(32, 8)>>>(Wnd, Wed);// 4  <- profiled
    k_segsum<<<dim3(NST, NB, 4), 64>>>(seq);                // 5
    k_finalize<<<dim3(NM, NB), 256>>>();                    // 6
    k_mmagemm<<<dim3(24, 13), 256, GEMM_SMEM>>>(bnd);       // 7
    k_logits<<<NB, 256>>>(Wco, bco, out);                   // 8
    k_node_logits<<<NR, 256>>>(Wno, bno, out);              // 9
    k_cvec<<<1, 256>>>(bed, Weo, beo);                      // 10
    k_edges<<<dim3(NE, NB), 256>>>(bed, Weo, beo, out);     // 11
}

// round 6
// speedup vs baseline: 2.6833x; 1.1397x over previous
#include <cuda_runtime.h>
#include <cuda_bf16.h>
#include <math.h>
#include <stdint.h>

#define NB 64
#define NS 512
#define NH 1024
#define NM 26
#define NE 676
#define NR (NB*NM)          // 1664 node rows total
#define NOFF (NM-1)         // 25 offsets per batch
#define NST 8               // S tiles of 64 rows
#define KSPLIT 8            // gemm1 K splits

// ---------------- scratch (device globals; no allocation allowed) ----------------
__device__ int   g_off[NB*NOFF];
__device__ int   g_count[NB];
__device__ int   g_rowstart[NB];
__device__ int   g_rowmap[NR];
__device__ int   g_ract;
__device__ __align__(16) float g_cls[NB*NH];
__device__ __align__(16) float g_naf[NB*NH];
__device__ __align__(16) float g_cdact[NB*NH];
__device__ __align__(16) float g_g1p[KSPLIT*NB*2048];  // gemm1 split-K partials
__device__ __align__(16) float g_part[NB*NST*NM*NH];   // segment tile partials
__device__ __align__(16) float g_ND[NR*NH];            // tanh(node_full @ W_nd + b_nd)
__device__ __align__(16) float g_A[NR*NH];             // node_full @ (W1+W3)
__device__ __align__(16) float g_Bm[NR*NH];            // node_full @ (W2-W3)
__device__ float g_cvec[2];   // edge logits of all-zero edge row
__device__ float g_nlc[2];    // node logits of all-zero node row
// bf16 split operands for tensor-core GEMM (COMPACTED rows)
__device__ __align__(16) __nv_bfloat16 g_nodeH[NR*NH];
__device__ __align__(16) __nv_bfloat16 g_nodeL[NR*NH];
__device__ __align__(16) __nv_bfloat16 g_WTh[3072*NH];  // W^T (N-major, K cols), hi
__device__ __align__(16) __nv_bfloat16 g_WTl[3072*NH];  // lo

// ============================================================================
// portable PTX helpers (no sm_103a-only features)
// ============================================================================
__device__ __forceinline__ uint32_t smem_to_u32(const void* p) {
    uint32_t a;
    asm("{ .reg .u64 t; cvta.to.shared.u64 t, %1; cvt.u32.u64 %0, t; }" : "=r"(a) : "l"(p));
    return a;
}
__device__ __forceinline__ void ldsm_x4(uint32_t (&r)[4], uint32_t addr) {
    asm volatile("ldmatrix.sync.aligned.m8n8.x4.shared.b16 {%0,%1,%2,%3}, [%4];"
        : "=r"(r[0]), "=r"(r[1]), "=r"(r[2]), "=r"(r[3]) : "r"(addr));
}
__device__ __forceinline__ void mma16816(float (&c)[4], const uint32_t (&a)[4],
                                         uint32_t b0, uint32_t b1) {
    asm volatile("mma.sync.aligned.m16n8k16.row.col.f32.bf16.bf16.f32 "
        "{%0,%1,%2,%3}, {%4,%5,%6,%7}, {%8,%9}, {%0,%1,%2,%3};"
        : "+f"(c[0]), "+f"(c[1]), "+f"(c[2]), "+f"(c[3])
        : "r"(a[0]), "r"(a[1]), "r"(a[2]), "r"(a[3]), "r"(b0), "r"(b1));
}
__device__ __forceinline__ void cp16(uint32_t dst, const void* src) {
    asm volatile("cp.async.cg.shared.global [%0], [%1], 16;" :: "r"(dst), "l"(src));
}
#define CP_COMMIT() asm volatile("cp.async.commit_group;" ::: "memory")
#define CP_WAIT1()  asm volatile("cp.async.wait_group 1;" ::: "memory")
#define CP_WAIT0()  asm volatile("cp.async.wait_group 0;" ::: "memory")

// ---------------- small helpers ----------------
__device__ __forceinline__ void block_reduce2_store(float s0, float s1,
                                                    float* o0, float* o1,
                                                    float add0, float add1) {
    __shared__ float red[16];
    #pragma unroll
    for (int o = 16; o > 0; o >>= 1) {
        s0 += __shfl_down_sync(0xffffffffu, s0, o);
        s1 += __shfl_down_sync(0xffffffffu, s1, o);
    }
    int t = threadIdx.x;
    if ((t & 31) == 0) { red[t >> 5] = s0; red[8 + (t >> 5)] = s1; }
    __syncthreads();
    if (t == 0) {
        float a = 0.f, b = 0.f;
        #pragma unroll
        for (int w = 0; w < 8; w++) { a += red[w]; b += red[8 + w]; }
        *o0 = a + add0;
        *o1 = b + add1;
    }
}

// ---------------- kernel: decode offsets + count + cls copy (fused) ----------------
__global__ void k_prep_cls(const float* __restrict__ seq, const int* __restrict__ po) {
    int b = blockIdx.x, t = threadIdx.x;
    bool wide = (po[1] == 0 && po[3] == 0);
    int val = 0;
    if (t < NOFF) {
        val = wide ? po[(b * NOFF + t) * 2] : po[b * NOFF + t];
        g_off[b * NOFF + t] = val;
    }
    if (t < 32) {
        unsigned mask = __ballot_sync(0xffffffffu, (t < NOFF) && (val > 0));
        if (t == 0) g_count[b] = __popc(mask);
    }
    ((float4*)(g_cls + (size_t)b * NH))[t] =
        ((const float4*)(seq + (size_t)b * NS * NH))[t];
}

// ---------------- kernel: row compaction prefix + rowmap (1 block) ----------------
__global__ void k_prefix(void) {
    __shared__ int sstart[NB];
    int t = threadIdx.x;
    if (t == 0) {
        int acc = 0;
        for (int b = 0; b < NB; b++) {
            sstart[b] = acc;
            g_rowstart[b] = acc;
            acc += g_count[b] + 1;
        }
        g_ract = acc;
    }
    __syncthreads();
    for (int i = t; i < NR; i += 256) g_rowmap[i] = -1;
    __syncthreads();
    for (int i = t; i < NB * NM; i += 256) {
        int b = i / NM, m = i - b * NM;
        if (m <= g_count[b]) g_rowmap[sstart[b] + m] = i;
    }
}

// ---------------- kernel: segment partial sums over 64-row S tiles ----------------
__global__ void k_segsum(const float* __restrict__ seq) {
    int st = blockIdx.x;          // 0..7
    int b  = blockIdx.y;          // 0..63
    int hc = blockIdx.z;          // 0..3
    int t  = threadIdx.x;         // 0..63
    int s0 = st * 64;
    int sEnd = s0 + 63;
    int cnt = g_count[b];
    const float4* base = (const float4*)(seq + (size_t)b * NS * NH + hc * 256) + t;
    int prev = 0;
    for (int m = 0; m < cnt; m++) {
        int off = g_off[b * NOFF + m];
        int lo = prev + 1;
        if (lo < s0) lo = s0;
        int hi = off < sEnd ? off : sEnd;
        if (lo <= hi) {
            float4 a0 = make_float4(0.f,0.f,0.f,0.f), a1 = a0, a2 = a0, a3 = a0;
            int s = lo;
            for (; s + 3 <= hi; s += 4) {
                float4 v0 = base[(size_t)(s + 0) * 256];
                float4 v1 = base[(size_t)(s + 1) * 256];
                float4 v2 = base[(size_t)(s + 2) * 256];
                float4 v3 = base[(size_t)(s + 3) * 256];
                a0.x += v0.x; a0.y += v0.y; a0.z += v0.z; a0.w += v0.w;
                a1.x += v1.x; a1.y += v1.y; a1.z += v1.z; a1.w += v1.w;
                a2.x += v2.x; a2.y += v2.y; a2.z += v2.z; a2.w += v2.w;
                a3.x += v3.x; a3.y += v3.y; a3.z += v3.z; a3.w += v3.w;
            }
            for (; s <= hi; s++) {
                float4 v = base[(size_t)s * 256];
                a0.x += v.x; a0.y += v.y; a0.z += v.z; a0.w += v.w;
            }
            a0.x += a1.x + a2.x + a3.x;
            a0.y += a1.y + a2.y + a3.y;
            a0.z += a1.z + a2.z + a3.z;
            a0.w += a1.w + a2.w + a3.w;
            ((float4*)(g_part + (((size_t)(b * NST + st) * NM) + m) * NH + hc * 256))[t] = a0;
        }
        prev = off;
        if (prev >= sEnd) break;
    }
}

// ---------------- kernel: GEMM1 split-K partial  cls(64x[128]) @ W[128,64] ----------
__global__ __launch_bounds__(256) void k_gemm1p(const float* __restrict__ Wnaf,
                                                const float* __restrict__ Wcd) {
    __shared__ float Xs[16 * 68];
    __shared__ float Ws[16 * 64];
    int n0 = blockIdx.x * 64;                 // 0..2047
    int ks0 = blockIdx.y * (NH / KSPLIT);     // K chunk start (128)
    const float* W = (n0 < 1024) ? Wnaf : Wcd;
    int nc0 = (n0 < 1024) ? n0 : n0 - 1024;
    int t = threadIdx.x;
    int tx = t & 15, ty = t >> 4;
    float acc[4][4] = {};
    for (int kt = ks0; kt < ks0 + NH / KSPLIT; kt += 16) {
        {
            int ml = t >> 2, k4 = t & 3;
            float4 x = *(const float4*)(g_cls + (size_t)ml * NH + kt + k4 * 4);
            Xs[(k4 * 4 + 0) * 68 + ml] = x.x;
            Xs[(k4 * 4 + 1) * 68 + ml] = x.y;
            Xs[(k4 * 4 + 2) * 68 + ml] = x.z;
            Xs[(k4 * 4 + 3) * 68 + ml] = x.w;
            int kl = t >> 4, n4 = t & 15;
            float4 w = *(const float4*)(W + (size_t)(kt + kl) * 1024 + nc0 + n4 * 4);
            *(float4*)(Ws + kl * 64 + n4 * 4) = w;
        }
        __syncthreads();
        #pragma unroll
        for (int k = 0; k < 16; k++) {
            float a[4], bb[4];
            *(float4*)a  = *(const float4*)(Xs + k * 68 + ty * 4);
            *(float4*)bb = *(const float4*)(Ws + k * 64 + tx * 4);
            #pragma unroll
            for (int i = 0; i < 4; i++)
                #pragma unroll
                for (int j = 0; j < 4; j++)
                    acc[i][j] += a[i] * bb[j];
        }
        __syncthreads();
    }
    float* dst = g_g1p + (size_t)blockIdx.y * NB * 2048;
    #pragma unroll
    for (int i = 0; i < 4; i++) {
        int m = ty * 4 + i;
        #pragma unroll
        for (int j = 0; j < 4; j++)
            dst[(size_t)m * 2048 + n0 + tx * 4 + j] = acc[i][j];
    }
}

// ---------------- kernel: GEMM1 reduce + bias + tanh ----------------
__global__ void k_gemm1r(const float* __restrict__ bnaf,
                         const float* __restrict__ bcd) {
    int idx = blockIdx.x * 256 + threadIdx.x;   // 0 .. 64*2048-1
    int m = idx >> 11, n = idx & 2047;
    float s = 0.f;
    #pragma unroll
    for (int ks = 0; ks < KSPLIT; ks++)
        s += g_g1p[(size_t)ks * NB * 2048 + idx];
    if (n < 1024) g_naf[(size_t)m * NH + n] = s + bnaf[n];
    else {
        int c = n - 1024;
        g_cdact[(size_t)m * NH + c] = tanhf(s + bcd[c]);
    }
}

// ---------------- kernel: W^T build + bf16 split ----------------
__global__ void k_prep_weights(const float* __restrict__ Wnd,
                               const float* __restrict__ Wed) {
    __shared__ float tile[32][33];
    int n0 = blockIdx.x * 32;
    int k0 = blockIdx.y * 32;
    int tx = threadIdx.x, ty = threadIdx.y;
    #pragma unroll
    for (int kk = 0; kk < 32; kk += 8) {
        int k = k0 + kk + ty;
        int n = n0 + tx;
        float v;
        if (n < 1024) v = Wnd[(size_t)k * 1024 + n];
        else if (n < 2048) { int c = n - 1024; v = Wed[(size_t)k * 1024 + c] + Wed[(size_t)(2048 + k) * 1024 + c]; }
        else { int c = n - 2048; v = Wed[(size_t)(1024 + k) * 1024 + c] - Wed[(size_t)(2048 + k) * 1024 + c]; }
        tile[kk + ty][tx] = v;
    }
    __syncthreads();
    #pragma unroll
    for (int kk = 0; kk < 32; kk += 8) {
        int n = n0 + kk + ty;
        int k = k0 + tx;
        float v = tile[tx][kk + ty];
        __nv_bfloat16 h = __float2bfloat16(v);
        g_WTh[(size_t)n * NH + k] = h;
        g_WTl[(size_t)n * NH + k] = __float2bfloat16(v - __bfloat162float(h));
    }
}

// ---------------- kernel: finalize node rows, write COMPACTED bf16 hi/lo ----------
__global__ void k_finalize(void) {
    int m = blockIdx.x, b = blockIdx.y, t = threadIdx.x;
    int cnt = g_count[b];
    if (m > cnt) return;                        // zero rows are not materialized
    float4 o = make_float4(0.f, 0.f, 0.f, 0.f);
    if (m < cnt) {
        int off  = g_off[b * NOFF + m];
        int prev = (m == 0) ? 0 : g_off[b * NOFF + m - 1];
        int stLo = (prev + 1) >> 6, stHi = off >> 6;
        for (int st = stLo; st <= stHi; st++) {
            float4 p = ((const float4*)(g_part + (((size_t)(b * NST + st) * NM) + m) * NH))[t];
            o.x += p.x; o.y += p.y; o.z += p.z; o.w += p.w;
        }
        float sc = 1.f / (float)(off - prev);
        o.x *= sc; o.y *= sc; o.z *= sc; o.w *= sc;
    } else {
        o = ((const float4*)(g_naf + (size_t)b * NH))[t];
    }
    size_t row = (size_t)(g_rowstart[b] + m);   // compacted row
    __nv_bfloat16 h0 = __float2bfloat16(o.x), h1 = __float2bfloat16(o.y);
    __nv_bfloat16 h2 = __float2bfloat16(o.z), h3 = __float2bfloat16(o.w);
    __nv_bfloat16 l0 = __float2bfloat16(o.x - __bfloat162float(h0));
    __nv_bfloat16 l1 = __float2bfloat16(o.y - __bfloat162float(h1));
    __nv_bfloat16 l2 = __float2bfloat16(o.z - __bfloat162float(h2));
    __nv_bfloat16 l3 = __float2bfloat16(o.w - __bfloat162float(h3));
    __nv_bfloat162 hA = __halves2bfloat162(h0, h1), hB = __halves2bfloat162(h2, h3);
    __nv_bfloat162 lA = __halves2bfloat162(l0, l1), lB = __halves2bfloat162(l2, l3);
    uint2 hv, lv;
    hv.x = *(uint32_t*)&hA; hv.y = *(uint32_t*)&hB;
    lv.x = *(uint32_t*)&lA; lv.y = *(uint32_t*)&lB;
    ((uint2*)(g_nodeH + row * NH))[t] = hv;
    ((uint2*)(g_nodeL + row * NH))[t] = lv;
}

// ---------------- kernel: cls logits ----------------
__global__ void k_logits(const float* __restrict__ Wco,
                         const float* __restrict__ bco,
                         float* __restrict__ out) {
    int b = blockIdx.x, t = threadIdx.x;
    const float2* w = (const float2*)Wco;
    float s0 = 0.f, s1 = 0.f;
    for (int h = t; h < NH; h += 256) {
        float x = g_cdact[(size_t)b * NH + h];
        float2 ww = w[h];
        s0 += x * ww.x; s1 += x * ww.y;
    }
    block_reduce2_store(s0, s1, out + b * 2, out + b * 2 + 1, bco[0], bco[1]);
}

// ============================================================================
// HMMA GEMM on COMPACTED rows: D(ract x 3072) = node @ WT^T, bf16 3-term split.
// CTA 128x128, K-tile 32, 3-stage cp.async (96KB -> 2 CTA/SM). Static grid
// 24x13; CTAs beyond the active compacted row count exit immediately.
// ============================================================================
#define TILE_B 8192
#define STAGE_B (4*TILE_B)
#define GEMM_SMEM (3*STAGE_B)

__global__ __launch_bounds__(256, 2) void k_mmagemm(const float* __restrict__ bnd) {
    const int m0 = blockIdx.y * 128, n0 = blockIdx.x * 128;
    if (m0 >= g_ract) return;                   // compaction early-exit
    extern __shared__ char smem[];
    uint32_t sb = smem_to_u32(smem);
    const int t = threadIdx.x;
    const int lane = t & 31, wid = t >> 5;
    const int wm = wid >> 2, wn = wid & 3;

    uint32_t swo[2], gOffA[2], gOffB[2];
    #pragma unroll
    for (int j = 0; j < 2; j++) {
        int u = j * 256 + t;
        int r = u >> 2, c = u & 3;
        uint32_t o = (uint32_t)r * 64 + (uint32_t)c * 16;
        swo[j] = o ^ ((o >> 3) & 0x30);
        gOffA[j] = (uint32_t)(m0 + r) * NH + c * 8;
        gOffB[j] = (uint32_t)(n0 + r) * NH + c * 8;
    }

    auto issue = [&](int kc) {
        uint32_t kk = (uint32_t)kc * 32;
        uint32_t d = sb + (kc % 3) * STAGE_B;
        #pragma unroll
        for (int j = 0; j < 2; j++) {
            cp16(d + 0 * TILE_B + swo[j], g_nodeH + gOffA[j] + kk);
            cp16(d + 1 * TILE_B + swo[j], g_nodeL + gOffA[j] + kk);
            cp16(d + 2 * TILE_B + swo[j], g_WTh   + gOffB[j] + kk);
            cp16(d + 3 * TILE_B + swo[j], g_WTl   + gOffB[j] + kk);
        }
        CP_COMMIT();
    };

    float acc[4][4][4] = {};

    const uint32_t aRow = (uint32_t)(wm * 64 + (lane & 15));
    const uint32_t aKhalf = (uint32_t)((lane >> 4) * 16);
    const uint32_t bRowBase = (uint32_t)(wn * 32 + ((lane >> 4) & 1) * 8 + (lane & 7));
    const uint32_t bCol = (uint32_t)(((lane >> 3) & 1) * 16);

    issue(0);
    issue(1);

    for (int kc = 0; kc < 32; kc++) {
        if (kc == 31) { CP_WAIT0(); } else { CP_WAIT1(); }
        __syncthreads();
        if (kc + 2 < 32) issue(kc + 2);
        uint32_t base = sb + (kc % 3) * STAGE_B;

        #pragma unroll
        for (int ks = 0; ks < 2; ks++) {
            uint32_t bH[2][4], bL[2][4];
            #pragma unroll
            for (int p = 0; p < 2; p++) {
                uint32_t o = (bRowBase + p * 16) * 64 + ks * 32 + bCol;
                o ^= (o >> 3) & 0x30;
                ldsm_x4(bH[p], base + 2 * TILE_B + o);
                ldsm_x4(bL[p], base + 3 * TILE_B + o);
            }
            #pragma unroll
            for (int mt = 0; mt < 4; mt++) {
                uint32_t aH[4], aL[4];
                uint32_t o = (aRow + mt * 16) * 64 + ks * 32 + aKhalf;
                o ^= (o >> 3) & 0x30;
                ldsm_x4(aH, base + o);
                ldsm_x4(aL, base + TILE_B + o);
                #pragma unroll
                for (int nt = 0; nt < 4; nt++) {
                    int p = nt >> 1, q = (nt & 1) * 2;
                    mma16816(acc[mt][nt], aH, bH[p][q], bH[p][q + 1]);
                    mma16816(acc[mt][nt], aH, bL[p][q], bL[p][q + 1]);
                    mma16816(acc[mt][nt], aL, bH[p][q], bH[p][q + 1]);
                }
            }
        }
    }

    // ---- epilogue: scatter through rowmap ----
    int sec  = n0 >> 10;
    int ncol = n0 & 1023;
    float* dst = (sec == 0) ? g_ND : ((sec == 1) ? g_A : g_Bm);
    int g = lane >> 2, tq = lane & 3;
    #pragma unroll
    for (int mt = 0; mt < 4; mt++) {
        int m = m0 + wm * 64 + mt * 16 + g;
        int r0 = g_rowmap[m];
        int r1 = g_rowmap[m + 8];
        #pragma unroll
        for (int nt = 0; nt < 4; nt++) {
            int n = ncol + wn * 32 + nt * 8 + tq * 2;
            float2 v0 = make_float2(acc[mt][nt][0], acc[mt][nt][1]);
            float2 v1 = make_float2(acc[mt][nt][2], acc[mt][nt][3]);
            if (sec == 0) {
                float b0 = bnd[n], b1 = bnd[n + 1];
                v0.x = tanhf(v0.x + b0); v0.y = tanhf(v0.y + b1);
                v1.x = tanhf(v1.x + b0); v1.y = tanhf(v1.y + b1);
            }
            if (r0 >= 0) *(float2*)(dst + (size_t)r0 * NH + n) = v0;
            if (r1 >= 0) *(float2*)(dst + (size_t)r1 * NH + n) = v1;
        }
    }
}

// ---------------- kernel: node logits (constant for zero rows) ----------------
__global__ void k_node_logits(const float* __restrict__ Wno,
                              const float* __restrict__ bno,
                              float* __restrict__ out) {
    int r = blockIdx.x, t = threadIdx.x;
    int b = r / NM, m = r - b * NM;
    float* o = out + 128 + (size_t)r * 2;
    if (m > g_count[b]) {
        if (t < 2) o[t] = g_nlc[t];
        return;
    }
    const float2* w = (const float2*)Wno;
    float s0 = 0.f, s1 = 0.f;
    for (int h = t; h < NH; h += 256) {
        float x = g_ND[(size_t)r * NH + h];
        float2 ww = w[h];
        s0 += x * ww.x; s1 += x * ww.y;
    }
    block_reduce2_store(s0, s1, o, o + 1, bno[0], bno[1]);
}

// ---------------- kernel: constants for all-zero edge row / node row ----------------
__global__ void k_cvec2(const float* __restrict__ bed,
                        const float* __restrict__ Weo,
                        const float* __restrict__ beo,
                        const float* __restrict__ bnd,
                        const float* __restrict__ Wno,
                        const float* __restrict__ bno) {
    int which = blockIdx.x;                 // 0: edge const, 1: node const
    const float*  bias = which ? bnd : bed;
    const float2* w    = which ? (const float2*)Wno : (const float2*)Weo;
    const float*  b2   = which ? bno : beo;
    float* dstp        = which ? g_nlc : g_cvec;
    int t = threadIdx.x;
    float s0 = 0.f, s1 = 0.f;
    for (int h = t; h < NH; h += 256) {
        float v = tanhf(bias[h]);
        float2 ww = w[h];
        s0 += v * ww.x; s1 += v * ww.y;
    }
    block_reduce2_store(s0, s1, &dstp[0], &dstp[1], b2[0], b2[1]);
}

// ---------------- kernel: edge logits ----------------
__global__ void k_edges(const float* __restrict__ bed,
                        const float* __restrict__ Weo,
                        const float* __restrict__ beo,
                        float* __restrict__ out) {
    int k = blockIdx.x, b = blockIdx.y, t = threadIdx.x;
    int n = g_count[b] + 1;
    float* o = out + 128 + NR * 2 + (size_t)(b * NE + k) * 2;
    if (k >= n * n) {
        if (t < 2) o[t] = g_cvec[t];
        return;
    }
    int i = k / n, j = k % n;
    const float* Ar = g_A  + (size_t)(b * NM + j) * NH;
    const float* Br = g_Bm + (size_t)(b * NM + i) * NH;
    const float2* w = (const float2*)Weo;
    float s0 = 0.f, s1 = 0.f;
    for (int h = t; h < NH; h += 256) {
        float v = tanhf(Ar[h] + Br[h] + bed[h]);
        float2 ww = w[h];
        s0 += v * ww.x; s1 += v * ww.y;
    }
    block_reduce2_store(s0, s1, o, o + 1, beo[0], beo[1]);
}

// ---------------- launch ----------------
extern "C" void kernel_launch(void* const* d_in, const int* in_sizes, int n_in,
                              void* d_out, int out_size) {
    const float* seq  = (const float*)d_in[0];
    const int*   po   = (const int*)  d_in[1];
    const float* Wnaf = (const float*)d_in[4];
    const float* bnaf = (const float*)d_in[5];
    const float* Wcd  = (const float*)d_in[6];
    const float* bcd  = (const float*)d_in[7];
    const float* Wco  = (const float*)d_in[8];
    const float* bco  = (const float*)d_in[9];
    const float* Wnd  = (const float*)d_in[10];
    const float* bnd  = (const float*)d_in[11];
    const float* Wno  = (const float*)d_in[12];
    const float* bno  = (const float*)d_in[13];
    const float* Wed  = (const float*)d_in[14];
    const float* bed  = (const float*)d_in[15];
    const float* Weo  = (const float*)d_in[16];
    const float* beo  = (const float*)d_in[17];
    float* out = (float*)d_out;

    static bool attr_done = false;
    if (!attr_done) {
        cudaFuncSetAttribute(k_mmagemm, cudaFuncAttributeMaxDynamicSharedMemorySize, GEMM_SMEM);
        attr_done = true;
    }

    k_prep_cls<<<NB, 256>>>(seq, po);                       // 1
    k_prefix<<<1, 256>>>();                                 // 2
    k_segsum<<<dim3(NST, NB, 4), 64>>>(seq);                // 3
    k_gemm1p<<<dim3(32, KSPLIT), 256>>>(Wnaf, Wcd);         // 4  <- profiled
    k_gemm1r<<<512, 256>>>(bnaf, bcd);                      // 5
    k_prep_weights<<<dim3(96, 32), dim3(32, 8)>>>(Wnd, Wed);// 6
    k_finalize<<<dim3(NM, NB), 256>>>();                    // 7
    k_mmagemm<<<dim3(24, 13), 256, GEMM_SMEM>>>(bnd);       // 8
    k_cvec2<<<2, 256>>>(bed, Weo, beo, bnd, Wno, bno);      // 9
    k_logits<<<NB, 256>>>(Wco, bco, out);                   // 10
    k_node_logits<<<NR, 256>>>(Wno, bno, out);              // 11
    k_edges<<<dim3(NE, NB), 256>>>(bed, Weo, beo, out);     // 12
}

// round 7
// speedup vs baseline: 3.0868x; 1.1504x over previous
#include <cuda_runtime.h>
#include <cuda_bf16.h>
#include <math.h>
#include <stdint.h>

#define NB 64
#define NS 512
#define NH 1024
#define NM 26
#define NE 676
#define NR (NB*NM)          // 1664 node rows total
#define NOFF (NM-1)         // 25 offsets per batch
#define NST 8               // S tiles of 64 rows
#define KSPLIT 16           // gemm1 K splits

// ---------------- scratch (device globals; no allocation allowed) ----------------
__device__ int   g_off[NB*NOFF];
__device__ int   g_count[NB];
__device__ int   g_rowstart[NB];
__device__ int   g_rowmap[NR];
__device__ int   g_ract;
__device__ __align__(16) float g_cls[NB*NH];
__device__ __align__(16) float g_naf[NB*NH];
__device__ __align__(16) float g_cdact[NB*NH];
__device__ __align__(16) float g_g1p[KSPLIT*NB*2048];  // gemm1 split-K partials
__device__ __align__(16) float g_part[NB*NST*NM*NH];   // segment tile partials
__device__ __align__(16) float g_ND[NR*NH];            // tanh(node_full @ W_nd + b_nd)
__device__ __align__(16) float g_A[NR*NH];             // node_full @ (W1+W3)
__device__ __align__(16) float g_Bm[NR*NH];            // node_full @ (W2-W3)
__device__ float g_cvec[2];   // edge logits of all-zero edge row
__device__ float g_nlc[2];    // node logits of all-zero node row
// bf16 split operands for tensor-core GEMM (COMPACTED rows)
__device__ __align__(16) __nv_bfloat16 g_nodeH[NR*NH];
__device__ __align__(16) __nv_bfloat16 g_nodeL[NR*NH];
__device__ __align__(16) __nv_bfloat16 g_WTh[3072*NH];  // W^T (N-major, K cols), hi
__device__ __align__(16) __nv_bfloat16 g_WTl[3072*NH];  // lo

// ============================================================================
// portable PTX helpers (no sm_103a-only features)
// ============================================================================
__device__ __forceinline__ uint32_t smem_to_u32(const void* p) {
    uint32_t a;
    asm("{ .reg .u64 t; cvta.to.shared.u64 t, %1; cvt.u32.u64 %0, t; }" : "=r"(a) : "l"(p));
    return a;
}
__device__ __forceinline__ void ldsm_x4(uint32_t (&r)[4], uint32_t addr) {
    asm volatile("ldmatrix.sync.aligned.m8n8.x4.shared.b16 {%0,%1,%2,%3}, [%4];"
        : "=r"(r[0]), "=r"(r[1]), "=r"(r[2]), "=r"(r[3]) : "r"(addr));
}
__device__ __forceinline__ void mma16816(float (&c)[4], const uint32_t (&a)[4],
                                         uint32_t b0, uint32_t b1) {
    asm volatile("mma.sync.aligned.m16n8k16.row.col.f32.bf16.bf16.f32 "
        "{%0,%1,%2,%3}, {%4,%5,%6,%7}, {%8,%9}, {%0,%1,%2,%3};"
        : "+f"(c[0]), "+f"(c[1]), "+f"(c[2]), "+f"(c[3])
        : "r"(a[0]), "r"(a[1]), "r"(a[2]), "r"(a[3]), "r"(b0), "r"(b1));
}
__device__ __forceinline__ void cp16(uint32_t dst, const void* src) {
    asm volatile("cp.async.cg.shared.global [%0], [%1], 16;" :: "r"(dst), "l"(src));
}
#define CP_COMMIT() asm volatile("cp.async.commit_group;" ::: "memory")
#define CP_WAIT1()  asm volatile("cp.async.wait_group 1;" ::: "memory")
#define CP_WAIT0()  asm volatile("cp.async.wait_group 0;" ::: "memory")

// ---------------- small helpers ----------------
__device__ __forceinline__ void block_reduce2_store(float s0, float s1,
                                                    float* o0, float* o1,
                                                    float add0, float add1) {
    __shared__ float red[16];
    #pragma unroll
    for (int o = 16; o > 0; o >>= 1) {
        s0 += __shfl_down_sync(0xffffffffu, s0, o);
        s1 += __shfl_down_sync(0xffffffffu, s1, o);
    }
    int t = threadIdx.x;
    if ((t & 31) == 0) { red[t >> 5] = s0; red[8 + (t >> 5)] = s1; }
    __syncthreads();
    if (t == 0) {
        float a = 0.f, b = 0.f;
        #pragma unroll
        for (int w = 0; w < 8; w++) { a += red[w]; b += red[8 + w]; }
        *o0 = a + add0;
        *o1 = b + add1;
    }
}

// ---------------- kernel: decode offsets + count + cls copy (fused) ----------------
__global__ void k_prep_cls(const float* __restrict__ seq, const int* __restrict__ po) {
    int b = blockIdx.x, t = threadIdx.x;
    bool wide = (po[1] == 0 && po[3] == 0);
    int val = 0;
    if (t < NOFF) {
        val = wide ? po[(b * NOFF + t) * 2] : po[b * NOFF + t];
        g_off[b * NOFF + t] = val;
    }
    if (t < 32) {
        unsigned mask = __ballot_sync(0xffffffffu, (t < NOFF) && (val > 0));
        if (t == 0) g_count[b] = __popc(mask);
    }
    ((float4*)(g_cls + (size_t)b * NH))[t] =
        ((const float4*)(seq + (size_t)b * NS * NH))[t];
}

// ---------------- kernel: row compaction prefix + rowmap (1 block) ----------------
__global__ void k_prefix(void) {
    __shared__ int sstart[NB];
    int t = threadIdx.x;
    if (t == 0) {
        int acc = 0;
        for (int b = 0; b < NB; b++) {
            sstart[b] = acc;
            g_rowstart[b] = acc;
            acc += g_count[b] + 1;
        }
        g_ract = acc;
    }
    __syncthreads();
    for (int i = t; i < NR; i += 256) g_rowmap[i] = -1;
    __syncthreads();
    for (int i = t; i < NB * NM; i += 256) {
        int b = i / NM, m = i - b * NM;
        if (m <= g_count[b]) g_rowmap[sstart[b] + m] = i;
    }
}

// ---------------- kernel: segment partial sums over 64-row S tiles ----------------
__global__ void k_segsum(const float* __restrict__ seq) {
    int st = blockIdx.x;          // 0..7
    int b  = blockIdx.y;          // 0..63
    int hc = blockIdx.z;          // 0..3
    int t  = threadIdx.x;         // 0..63
    int s0 = st * 64;
    int sEnd = s0 + 63;
    int cnt = g_count[b];
    const float4* base = (const float4*)(seq + (size_t)b * NS * NH + hc * 256) + t;
    int prev = 0;
    for (int m = 0; m < cnt; m++) {
        int off = g_off[b * NOFF + m];
        int lo = prev + 1;
        if (lo < s0) lo = s0;
        int hi = off < sEnd ? off : sEnd;
        if (lo <= hi) {
            float4 a0 = make_float4(0.f,0.f,0.f,0.f), a1 = a0, a2 = a0, a3 = a0;
            int s = lo;
            for (; s + 3 <= hi; s += 4) {
                float4 v0 = base[(size_t)(s + 0) * 256];
                float4 v1 = base[(size_t)(s + 1) * 256];
                float4 v2 = base[(size_t)(s + 2) * 256];
                float4 v3 = base[(size_t)(s + 3) * 256];
                a0.x += v0.x; a0.y += v0.y; a0.z += v0.z; a0.w += v0.w;
                a1.x += v1.x; a1.y += v1.y; a1.z += v1.z; a1.w += v1.w;
                a2.x += v2.x; a2.y += v2.y; a2.z += v2.z; a2.w += v2.w;
                a3.x += v3.x; a3.y += v3.y; a3.z += v3.z; a3.w += v3.w;
            }
            for (; s <= hi; s++) {
                float4 v = base[(size_t)s * 256];
                a0.x += v.x; a0.y += v.y; a0.z += v.z; a0.w += v.w;
            }
            a0.x += a1.x + a2.x + a3.x;
            a0.y += a1.y + a2.y + a3.y;
            a0.z += a1.z + a2.z + a3.z;
            a0.w += a1.w + a2.w + a3.w;
            ((float4*)(g_part + (((size_t)(b * NST + st) * NM) + m) * NH + hc * 256))[t] = a0;
        }
        prev = off;
        if (prev >= sEnd) break;
    }
}

// ---------------- kernel: GEMM1 split-K partial  cls(64x[64]) @ W[64,64] ----------
__global__ __launch_bounds__(256) void k_gemm1p(const float* __restrict__ Wnaf,
                                                const float* __restrict__ Wcd) {
    __shared__ float Xs[16 * 68];
    __shared__ float Ws[16 * 64];
    int n0 = blockIdx.x * 64;                 // 0..2047
    int ks0 = blockIdx.y * (NH / KSPLIT);     // K chunk start (64)
    const float* W = (n0 < 1024) ? Wnaf : Wcd;
    int nc0 = (n0 < 1024) ? n0 : n0 - 1024;
    int t = threadIdx.x;
    int tx = t & 15, ty = t >> 4;
    float acc[4][4] = {};
    for (int kt = ks0; kt < ks0 + NH / KSPLIT; kt += 16) {
        {
            int ml = t >> 2, k4 = t & 3;
            float4 x = *(const float4*)(g_cls + (size_t)ml * NH + kt + k4 * 4);
            Xs[(k4 * 4 + 0) * 68 + ml] = x.x;
            Xs[(k4 * 4 + 1) * 68 + ml] = x.y;
            Xs[(k4 * 4 + 2) * 68 + ml] = x.z;
            Xs[(k4 * 4 + 3) * 68 + ml] = x.w;
            int kl = t >> 4, n4 = t & 15;
            float4 w = *(const float4*)(W + (size_t)(kt + kl) * 1024 + nc0 + n4 * 4);
            *(float4*)(Ws + kl * 64 + n4 * 4) = w;
        }
        __syncthreads();
        #pragma unroll
        for (int k = 0; k < 16; k++) {
            float a[4], bb[4];
            *(float4*)a  = *(const float4*)(Xs + k * 68 + ty * 4);
            *(float4*)bb = *(const float4*)(Ws + k * 64 + tx * 4);
            #pragma unroll
            for (int i = 0; i < 4; i++)
                #pragma unroll
                for (int j = 0; j < 4; j++)
                    acc[i][j] += a[i] * bb[j];
        }
        __syncthreads();
    }
    float* dst = g_g1p + (size_t)blockIdx.y * NB * 2048;
    #pragma unroll
    for (int i = 0; i < 4; i++) {
        int m = ty * 4 + i;
        #pragma unroll
        for (int j = 0; j < 4; j++)
            dst[(size_t)m * 2048 + n0 + tx * 4 + j] = acc[i][j];
    }
}

// ---------------- kernel: GEMM1 reduce + bias + tanh ----------------
__global__ void k_gemm1r(const float* __restrict__ bnaf,
                         const float* __restrict__ bcd) {
    int idx = blockIdx.x * 256 + threadIdx.x;   // 0 .. 64*2048-1
    int m = idx >> 11, n = idx & 2047;
    float s = 0.f;
    #pragma unroll
    for (int ks = 0; ks < KSPLIT; ks++)
        s += g_g1p[(size_t)ks * NB * 2048 + idx];
    if (n < 1024) g_naf[(size_t)m * NH + n] = s + bnaf[n];
    else {
        int c = n - 1024;
        g_cdact[(size_t)m * NH + c] = tanhf(s + bcd[c]);
    }
}

// ---------------- kernel: W^T build + bf16 split ----------------
__global__ void k_prep_weights(const float* __restrict__ Wnd,
                               const float* __restrict__ Wed) {
    __shared__ float tile[32][33];
    int n0 = blockIdx.x * 32;
    int k0 = blockIdx.y * 32;
    int tx = threadIdx.x, ty = threadIdx.y;
    #pragma unroll
    for (int kk = 0; kk < 32; kk += 8) {
        int k = k0 + kk + ty;
        int n = n0 + tx;
        float v;
        if (n < 1024) v = Wnd[(size_t)k * 1024 + n];
        else if (n < 2048) { int c = n - 1024; v = Wed[(size_t)k * 1024 + c] + Wed[(size_t)(2048 + k) * 1024 + c]; }
        else { int c = n - 2048; v = Wed[(size_t)(1024 + k) * 1024 + c] - Wed[(size_t)(2048 + k) * 1024 + c]; }
        tile[kk + ty][tx] = v;
    }
    __syncthreads();
    #pragma unroll
    for (int kk = 0; kk < 32; kk += 8) {
        int n = n0 + kk + ty;
        int k = k0 + tx;
        float v = tile[tx][kk + ty];
        __nv_bfloat16 h = __float2bfloat16(v);
        g_WTh[(size_t)n * NH + k] = h;
        g_WTl[(size_t)n * NH + k] = __float2bfloat16(v - __bfloat162float(h));
    }
}

// ---------------- kernel: finalize node rows, write COMPACTED bf16 hi/lo ----------
__global__ void k_finalize(void) {
    int m = blockIdx.x, b = blockIdx.y, t = threadIdx.x;
    int cnt = g_count[b];
    if (m > cnt) return;                        // zero rows are not materialized
    float4 o = make_float4(0.f, 0.f, 0.f, 0.f);
    if (m < cnt) {
        int off  = g_off[b * NOFF + m];
        int prev = (m == 0) ? 0 : g_off[b * NOFF + m - 1];
        int stLo = (prev + 1) >> 6, stHi = off >> 6;
        for (int st = stLo; st <= stHi; st++) {
            float4 p = ((const float4*)(g_part + (((size_t)(b * NST + st) * NM) + m) * NH))[t];
            o.x += p.x; o.y += p.y; o.z += p.z; o.w += p.w;
        }
        float sc = 1.f / (float)(off - prev);
        o.x *= sc; o.y *= sc; o.z *= sc; o.w *= sc;
    } else {
        o = ((const float4*)(g_naf + (size_t)b * NH))[t];
    }
    size_t row = (size_t)(g_rowstart[b] + m);   // compacted row
    __nv_bfloat16 h0 = __float2bfloat16(o.x), h1 = __float2bfloat16(o.y);
    __nv_bfloat16 h2 = __float2bfloat16(o.z), h3 = __float2bfloat16(o.w);
    __nv_bfloat16 l0 = __float2bfloat16(o.x - __bfloat162float(h0));
    __nv_bfloat16 l1 = __float2bfloat16(o.y - __bfloat162float(h1));
    __nv_bfloat16 l2 = __float2bfloat16(o.z - __bfloat162float(h2));
    __nv_bfloat16 l3 = __float2bfloat16(o.w - __bfloat162float(h3));
    __nv_bfloat162 hA = __halves2bfloat162(h0, h1), hB = __halves2bfloat162(h2, h3);
    __nv_bfloat162 lA = __halves2bfloat162(l0, l1), lB = __halves2bfloat162(l2, l3);
    uint2 hv, lv;
    hv.x = *(uint32_t*)&hA; hv.y = *(uint32_t*)&hB;
    lv.x = *(uint32_t*)&lA; lv.y = *(uint32_t*)&lB;
    ((uint2*)(g_nodeH + row * NH))[t] = hv;
    ((uint2*)(g_nodeL + row * NH))[t] = lv;
}

// ---------------- kernel: cls logits ----------------
__global__ void k_logits(const float* __restrict__ Wco,
                         const float* __restrict__ bco,
                         float* __restrict__ out) {
    int b = blockIdx.x, t = threadIdx.x;
    const float2* w = (const float2*)Wco;
    float s0 = 0.f, s1 = 0.f;
    for (int h = t; h < NH; h += 256) {
        float x = g_cdact[(size_t)b * NH + h];
        float2 ww = w[h];
        s0 += x * ww.x; s1 += x * ww.y;
    }
    block_reduce2_store(s0, s1, out + b * 2, out + b * 2 + 1, bco[0], bco[1]);
}

// ============================================================================
// HMMA GEMM on COMPACTED rows: D(ract x 3072) = node @ WT^T, bf16 3-term split.
// ============================================================================
#define TILE_B 8192
#define STAGE_B (4*TILE_B)
#define GEMM_SMEM (3*STAGE_B)

__global__ __launch_bounds__(256, 2) void k_mmagemm(const float* __restrict__ bnd) {
    const int m0 = blockIdx.y * 128, n0 = blockIdx.x * 128;
    if (m0 >= g_ract) return;                   // compaction early-exit
    extern __shared__ char smem[];
    uint32_t sb = smem_to_u32(smem);
    const int t = threadIdx.x;
    const int lane = t & 31, wid = t >> 5;
    const int wm = wid >> 2, wn = wid & 3;

    uint32_t swo[2], gOffA[2], gOffB[2];
    #pragma unroll
    for (int j = 0; j < 2; j++) {
        int u = j * 256 + t;
        int r = u >> 2, c = u & 3;
        uint32_t o = (uint32_t)r * 64 + (uint32_t)c * 16;
        swo[j] = o ^ ((o >> 3) & 0x30);
        gOffA[j] = (uint32_t)(m0 + r) * NH + c * 8;
        gOffB[j] = (uint32_t)(n0 + r) * NH + c * 8;
    }

    auto issue = [&](int kc) {
        uint32_t kk = (uint32_t)kc * 32;
        uint32_t d = sb + (kc % 3) * STAGE_B;
        #pragma unroll
        for (int j = 0; j < 2; j++) {
            cp16(d + 0 * TILE_B + swo[j], g_nodeH + gOffA[j] + kk);
            cp16(d + 1 * TILE_B + swo[j], g_nodeL + gOffA[j] + kk);
            cp16(d + 2 * TILE_B + swo[j], g_WTh   + gOffB[j] + kk);
            cp16(d + 3 * TILE_B + swo[j], g_WTl   + gOffB[j] + kk);
        }
        CP_COMMIT();
    };

    float acc[4][4][4] = {};

    const uint32_t aRow = (uint32_t)(wm * 64 + (lane & 15));
    const uint32_t aKhalf = (uint32_t)((lane >> 4) * 16);
    const uint32_t bRowBase = (uint32_t)(wn * 32 + ((lane >> 4) & 1) * 8 + (lane & 7));
    const uint32_t bCol = (uint32_t)(((lane >> 3) & 1) * 16);

    issue(0);
    issue(1);

    for (int kc = 0; kc < 32; kc++) {
        if (kc == 31) { CP_WAIT0(); } else { CP_WAIT1(); }
        __syncthreads();
        if (kc + 2 < 32) issue(kc + 2);
        uint32_t base = sb + (kc % 3) * STAGE_B;

        #pragma unroll
        for (int ks = 0; ks < 2; ks++) {
            uint32_t bH[2][4], bL[2][4];
            #pragma unroll
            for (int p = 0; p < 2; p++) {
                uint32_t o = (bRowBase + p * 16) * 64 + ks * 32 + bCol;
                o ^= (o >> 3) & 0x30;
                ldsm_x4(bH[p], base + 2 * TILE_B + o);
                ldsm_x4(bL[p], base + 3 * TILE_B + o);
            }
            #pragma unroll
            for (int mt = 0; mt < 4; mt++) {
                uint32_t aH[4], aL[4];
                uint32_t o = (aRow + mt * 16) * 64 + ks * 32 + aKhalf;
                o ^= (o >> 3) & 0x30;
                ldsm_x4(aH, base + o);
                ldsm_x4(aL, base + TILE_B + o);
                #pragma unroll
                for (int nt = 0; nt < 4; nt++) {
                    int p = nt >> 1, q = (nt & 1) * 2;
                    mma16816(acc[mt][nt], aH, bH[p][q], bH[p][q + 1]);
                    mma16816(acc[mt][nt], aH, bL[p][q], bL[p][q + 1]);
                    mma16816(acc[mt][nt], aL, bH[p][q], bH[p][q + 1]);
                }
            }
        }
    }

    int sec  = n0 >> 10;
    int ncol = n0 & 1023;
    float* dst = (sec == 0) ? g_ND : ((sec == 1) ? g_A : g_Bm);
    int g = lane >> 2, tq = lane & 3;
    #pragma unroll
    for (int mt = 0; mt < 4; mt++) {
        int m = m0 + wm * 64 + mt * 16 + g;
        int r0 = g_rowmap[m];
        int r1 = g_rowmap[m + 8];
        #pragma unroll
        for (int nt = 0; nt < 4; nt++) {
            int n = ncol + wn * 32 + nt * 8 + tq * 2;
            float2 v0 = make_float2(acc[mt][nt][0], acc[mt][nt][1]);
            float2 v1 = make_float2(acc[mt][nt][2], acc[mt][nt][3]);
            if (sec == 0) {
                float b0 = bnd[n], b1 = bnd[n + 1];
                v0.x = tanhf(v0.x + b0); v0.y = tanhf(v0.y + b1);
                v1.x = tanhf(v1.x + b0); v1.y = tanhf(v1.y + b1);
            }
            if (r0 >= 0) *(float2*)(dst + (size_t)r0 * NH + n) = v0;
            if (r1 >= 0) *(float2*)(dst + (size_t)r1 * NH + n) = v1;
        }
    }
}

// ---------------- kernel: node logits (constant for zero rows) ----------------
__global__ void k_node_logits(const float* __restrict__ Wno,
                              const float* __restrict__ bno,
                              float* __restrict__ out) {
    int r = blockIdx.x, t = threadIdx.x;
    int b = r / NM, m = r - b * NM;
    float* o = out + 128 + (size_t)r * 2;
    if (m > g_count[b]) {
        if (t < 2) o[t] = g_nlc[t];
        return;
    }
    const float2* w = (const float2*)Wno;
    float s0 = 0.f, s1 = 0.f;
    for (int h = t; h < NH; h += 256) {
        float x = g_ND[(size_t)r * NH + h];
        float2 ww = w[h];
        s0 += x * ww.x; s1 += x * ww.y;
    }
    block_reduce2_store(s0, s1, o, o + 1, bno[0], bno[1]);
}

// ---------------- kernel: constants for all-zero edge row / node row ----------------
__global__ void k_cvec2(const float* __restrict__ bed,
                        const float* __restrict__ Weo,
                        const float* __restrict__ beo,
                        const float* __restrict__ bnd,
                        const float* __restrict__ Wno,
                        const float* __restrict__ bno) {
    int which = blockIdx.x;                 // 0: edge const, 1: node const
    const float*  bias = which ? bnd : bed;
    const float2* w    = which ? (const float2*)Wno : (const float2*)Weo;
    const float*  b2   = which ? bno : beo;
    float* dstp        = which ? g_nlc : g_cvec;
    int t = threadIdx.x;
    float s0 = 0.f, s1 = 0.f;
    for (int h = t; h < NH; h += 256) {
        float v = tanhf(bias[h]);
        float2 ww = w[h];
        s0 += v * ww.x; s1 += v * ww.y;
    }
    block_reduce2_store(s0, s1, &dstp[0], &dstp[1], b2[0], b2[1]);
}

// ---------------- kernel: edge logits (warp per edge) ----------------
__global__ __launch_bounds__(256) void k_edges(const float* __restrict__ bed,
                                               const float* __restrict__ Weo,
                                               const float* __restrict__ beo,
                                               float* __restrict__ out) {
    __shared__ __align__(16) float sbed[NH];
    __shared__ __align__(16) float sw0[NH];
    __shared__ __align__(16) float sw1[NH];
    int b = blockIdx.y, t = threadIdx.x;
    for (int h = t; h < NH; h += 256) {
        sbed[h] = bed[h];
        float2 ww = ((const float2*)Weo)[h];
        sw0[h] = ww.x; sw1[h] = ww.y;
    }
    __syncthreads();

    int warp = t >> 5, lane = t & 31;
    int k = blockIdx.x * 8 + warp;
    if (k >= NE) return;
    int n = g_count[b] + 1;
    float* o = out + 128 + NR * 2 + (size_t)(b * NE + k) * 2;
    if (k >= n * n) {
        if (lane < 2) o[lane] = g_cvec[lane];
        return;
    }
    int i = k / n, j = k % n;
    const float4* Ar = (const float4*)(g_A  + (size_t)(b * NM + j) * NH);
    const float4* Br = (const float4*)(g_Bm + (size_t)(b * NM + i) * NH);
    const float4* sb4 = (const float4*)sbed;
    const float4* w04 = (const float4*)sw0;
    const float4* w14 = (const float4*)sw1;
    float s0 = 0.f, s1 = 0.f;
    #pragma unroll
    for (int it = 0; it < 8; it++) {
        int h4 = it * 32 + lane;
        float4 a  = Ar[h4];
        float4 bb = Br[h4];
        float4 be = sb4[h4];
        float4 w0 = w04[h4];
        float4 w1 = w14[h4];
        float v0 = tanhf(a.x + bb.x + be.x);
        float v1 = tanhf(a.y + bb.y + be.y);
        float v2 = tanhf(a.z + bb.z + be.z);
        float v3 = tanhf(a.w + bb.w + be.w);
        s0 += v0 * w0.x + v1 * w0.y + v2 * w0.z + v3 * w0.w;
        s1 += v0 * w1.x + v1 * w1.y + v2 * w1.z + v3 * w1.w;
    }
    #pragma unroll
    for (int off = 16; off > 0; off >>= 1) {
        s0 += __shfl_down_sync(0xffffffffu, s0, off);
        s1 += __shfl_down_sync(0xffffffffu, s1, off);
    }
    if (lane == 0) { o[0] = s0 + beo[0]; o[1] = s1 + beo[1]; }
}

// ---------------- launch ----------------
extern "C" void kernel_launch(void* const* d_in, const int* in_sizes, int n_in,
                              void* d_out, int out_size) {
    const float* seq  = (const float*)d_in[0];
    const int*   po   = (const int*)  d_in[1];
    const float* Wnaf = (const float*)d_in[4];
    const float* bnaf = (const float*)d_in[5];
    const float* Wcd  = (const float*)d_in[6];
    const float* bcd  = (const float*)d_in[7];
    const float* Wco  = (const float*)d_in[8];
    const float* bco  = (const float*)d_in[9];
    const float* Wnd  = (const float*)d_in[10];
    const float* bnd  = (const float*)d_in[11];
    const float* Wno  = (const float*)d_in[12];
    const float* bno  = (const float*)d_in[13];
    const float* Wed  = (const float*)d_in[14];
    const float* bed  = (const float*)d_in[15];
    const float* Weo  = (const float*)d_in[16];
    const float* beo  = (const float*)d_in[17];
    float* out = (float*)d_out;

    static bool attr_done = false;
    if (!attr_done) {
        cudaFuncSetAttribute(k_mmagemm, cudaFuncAttributeMaxDynamicSharedMemorySize, GEMM_SMEM);
        attr_done = true;
    }

    k_prep_cls<<<NB, 256>>>(seq, po);                       // 1
    k_prefix<<<1, 256>>>();                                 // 2
    k_segsum<<<dim3(NST, NB, 4), 64>>>(seq);                // 3
    k_gemm1p<<<dim3(32, KSPLIT), 256>>>(Wnaf, Wcd);         // 4  <- profiled
    k_gemm1r<<<512, 256>>>(bnaf, bcd);                      // 5
    k_prep_weights<<<dim3(96, 32), dim3(32, 8)>>>(Wnd, Wed);// 6
    k_finalize<<<dim3(NM, NB), 256>>>();                    // 7
    k_mmagemm<<<dim3(24, 13), 256, GEMM_SMEM>>>(bnd);       // 8
    k_cvec2<<<2, 256>>>(bed, Weo, beo, bnd, Wno, bno);      // 9
    k_logits<<<NB, 256>>>(Wco, bco, out);                   // 10
    k_node_logits<<<NR, 256>>>(Wno, bno, out);              // 11
    k_edges<<<dim3(85, NB), 256>>>(bed, Weo, beo, out);     // 12
}

// round 8
// speedup vs baseline: 3.1601x; 1.0237x over previous
#include <cuda_runtime.h>
#include <cuda_bf16.h>
#include <math.h>
#include <stdint.h>

#define NB 64
#define NS 512
#define NH 1024
#define NM 26
#define NE 676
#define NR (NB*NM)          // 1664 node rows total
#define NOFF (NM-1)         // 25 offsets per batch
#define NST 8               // S tiles of 64 rows
#define KSPLIT 16           // gemm1 K splits

// ---------------- scratch (device globals; no allocation allowed) ----------------
__device__ int   g_off[NB*NOFF];
__device__ int   g_count[NB];
__device__ int   g_rowstart[NB];
__device__ int   g_rowmap[NR];
__device__ int   g_ract;
__device__ __align__(16) float g_cls[NB*NH];
__device__ __align__(16) float g_naf[NB*NH];
__device__ __align__(16) float g_cdact[NB*NH];
__device__ __align__(16) float g_g1p[KSPLIT*NB*2048];  // gemm1 split-K partials
__device__ __align__(16) float g_part[NB*NST*NM*NH];   // segment tile partials
__device__ __align__(16) float g_ND[NR*NH];            // tanh(node_full @ W_nd + b_nd)
__device__ __align__(16) float g_A[NR*NH];             // node_full @ (W1+W3)
__device__ __align__(16) float g_Bm[NR*NH];            // node_full @ (W2-W3)
__device__ float g_cvec[2];   // edge logits of all-zero edge row
__device__ float g_nlc[2];    // node logits of all-zero node row
// bf16 split operands for tensor-core GEMM (COMPACTED rows)
__device__ __align__(16) __nv_bfloat16 g_nodeH[NR*NH];
__device__ __align__(16) __nv_bfloat16 g_nodeL[NR*NH];
__device__ __align__(16) __nv_bfloat16 g_WTh[3072*NH];  // W^T (N-major, K cols), hi
__device__ __align__(16) __nv_bfloat16 g_WTl[3072*NH];  // lo

// ============================================================================
// portable PTX helpers (no sm_103a-only features)
// ============================================================================
__device__ __forceinline__ uint32_t smem_to_u32(const void* p) {
    uint32_t a;
    asm("{ .reg .u64 t; cvta.to.shared.u64 t, %1; cvt.u32.u64 %0, t; }" : "=r"(a) : "l"(p));
    return a;
}
__device__ __forceinline__ void ldsm_x4(uint32_t (&r)[4], uint32_t addr) {
    asm volatile("ldmatrix.sync.aligned.m8n8.x4.shared.b16 {%0,%1,%2,%3}, [%4];"
        : "=r"(r[0]), "=r"(r[1]), "=r"(r[2]), "=r"(r[3]) : "r"(addr));
}
__device__ __forceinline__ void mma16816(float (&c)[4], const uint32_t (&a)[4],
                                         uint32_t b0, uint32_t b1) {
    asm volatile("mma.sync.aligned.m16n8k16.row.col.f32.bf16.bf16.f32 "
        "{%0,%1,%2,%3}, {%4,%5,%6,%7}, {%8,%9}, {%0,%1,%2,%3};"
        : "+f"(c[0]), "+f"(c[1]), "+f"(c[2]), "+f"(c[3])
        : "r"(a[0]), "r"(a[1]), "r"(a[2]), "r"(a[3]), "r"(b0), "r"(b1));
}
__device__ __forceinline__ void cp16(uint32_t dst, const void* src) {
    asm volatile("cp.async.cg.shared.global [%0], [%1], 16;" :: "r"(dst), "l"(src));
}
#define CP_COMMIT() asm volatile("cp.async.commit_group;" ::: "memory")
#define CP_WAIT1()  asm volatile("cp.async.wait_group 1;" ::: "memory")
#define CP_WAIT0()  asm volatile("cp.async.wait_group 0;" ::: "memory")

// ---------------- small helpers ----------------
__device__ __forceinline__ void block_reduce2_store(float s0, float s1,
                                                    float* o0, float* o1,
                                                    float add0, float add1) {
    __shared__ float red[16];
    #pragma unroll
    for (int o = 16; o > 0; o >>= 1) {
        s0 += __shfl_down_sync(0xffffffffu, s0, o);
        s1 += __shfl_down_sync(0xffffffffu, s1, o);
    }
    int t = threadIdx.x;
    if ((t & 31) == 0) { red[t >> 5] = s0; red[8 + (t >> 5)] = s1; }
    __syncthreads();
    if (t == 0) {
        float a = 0.f, b = 0.f;
        #pragma unroll
        for (int w = 0; w < 8; w++) { a += red[w]; b += red[8 + w]; }
        *o0 = a + add0;
        *o1 = b + add1;
    }
}

// ---------------- kernel: constants for all-zero edge row / node row (NO deps) ----
__global__ void k_cvec2(const float* __restrict__ bed,
                        const float* __restrict__ Weo,
                        const float* __restrict__ beo,
                        const float* __restrict__ bnd,
                        const float* __restrict__ Wno,
                        const float* __restrict__ bno) {
    int which = blockIdx.x;                 // 0: edge const, 1: node const
    const float*  bias = which ? bnd : bed;
    const float2* w    = which ? (const float2*)Wno : (const float2*)Weo;
    const float*  b2   = which ? bno : beo;
    float* dstp        = which ? g_nlc : g_cvec;
    int t = threadIdx.x;
    float s0 = 0.f, s1 = 0.f;
    for (int h = t; h < NH; h += 256) {
        float v = tanhf(bias[h]);
        float2 ww = w[h];
        s0 += v * ww.x; s1 += v * ww.y;
    }
    block_reduce2_store(s0, s1, &dstp[0], &dstp[1], b2[0], b2[1]);
}

// ---------------- kernel: decode offsets + count + cls copy (fused) ----------------
__global__ void k_prep_cls(const float* __restrict__ seq, const int* __restrict__ po) {
    int b = blockIdx.x, t = threadIdx.x;
    bool wide = (po[1] == 0 && po[3] == 0);
    int val = 0;
    if (t < NOFF) {
        val = wide ? po[(b * NOFF + t) * 2] : po[b * NOFF + t];
        g_off[b * NOFF + t] = val;
    }
    if (t < 32) {
        unsigned mask = __ballot_sync(0xffffffffu, (t < NOFF) && (val > 0));
        if (t == 0) g_count[b] = __popc(mask);
    }
    ((float4*)(g_cls + (size_t)b * NH))[t] =
        ((const float4*)(seq + (size_t)b * NS * NH))[t];
}

// ---------------- kernel: segment partial sums over 64-row S tiles (unroll 8) ------
__global__ void k_segsum(const float* __restrict__ seq) {
    int st = blockIdx.x;          // 0..7
    int b  = blockIdx.y;          // 0..63
    int hc = blockIdx.z;          // 0..3
    int t  = threadIdx.x;         // 0..63
    int s0 = st * 64;
    int sEnd = s0 + 63;
    int cnt = g_count[b];
    const float4* base = (const float4*)(seq + (size_t)b * NS * NH + hc * 256) + t;
    int prev = 0;
    for (int m = 0; m < cnt; m++) {
        int off = g_off[b * NOFF + m];
        int lo = prev + 1;
        if (lo < s0) lo = s0;
        int hi = off < sEnd ? off : sEnd;
        if (lo <= hi) {
            float4 a0 = make_float4(0.f,0.f,0.f,0.f), a1 = a0, a2 = a0, a3 = a0;
            int s = lo;
            for (; s + 7 <= hi; s += 8) {
                float4 v0 = base[(size_t)(s + 0) * 256];
                float4 v1 = base[(size_t)(s + 1) * 256];
                float4 v2 = base[(size_t)(s + 2) * 256];
                float4 v3 = base[(size_t)(s + 3) * 256];
                float4 v4 = base[(size_t)(s + 4) * 256];
                float4 v5 = base[(size_t)(s + 5) * 256];
                float4 v6 = base[(size_t)(s + 6) * 256];
                float4 v7 = base[(size_t)(s + 7) * 256];
                a0.x += v0.x + v4.x; a0.y += v0.y + v4.y; a0.z += v0.z + v4.z; a0.w += v0.w + v4.w;
                a1.x += v1.x + v5.x; a1.y += v1.y + v5.y; a1.z += v1.z + v5.z; a1.w += v1.w + v5.w;
                a2.x += v2.x + v6.x; a2.y += v2.y + v6.y; a2.z += v2.z + v6.z; a2.w += v2.w + v6.w;
                a3.x += v3.x + v7.x; a3.y += v3.y + v7.y; a3.z += v3.z + v7.z; a3.w += v3.w + v7.w;
            }
            for (; s + 3 <= hi; s += 4) {
                float4 v0 = base[(size_t)(s + 0) * 256];
                float4 v1 = base[(size_t)(s + 1) * 256];
                float4 v2 = base[(size_t)(s + 2) * 256];
                float4 v3 = base[(size_t)(s + 3) * 256];
                a0.x += v0.x; a0.y += v0.y; a0.z += v0.z; a0.w += v0.w;
                a1.x += v1.x; a1.y += v1.y; a1.z += v1.z; a1.w += v1.w;
                a2.x += v2.x; a2.y += v2.y; a2.z += v2.z; a2.w += v2.w;
                a3.x += v3.x; a3.y += v3.y; a3.z += v3.z; a3.w += v3.w;
            }
            for (; s <= hi; s++) {
                float4 v = base[(size_t)s * 256];
                a0.x += v.x; a0.y += v.y; a0.z += v.z; a0.w += v.w;
            }
            a0.x += a1.x + a2.x + a3.x;
            a0.y += a1.y + a2.y + a3.y;
            a0.z += a1.z + a2.z + a3.z;
            a0.w += a1.w + a2.w + a3.w;
            ((float4*)(g_part + (((size_t)(b * NST + st) * NM) + m) * NH + hc * 256))[t] = a0;
        }
        prev = off;
        if (prev >= sEnd) break;
    }
}

// ---------------- kernel: GEMM1 split-K partial, whole K=64 slab, ONE barrier ------
__global__ __launch_bounds__(256) void k_gemm1p(const float* __restrict__ Wnaf,
                                                const float* __restrict__ Wcd) {
    __shared__ float Xs[64 * 68];      // [k][m], pad 4
    __shared__ float Ws[64 * 64];      // [k][n]
    int n0 = blockIdx.x * 64;                 // 0..2047
    int ks0 = blockIdx.y * 64;                // K chunk start
    const float* W = (n0 < 1024) ? Wnaf : Wcd;
    int nc0 = (n0 < 1024) ? n0 : n0 - 1024;
    int t = threadIdx.x;
    #pragma unroll
    for (int r = 0; r < 4; r++) {
        int f4 = t + r * 256;
        int row = f4 >> 4, q = f4 & 15;
        // X: cls[row][ks0 + q*4 ..], store transposed
        float4 x = *(const float4*)(g_cls + (size_t)row * NH + ks0 + q * 4);
        Xs[(q * 4 + 0) * 68 + row] = x.x;
        Xs[(q * 4 + 1) * 68 + row] = x.y;
        Xs[(q * 4 + 2) * 68 + row] = x.z;
        Xs[(q * 4 + 3) * 68 + row] = x.w;
        // W: W[ks0+row][nc0 + q*4 ..]
        float4 w = *(const float4*)(W + (size_t)(ks0 + row) * 1024 + nc0 + q * 4);
        *(float4*)(Ws + row * 64 + q * 4) = w;
    }
    __syncthreads();
    int tx = t & 15, ty = t >> 4;
    float acc[4][4] = {};
    #pragma unroll 16
    for (int k = 0; k < 64; k++) {
        float a[4], bb[4];
        *(float4*)a  = *(const float4*)(Xs + k * 68 + ty * 4);
        *(float4*)bb = *(const float4*)(Ws + k * 64 + tx * 4);
        #pragma unroll
        for (int i = 0; i < 4; i++)
            #pragma unroll
            for (int j = 0; j < 4; j++)
                acc[i][j] += a[i] * bb[j];
    }
    float* dst = g_g1p + (size_t)blockIdx.y * NB * 2048;
    #pragma unroll
    for (int i = 0; i < 4; i++) {
        int m = ty * 4 + i;
        #pragma unroll
        for (int j = 0; j < 4; j++)
            dst[(size_t)m * 2048 + n0 + tx * 4 + j] = acc[i][j];
    }
}

// ---------------- kernel: GEMM1 reduce + bias + tanh; block 512 does prefix --------
__global__ void k_gemm1r(const float* __restrict__ bnaf,
                         const float* __restrict__ bcd) {
    if (blockIdx.x == 512) {
        // row compaction prefix + rowmap (formerly k_prefix)
        __shared__ int sstart[NB];
        int t = threadIdx.x;
        if (t == 0) {
            int acc = 0;
            for (int b = 0; b < NB; b++) {
                sstart[b] = acc;
                g_rowstart[b] = acc;
                acc += g_count[b] + 1;
            }
            g_ract = acc;
        }
        __syncthreads();
        for (int i = t; i < NR; i += 256) g_rowmap[i] = -1;
        __syncthreads();
        for (int i = t; i < NB * NM; i += 256) {
            int b = i / NM, m = i - b * NM;
            if (m <= g_count[b]) g_rowmap[sstart[b] + m] = i;
        }
        return;
    }
    int idx = blockIdx.x * 256 + threadIdx.x;   // 0 .. 64*2048-1
    int m = idx >> 11, n = idx & 2047;
    float s = 0.f;
    #pragma unroll
    for (int ks = 0; ks < KSPLIT; ks++)
        s += g_g1p[(size_t)ks * NB * 2048 + idx];
    if (n < 1024) g_naf[(size_t)m * NH + n] = s + bnaf[n];
    else {
        int c = n - 1024;
        g_cdact[(size_t)m * NH + c] = tanhf(s + bcd[c]);
    }
}

// ---------------- kernel: W^T build + bf16 split ----------------
__global__ void k_prep_weights(const float* __restrict__ Wnd,
                               const float* __restrict__ Wed) {
    __shared__ float tile[32][33];
    int n0 = blockIdx.x * 32;
    int k0 = blockIdx.y * 32;
    int tx = threadIdx.x, ty = threadIdx.y;
    #pragma unroll
    for (int kk = 0; kk < 32; kk += 8) {
        int k = k0 + kk + ty;
        int n = n0 + tx;
        float v;
        if (n < 1024) v = Wnd[(size_t)k * 1024 + n];
        else if (n < 2048) { int c = n - 1024; v = Wed[(size_t)k * 1024 + c] + Wed[(size_t)(2048 + k) * 1024 + c]; }
        else { int c = n - 2048; v = Wed[(size_t)(1024 + k) * 1024 + c] - Wed[(size_t)(2048 + k) * 1024 + c]; }
        tile[kk + ty][tx] = v;
    }
    __syncthreads();
    #pragma unroll
    for (int kk = 0; kk < 32; kk += 8) {
        int n = n0 + kk + ty;
        int k = k0 + tx;
        float v = tile[tx][kk + ty];
        __nv_bfloat16 h = __float2bfloat16(v);
        g_WTh[(size_t)n * NH + k] = h;
        g_WTl[(size_t)n * NH + k] = __float2bfloat16(v - __bfloat162float(h));
    }
}

// ---------------- kernel: finalize node rows, write COMPACTED bf16 hi/lo ----------
__global__ void k_finalize(void) {
    int m = blockIdx.x, b = blockIdx.y, t = threadIdx.x;
    int cnt = g_count[b];
    if (m > cnt) return;                        // zero rows are not materialized
    float4 o = make_float4(0.f, 0.f, 0.f, 0.f);
    if (m < cnt) {
        int off  = g_off[b * NOFF + m];
        int prev = (m == 0) ? 0 : g_off[b * NOFF + m - 1];
        int stLo = (prev + 1) >> 6, stHi = off >> 6;
        for (int st = stLo; st <= stHi; st++) {
            float4 p = ((const float4*)(g_part + (((size_t)(b * NST + st) * NM) + m) * NH))[t];
            o.x += p.x; o.y += p.y; o.z += p.z; o.w += p.w;
        }
        float sc = 1.f / (float)(off - prev);
        o.x *= sc; o.y *= sc; o.z *= sc; o.w *= sc;
    } else {
        o = ((const float4*)(g_naf + (size_t)b * NH))[t];
    }
    size_t row = (size_t)(g_rowstart[b] + m);   // compacted row
    __nv_bfloat16 h0 = __float2bfloat16(o.x), h1 = __float2bfloat16(o.y);
    __nv_bfloat16 h2 = __float2bfloat16(o.z), h3 = __float2bfloat16(o.w);
    __nv_bfloat16 l0 = __float2bfloat16(o.x - __bfloat162float(h0));
    __nv_bfloat16 l1 = __float2bfloat16(o.y - __bfloat162float(h1));
    __nv_bfloat16 l2 = __float2bfloat16(o.z - __bfloat162float(h2));
    __nv_bfloat16 l3 = __float2bfloat16(o.w - __bfloat162float(h3));
    __nv_bfloat162 hA = __halves2bfloat162(h0, h1), hB = __halves2bfloat162(h2, h3);
    __nv_bfloat162 lA = __halves2bfloat162(l0, l1), lB = __halves2bfloat162(l2, l3);
    uint2 hv, lv;
    hv.x = *(uint32_t*)&hA; hv.y = *(uint32_t*)&hB;
    lv.x = *(uint32_t*)&lA; lv.y = *(uint32_t*)&lB;
    ((uint2*)(g_nodeH + row * NH))[t] = hv;
    ((uint2*)(g_nodeL + row * NH))[t] = lv;
}

// ============================================================================
// HMMA GEMM on COMPACTED rows: D(ract x 3072) = node @ WT^T, bf16 3-term split.
// ============================================================================
#define TILE_B 8192
#define STAGE_B (4*TILE_B)
#define GEMM_SMEM (3*STAGE_B)

__global__ __launch_bounds__(256, 2) void k_mmagemm(const float* __restrict__ bnd) {
    const int m0 = blockIdx.y * 128, n0 = blockIdx.x * 128;
    if (m0 >= g_ract) return;                   // compaction early-exit
    extern __shared__ char smem[];
    uint32_t sb = smem_to_u32(smem);
    const int t = threadIdx.x;
    const int lane = t & 31, wid = t >> 5;
    const int wm = wid >> 2, wn = wid & 3;

    uint32_t swo[2], gOffA[2], gOffB[2];
    #pragma unroll
    for (int j = 0; j < 2; j++) {
        int u = j * 256 + t;
        int r = u >> 2, c = u & 3;
        uint32_t o = (uint32_t)r * 64 + (uint32_t)c * 16;
        swo[j] = o ^ ((o >> 3) & 0x30);
        gOffA[j] = (uint32_t)(m0 + r) * NH + c * 8;
        gOffB[j] = (uint32_t)(n0 + r) * NH + c * 8;
    }

    auto issue = [&](int kc) {
        uint32_t kk = (uint32_t)kc * 32;
        uint32_t d = sb + (kc % 3) * STAGE_B;
        #pragma unroll
        for (int j = 0; j < 2; j++) {
            cp16(d + 0 * TILE_B + swo[j], g_nodeH + gOffA[j] + kk);
            cp16(d + 1 * TILE_B + swo[j], g_nodeL + gOffA[j] + kk);
            cp16(d + 2 * TILE_B + swo[j], g_WTh   + gOffB[j] + kk);
            cp16(d + 3 * TILE_B + swo[j], g_WTl   + gOffB[j] + kk);
        }
        CP_COMMIT();
    };

    float acc[4][4][4] = {};

    const uint32_t aRow = (uint32_t)(wm * 64 + (lane & 15));
    const uint32_t aKhalf = (uint32_t)((lane >> 4) * 16);
    const uint32_t bRowBase = (uint32_t)(wn * 32 + ((lane >> 4) & 1) * 8 + (lane & 7));
    const uint32_t bCol = (uint32_t)(((lane >> 3) & 1) * 16);

    issue(0);
    issue(1);

    for (int kc = 0; kc < 32; kc++) {
        if (kc == 31) { CP_WAIT0(); } else { CP_WAIT1(); }
        __syncthreads();
        if (kc + 2 < 32) issue(kc + 2);
        uint32_t base = sb + (kc % 3) * STAGE_B;

        #pragma unroll
        for (int ks = 0; ks < 2; ks++) {
            uint32_t bH[2][4], bL[2][4];
            #pragma unroll
            for (int p = 0; p < 2; p++) {
                uint32_t o = (bRowBase + p * 16) * 64 + ks * 32 + bCol;
                o ^= (o >> 3) & 0x30;
                ldsm_x4(bH[p], base + 2 * TILE_B + o);
                ldsm_x4(bL[p], base + 3 * TILE_B + o);
            }
            #pragma unroll
            for (int mt = 0; mt < 4; mt++) {
                uint32_t aH[4], aL[4];
                uint32_t o = (aRow + mt * 16) * 64 + ks * 32 + aKhalf;
                o ^= (o >> 3) & 0x30;
                ldsm_x4(aH, base + o);
                ldsm_x4(aL, base + TILE_B + o);
                #pragma unroll
                for (int nt = 0; nt < 4; nt++) {
                    int p = nt >> 1, q = (nt & 1) * 2;
                    mma16816(acc[mt][nt], aH, bH[p][q], bH[p][q + 1]);
                    mma16816(acc[mt][nt], aH, bL[p][q], bL[p][q + 1]);
                    mma16816(acc[mt][nt], aL, bH[p][q], bH[p][q + 1]);
                }
            }
        }
    }

    int sec  = n0 >> 10;
    int ncol = n0 & 1023;
    float* dst = (sec == 0) ? g_ND : ((sec == 1) ? g_A : g_Bm);
    int g = lane >> 2, tq = lane & 3;
    #pragma unroll
    for (int mt = 0; mt < 4; mt++) {
        int m = m0 + wm * 64 + mt * 16 + g;
        int r0 = g_rowmap[m];
        int r1 = g_rowmap[m + 8];
        #pragma unroll
        for (int nt = 0; nt < 4; nt++) {
            int n = ncol + wn * 32 + nt * 8 + tq * 2;
            float2 v0 = make_float2(acc[mt][nt][0], acc[mt][nt][1]);
            float2 v1 = make_float2(acc[mt][nt][2], acc[mt][nt][3]);
            if (sec == 0) {
                float b0 = bnd[n], b1 = bnd[n + 1];
                v0.x = tanhf(v0.x + b0); v0.y = tanhf(v0.y + b1);
                v1.x = tanhf(v1.x + b0); v1.y = tanhf(v1.y + b1);
            }
            if (r0 >= 0) *(float2*)(dst + (size_t)r0 * NH + n) = v0;
            if (r1 >= 0) *(float2*)(dst + (size_t)r1 * NH + n) = v1;
        }
    }
}

// ---------------- kernel: node logits + cls logits (warp per row, merged) ----------
__global__ __launch_bounds__(256) void k_alllogits(const float* __restrict__ Wno,
                                                   const float* __restrict__ bno,
                                                   const float* __restrict__ Wco,
                                                   const float* __restrict__ bco,
                                                   float* __restrict__ out) {
    int blk = blockIdx.x, t = threadIdx.x;
    int warp = t >> 5, lane = t & 31;
    const float4* X;
    const float4* W4;
    float add0, add1;
    float* o;
    if (blk < 208) {
        int r = blk * 8 + warp;                 // 0..1663
        int b = r / NM, m = r - b * NM;
        o = out + 128 + (size_t)r * 2;
        if (m > g_count[b]) {
            if (lane < 2) o[lane] = g_nlc[lane];
            return;
        }
        X = (const float4*)(g_ND + (size_t)r * NH);
        W4 = (const float4*)Wno;
        add0 = bno[0]; add1 = bno[1];
    } else {
        int b = (blk - 208) * 8 + warp;         // 0..63
        o = out + (size_t)b * 2;
        X = (const float4*)(g_cdact + (size_t)b * NH);
        W4 = (const float4*)Wco;
        add0 = bco[0]; add1 = bco[1];
    }
    float s0 = 0.f, s1 = 0.f;
    #pragma unroll
    for (int it = 0; it < 8; it++) {
        int h4 = it * 32 + lane;
        float4 x  = X[h4];
        float4 wa = W4[h4 * 2];
        float4 wb = W4[h4 * 2 + 1];
        s0 += x.x * wa.x + x.y * wa.z + x.z * wb.x + x.w * wb.z;
        s1 += x.x * wa.y + x.y * wa.w + x.z * wb.y + x.w * wb.w;
    }
    #pragma unroll
    for (int off = 16; off > 0; off >>= 1) {
        s0 += __shfl_down_sync(0xffffffffu, s0, off);
        s1 += __shfl_down_sync(0xffffffffu, s1, off);
    }
    if (lane == 0) { o[0] = s0 + add0; o[1] = s1 + add1; }
}

// ---------------- kernel: edge logits (warp per edge) ----------------
__global__ __launch_bounds__(256) void k_edges(const float* __restrict__ bed,
                                               const float* __restrict__ Weo,
                                               const float* __restrict__ beo,
                                               float* __restrict__ out) {
    __shared__ __align__(16) float sbed[NH];
    __shared__ __align__(16) float sw0[NH];
    __shared__ __align__(16) float sw1[NH];
    int b = blockIdx.y, t = threadIdx.x;
    for (int h = t; h < NH; h += 256) {
        sbed[h] = bed[h];
        float2 ww = ((const float2*)Weo)[h];
        sw0[h] = ww.x; sw1[h] = ww.y;
    }
    __syncthreads();

    int warp = t >> 5, lane = t & 31;
    int k = blockIdx.x * 8 + warp;
    if (k >= NE) return;
    int n = g_count[b] + 1;
    float* o = out + 128 + NR * 2 + (size_t)(b * NE + k) * 2;
    if (k >= n * n) {
        if (lane < 2) o[lane] = g_cvec[lane];
        return;
    }
    int i = k / n, j = k % n;
    const float4* Ar = (const float4*)(g_A  + (size_t)(b * NM + j) * NH);
    const float4* Br = (const float4*)(g_Bm + (size_t)(b * NM + i) * NH);
    const float4* sb4 = (const float4*)sbed;
    const float4* w04 = (const float4*)sw0;
    const float4* w14 = (const float4*)sw1;
    float s0 = 0.f, s1 = 0.f;
    #pragma unroll
    for (int it = 0; it < 8; it++) {
        int h4 = it * 32 + lane;
        float4 a  = Ar[h4];
        float4 bb = Br[h4];
        float4 be = sb4[h4];
        float4 w0 = w04[h4];
        float4 w1 = w14[h4];
        float v0 = tanhf(a.x + bb.x + be.x);
        float v1 = tanhf(a.y + bb.y + be.y);
        float v2 = tanhf(a.z + bb.z + be.z);
        float v3 = tanhf(a.w + bb.w + be.w);
        s0 += v0 * w0.x + v1 * w0.y + v2 * w0.z + v3 * w0.w;
        s1 += v0 * w1.x + v1 * w1.y + v2 * w1.z + v3 * w1.w;
    }
    #pragma unroll
    for (int off = 16; off > 0; off >>= 1) {
        s0 += __shfl_down_sync(0xffffffffu, s0, off);
        s1 += __shfl_down_sync(0xffffffffu, s1, off);
    }
    if (lane == 0) { o[0] = s0 + beo[0]; o[1] = s1 + beo[1]; }
}

// ---------------- launch ----------------
extern "C" void kernel_launch(void* const* d_in, const int* in_sizes, int n_in,
                              void* d_out, int out_size) {
    const float* seq  = (const float*)d_in[0];
    const int*   po   = (const int*)  d_in[1];
    const float* Wnaf = (const float*)d_in[4];
    const float* bnaf = (const float*)d_in[5];
    const float* Wcd  = (const float*)d_in[6];
    const float* bcd  = (const float*)d_in[7];
    const float* Wco  = (const float*)d_in[8];
    const float* bco  = (const float*)d_in[9];
    const float* Wnd  = (const float*)d_in[10];
    const float* bnd  = (const float*)d_in[11];
    const float* Wno  = (const float*)d_in[12];
    const float* bno  = (const float*)d_in[13];
    const float* Wed  = (const float*)d_in[14];
    const float* bed  = (const float*)d_in[15];
    const float* Weo  = (const float*)d_in[16];
    const float* beo  = (const float*)d_in[17];
    float* out = (float*)d_out;

    static bool attr_done = false;
    if (!attr_done) {
        cudaFuncSetAttribute(k_mmagemm, cudaFuncAttributeMaxDynamicSharedMemorySize, GEMM_SMEM);
        attr_done = true;
    }

    k_cvec2<<<2, 256>>>(bed, Weo, beo, bnd, Wno, bno);      // 1 (no deps)
    k_prep_cls<<<NB, 256>>>(seq, po);                       // 2
    k_segsum<<<dim3(NST, NB, 4), 64>>>(seq);                // 3
    k_gemm1p<<<dim3(32, KSPLIT), 256>>>(Wnaf, Wcd);         // 4  <- profiled
    k_gemm1r<<<513, 256>>>(bnaf, bcd);                      // 5 (block 512 = prefix)
    k_prep_weights<<<dim3(96, 32), dim3(32, 8)>>>(Wnd, Wed);// 6
    k_finalize<<<dim3(NM, NB), 256>>>();                    // 7
    k_mmagemm<<<dim3(24, 13), 256, GEMM_SMEM>>>(bnd);       // 8
    k_edges<<<dim3(85, NB), 256>>>(bed, Weo, beo, out);     // 9
    k_alllogits<<<216, 256>>>(Wno, bno, Wco, bco, out);     // 10
}

// round 9
// speedup vs baseline: 3.5864x; 1.1349x over previous
#include <cuda_runtime.h>
#include <cuda_bf16.h>
#include <math.h>
#include <stdint.h>

#define NB 64
#define NS 512
#define NH 1024
#define NM 26
#define NE 676
#define NR (NB*NM)          // 1664 node rows total
#define NOFF (NM-1)         // 25 offsets per batch
#define NST 8               // S tiles of 64 rows
#define KSPLIT 16           // gemm1 K splits

// ---------------- scratch (device globals; no allocation allowed) ----------------
__device__ int   g_off[NB*NOFF];
__device__ int   g_count[NB];
__device__ int   g_rowstart[NB];
__device__ int   g_rowmap[NR];
__device__ int   g_ract;
__device__ __align__(16) float g_cls[NB*NH];
__device__ __align__(16) float g_naf[NB*NH];
__device__ __align__(16) float g_cdact[NB*NH];
__device__ __align__(16) float g_g1p[KSPLIT*NB*2048];  // gemm1 split-K partials
__device__ __align__(16) float g_part[NB*NST*NM*NH];   // segment tile partials
__device__ __align__(16) float g_ND[NR*NH];            // tanh(node_full @ W_nd + b_nd)
__device__ __align__(16) float g_A[NR*NH];             // node_full @ (W1+W3)
__device__ __align__(16) float g_Bm[NR*NH];            // node_full @ (W2-W3)
__device__ float g_cvec[2];   // edge logits of all-zero edge row
__device__ float g_nlc[2];    // node logits of all-zero node row
// bf16 split operands for tensor-core GEMM (COMPACTED rows)
__device__ __align__(16) __nv_bfloat16 g_nodeH[NR*NH];
__device__ __align__(16) __nv_bfloat16 g_nodeL[NR*NH];
__device__ __align__(16) __nv_bfloat16 g_WTh[3072*NH];  // W^T (N-major, K cols), hi
__device__ __align__(16) __nv_bfloat16 g_WTl[3072*NH];  // lo

// ============================================================================
// portable PTX helpers (no sm_103a-only features)
// ============================================================================
__device__ __forceinline__ uint32_t smem_to_u32(const void* p) {
    uint32_t a;
    asm("{ .reg .u64 t; cvta.to.shared.u64 t, %1; cvt.u32.u64 %0, t; }" : "=r"(a) : "l"(p));
    return a;
}
__device__ __forceinline__ void ldsm_x4(uint32_t (&r)[4], uint32_t addr) {
    asm volatile("ldmatrix.sync.aligned.m8n8.x4.shared.b16 {%0,%1,%2,%3}, [%4];"
        : "=r"(r[0]), "=r"(r[1]), "=r"(r[2]), "=r"(r[3]) : "r"(addr));
}
__device__ __forceinline__ void mma16816(float (&c)[4], const uint32_t (&a)[4],
                                         uint32_t b0, uint32_t b1) {
    asm volatile("mma.sync.aligned.m16n8k16.row.col.f32.bf16.bf16.f32 "
        "{%0,%1,%2,%3}, {%4,%5,%6,%7}, {%8,%9}, {%0,%1,%2,%3};"
        : "+f"(c[0]), "+f"(c[1]), "+f"(c[2]), "+f"(c[3])
        : "r"(a[0]), "r"(a[1]), "r"(a[2]), "r"(a[3]), "r"(b0), "r"(b1));
}
__device__ __forceinline__ void cp16(uint32_t dst, const void* src) {
    asm volatile("cp.async.cg.shared.global [%0], [%1], 16;" :: "r"(dst), "l"(src));
}
#define CP_COMMIT() asm volatile("cp.async.commit_group;" ::: "memory")
#define CP_WAIT1()  asm volatile("cp.async.wait_group 1;" ::: "memory")
#define CP_WAIT0()  asm volatile("cp.async.wait_group 0;" ::: "memory")

__device__ __forceinline__ float fast_tanh(float x) {
    float y;
    asm("tanh.approx.f32 %0, %1;" : "=f"(y) : "f"(x));
    return y;
}

// ---------------- small helpers ----------------
__device__ __forceinline__ void block_reduce2_store(float s0, float s1,
                                                    float* o0, float* o1,
                                                    float add0, float add1) {
    __shared__ float red[16];
    #pragma unroll
    for (int o = 16; o > 0; o >>= 1) {
        s0 += __shfl_down_sync(0xffffffffu, s0, o);
        s1 += __shfl_down_sync(0xffffffffu, s1, o);
    }
    int t = threadIdx.x;
    if ((t & 31) == 0) { red[t >> 5] = s0; red[8 + (t >> 5)] = s1; }
    __syncthreads();
    if (t == 0) {
        float a = 0.f, b = 0.f;
        #pragma unroll
        for (int w = 0; w < 8; w++) { a += red[w]; b += red[8 + w]; }
        *o0 = a + add0;
        *o1 = b + add1;
    }
}

// ---------------- kernel: prep_cls (blocks 0-63) + cvec consts (blocks 64-65) ------
__global__ void k_prep0(const float* __restrict__ seq, const int* __restrict__ po,
                        const float* __restrict__ bed, const float* __restrict__ Weo,
                        const float* __restrict__ beo, const float* __restrict__ bnd,
                        const float* __restrict__ Wno, const float* __restrict__ bno) {
    int blk = blockIdx.x, t = threadIdx.x;
    if (blk < NB) {
        int b = blk;
        bool wide = (po[1] == 0 && po[3] == 0);
        int val = 0;
        if (t < NOFF) {
            val = wide ? po[(b * NOFF + t) * 2] : po[b * NOFF + t];
            g_off[b * NOFF + t] = val;
        }
        if (t < 32) {
            unsigned mask = __ballot_sync(0xffffffffu, (t < NOFF) && (val > 0));
            if (t == 0) g_count[b] = __popc(mask);
        }
        ((float4*)(g_cls + (size_t)b * NH))[t] =
            ((const float4*)(seq + (size_t)b * NS * NH))[t];
    } else {
        int which = blk - NB;               // 0: edge const, 1: node const
        const float*  bias = which ? bnd : bed;
        const float2* w    = which ? (const float2*)Wno : (const float2*)Weo;
        const float*  b2   = which ? bno : beo;
        float* dstp        = which ? g_nlc : g_cvec;
        float s0 = 0.f, s1 = 0.f;
        for (int h = t; h < NH; h += 256) {
            float v = tanhf(bias[h]);
            float2 ww = w[h];
            s0 += v * ww.x; s1 += v * ww.y;
        }
        block_reduce2_store(s0, s1, &dstp[0], &dstp[1], b2[0], b2[1]);
    }
}

// ---------------- kernel: segment partial sums over 64-row S tiles (unroll 8) ------
__global__ void k_segsum(const float* __restrict__ seq) {
    int st = blockIdx.x;          // 0..7
    int b  = blockIdx.y;          // 0..63
    int hc = blockIdx.z;          // 0..3
    int t  = threadIdx.x;         // 0..63
    int s0 = st * 64;
    int sEnd = s0 + 63;
    int cnt = g_count[b];
    const float4* base = (const float4*)(seq + (size_t)b * NS * NH + hc * 256) + t;
    int prev = 0;
    for (int m = 0; m < cnt; m++) {
        int off = g_off[b * NOFF + m];
        int lo = prev + 1;
        if (lo < s0) lo = s0;
        int hi = off < sEnd ? off : sEnd;
        if (lo <= hi) {
            float4 a0 = make_float4(0.f,0.f,0.f,0.f), a1 = a0, a2 = a0, a3 = a0;
            int s = lo;
            for (; s + 7 <= hi; s += 8) {
                float4 v0 = base[(size_t)(s + 0) * 256];
                float4 v1 = base[(size_t)(s + 1) * 256];
                float4 v2 = base[(size_t)(s + 2) * 256];
                float4 v3 = base[(size_t)(s + 3) * 256];
                float4 v4 = base[(size_t)(s + 4) * 256];
                float4 v5 = base[(size_t)(s + 5) * 256];
                float4 v6 = base[(size_t)(s + 6) * 256];
                float4 v7 = base[(size_t)(s + 7) * 256];
                a0.x += v0.x + v4.x; a0.y += v0.y + v4.y; a0.z += v0.z + v4.z; a0.w += v0.w + v4.w;
                a1.x += v1.x + v5.x; a1.y += v1.y + v5.y; a1.z += v1.z + v5.z; a1.w += v1.w + v5.w;
                a2.x += v2.x + v6.x; a2.y += v2.y + v6.y; a2.z += v2.z + v6.z; a2.w += v2.w + v6.w;
                a3.x += v3.x + v7.x; a3.y += v3.y + v7.y; a3.z += v3.z + v7.z; a3.w += v3.w + v7.w;
            }
            for (; s + 3 <= hi; s += 4) {
                float4 v0 = base[(size_t)(s + 0) * 256];
                float4 v1 = base[(size_t)(s + 1) * 256];
                float4 v2 = base[(size_t)(s + 2) * 256];
                float4 v3 = base[(size_t)(s + 3) * 256];
                a0.x += v0.x; a0.y += v0.y; a0.z += v0.z; a0.w += v0.w;
                a1.x += v1.x; a1.y += v1.y; a1.z += v1.z; a1.w += v1.w;
                a2.x += v2.x; a2.y += v2.y; a2.z += v2.z; a2.w += v2.w;
                a3.x += v3.x; a3.y += v3.y; a3.z += v3.z; a3.w += v3.w;
            }
            for (; s <= hi; s++) {
                float4 v = base[(size_t)s * 256];
                a0.x += v.x; a0.y += v.y; a0.z += v.z; a0.w += v.w;
            }
            a0.x += a1.x + a2.x + a3.x;
            a0.y += a1.y + a2.y + a3.y;
            a0.z += a1.z + a2.z + a3.z;
            a0.w += a1.w + a2.w + a3.w;
            ((float4*)(g_part + (((size_t)(b * NST + st) * NM) + m) * NH + hc * 256))[t] = a0;
        }
        prev = off;
        if (prev >= sEnd) break;
    }
}

// ---------------- kernel: GEMM1 split-K partial ----------
__global__ __launch_bounds__(256) void k_gemm1p(const float* __restrict__ Wnaf,
                                                const float* __restrict__ Wcd) {
    __shared__ float Xs[64 * 68];      // [k][m], pad 4
    __shared__ float Ws[64 * 64];      // [k][n]
    int n0 = blockIdx.x * 64;                 // 0..2047
    int ks0 = blockIdx.y * 64;                // K chunk start
    const float* W = (n0 < 1024) ? Wnaf : Wcd;
    int nc0 = (n0 < 1024) ? n0 : n0 - 1024;
    int t = threadIdx.x;
    #pragma unroll
    for (int r = 0; r < 4; r++) {
        int f4 = t + r * 256;
        int row = f4 >> 4, q = f4 & 15;
        float4 x = *(const float4*)(g_cls + (size_t)row * NH + ks0 + q * 4);
        Xs[(q * 4 + 0) * 68 + row] = x.x;
        Xs[(q * 4 + 1) * 68 + row] = x.y;
        Xs[(q * 4 + 2) * 68 + row] = x.z;
        Xs[(q * 4 + 3) * 68 + row] = x.w;
        float4 w = *(const float4*)(W + (size_t)(ks0 + row) * 1024 + nc0 + q * 4);
        *(float4*)(Ws + row * 64 + q * 4) = w;
    }
    __syncthreads();
    int tx = t & 15, ty = t >> 4;
    float acc[4][4] = {};
    #pragma unroll 16
    for (int k = 0; k < 64; k++) {
        float a[4], bb[4];
        *(float4*)a  = *(const float4*)(Xs + k * 68 + ty * 4);
        *(float4*)bb = *(const float4*)(Ws + k * 64 + tx * 4);
        #pragma unroll
        for (int i = 0; i < 4; i++)
            #pragma unroll
            for (int j = 0; j < 4; j++)
                acc[i][j] += a[i] * bb[j];
    }
    float* dst = g_g1p + (size_t)blockIdx.y * NB * 2048;
    #pragma unroll
    for (int i = 0; i < 4; i++) {
        int m = ty * 4 + i;
        #pragma unroll
        for (int j = 0; j < 4; j++)
            dst[(size_t)m * 2048 + n0 + tx * 4 + j] = acc[i][j];
    }
}

// ---------------- kernel: GEMM1 reduce + bias + tanh; block 512 does prefix --------
__global__ void k_gemm1r(const float* __restrict__ bnaf,
                         const float* __restrict__ bcd) {
    if (blockIdx.x == 512) {
        __shared__ int sstart[NB];
        int t = threadIdx.x;
        if (t == 0) {
            int acc = 0;
            for (int b = 0; b < NB; b++) {
                sstart[b] = acc;
                g_rowstart[b] = acc;
                acc += g_count[b] + 1;
            }
            g_ract = acc;
        }
        __syncthreads();
        for (int i = t; i < NR; i += 256) g_rowmap[i] = -1;
        __syncthreads();
        for (int i = t; i < NB * NM; i += 256) {
            int b = i / NM, m = i - b * NM;
            if (m <= g_count[b]) g_rowmap[sstart[b] + m] = i;
        }
        return;
    }
    int idx = blockIdx.x * 256 + threadIdx.x;
    int m = idx >> 11, n = idx & 2047;
    float s = 0.f;
    #pragma unroll
    for (int ks = 0; ks < KSPLIT; ks++)
        s += g_g1p[(size_t)ks * NB * 2048 + idx];
    if (n < 1024) g_naf[(size_t)m * NH + n] = s + bnaf[n];
    else {
        int c = n - 1024;
        g_cdact[(size_t)m * NH + c] = tanhf(s + bcd[c]);
    }
}

// ---------------- kernel: W^T build + bf16 split ----------------
__global__ void k_prep_weights(const float* __restrict__ Wnd,
                               const float* __restrict__ Wed) {
    __shared__ float tile[32][33];
    int n0 = blockIdx.x * 32;
    int k0 = blockIdx.y * 32;
    int tx = threadIdx.x, ty = threadIdx.y;
    #pragma unroll
    for (int kk = 0; kk < 32; kk += 8) {
        int k = k0 + kk + ty;
        int n = n0 + tx;
        float v;
        if (n < 1024) v = Wnd[(size_t)k * 1024 + n];
        else if (n < 2048) { int c = n - 1024; v = Wed[(size_t)k * 1024 + c] + Wed[(size_t)(2048 + k) * 1024 + c]; }
        else { int c = n - 2048; v = Wed[(size_t)(1024 + k) * 1024 + c] - Wed[(size_t)(2048 + k) * 1024 + c]; }
        tile[kk + ty][tx] = v;
    }
    __syncthreads();
    #pragma unroll
    for (int kk = 0; kk < 32; kk += 8) {
        int n = n0 + kk + ty;
        int k = k0 + tx;
        float v = tile[tx][kk + ty];
        __nv_bfloat16 h = __float2bfloat16(v);
        g_WTh[(size_t)n * NH + k] = h;
        g_WTl[(size_t)n * NH + k] = __float2bfloat16(v - __bfloat162float(h));
    }
}

// ---------------- kernel: finalize node rows, write COMPACTED bf16 hi/lo ----------
__global__ void k_finalize(void) {
    int m = blockIdx.x, b = blockIdx.y, t = threadIdx.x;
    int cnt = g_count[b];
    if (m > cnt) return;
    float4 o = make_float4(0.f, 0.f, 0.f, 0.f);
    if (m < cnt) {
        int off  = g_off[b * NOFF + m];
        int prev = (m == 0) ? 0 : g_off[b * NOFF + m - 1];
        int stLo = (prev + 1) >> 6, stHi = off >> 6;
        for (int st = stLo; st <= stHi; st++) {
            float4 p = ((const float4*)(g_part + (((size_t)(b * NST + st) * NM) + m) * NH))[t];
            o.x += p.x; o.y += p.y; o.z += p.z; o.w += p.w;
        }
        float sc = 1.f / (float)(off - prev);
        o.x *= sc; o.y *= sc; o.z *= sc; o.w *= sc;
    } else {
        o = ((const float4*)(g_naf + (size_t)b * NH))[t];
    }
    size_t row = (size_t)(g_rowstart[b] + m);
    __nv_bfloat16 h0 = __float2bfloat16(o.x), h1 = __float2bfloat16(o.y);
    __nv_bfloat16 h2 = __float2bfloat16(o.z), h3 = __float2bfloat16(o.w);
    __nv_bfloat16 l0 = __float2bfloat16(o.x - __bfloat162float(h0));
    __nv_bfloat16 l1 = __float2bfloat16(o.y - __bfloat162float(h1));
    __nv_bfloat16 l2 = __float2bfloat16(o.z - __bfloat162float(h2));
    __nv_bfloat16 l3 = __float2bfloat16(o.w - __bfloat162float(h3));
    __nv_bfloat162 hA = __halves2bfloat162(h0, h1), hB = __halves2bfloat162(h2, h3);
    __nv_bfloat162 lA = __halves2bfloat162(l0, l1), lB = __halves2bfloat162(l2, l3);
    uint2 hv, lv;
    hv.x = *(uint32_t*)&hA; hv.y = *(uint32_t*)&hB;
    lv.x = *(uint32_t*)&lA; lv.y = *(uint32_t*)&lB;
    ((uint2*)(g_nodeH + row * NH))[t] = hv;
    ((uint2*)(g_nodeL + row * NH))[t] = lv;
}

// ============================================================================
// HMMA GEMM on COMPACTED rows: D(ract x 3072) = node @ WT^T, bf16 3-term split.
// ============================================================================
#define TILE_B 8192
#define STAGE_B (4*TILE_B)
#define GEMM_SMEM (3*STAGE_B)

__global__ __launch_bounds__(256, 2) void k_mmagemm(const float* __restrict__ bnd) {
    const int m0 = blockIdx.y * 128, n0 = blockIdx.x * 128;
    if (m0 >= g_ract) return;
    extern __shared__ char smem[];
    uint32_t sb = smem_to_u32(smem);
    const int t = threadIdx.x;
    const int lane = t & 31, wid = t >> 5;
    const int wm = wid >> 2, wn = wid & 3;

    uint32_t swo[2], gOffA[2], gOffB[2];
    #pragma unroll
    for (int j = 0; j < 2; j++) {
        int u = j * 256 + t;
        int r = u >> 2, c = u & 3;
        uint32_t o = (uint32_t)r * 64 + (uint32_t)c * 16;
        swo[j] = o ^ ((o >> 3) & 0x30);
        gOffA[j] = (uint32_t)(m0 + r) * NH + c * 8;
        gOffB[j] = (uint32_t)(n0 + r) * NH + c * 8;
    }

    auto issue = [&](int kc) {
        uint32_t kk = (uint32_t)kc * 32;
        uint32_t d = sb + (kc % 3) * STAGE_B;
        #pragma unroll
        for (int j = 0; j < 2; j++) {
            cp16(d + 0 * TILE_B + swo[j], g_nodeH + gOffA[j] + kk);
            cp16(d + 1 * TILE_B + swo[j], g_nodeL + gOffA[j] + kk);
            cp16(d + 2 * TILE_B + swo[j], g_WTh   + gOffB[j] + kk);
            cp16(d + 3 * TILE_B + swo[j], g_WTl   + gOffB[j] + kk);
        }
        CP_COMMIT();
    };

    float acc[4][4][4] = {};

    const uint32_t aRow = (uint32_t)(wm * 64 + (lane & 15));
    const uint32_t aKhalf = (uint32_t)((lane >> 4) * 16);
    const uint32_t bRowBase = (uint32_t)(wn * 32 + ((lane >> 4) & 1) * 8 + (lane & 7));
    const uint32_t bCol = (uint32_t)(((lane >> 3) & 1) * 16);

    issue(0);
    issue(1);

    for (int kc = 0; kc < 32; kc++) {
        if (kc == 31) { CP_WAIT0(); } else { CP_WAIT1(); }
        __syncthreads();
        if (kc + 2 < 32) issue(kc + 2);
        uint32_t base = sb + (kc % 3) * STAGE_B;

        #pragma unroll
        for (int ks = 0; ks < 2; ks++) {
            uint32_t bH[2][4], bL[2][4];
            #pragma unroll
            for (int p = 0; p < 2; p++) {
                uint32_t o = (bRowBase + p * 16) * 64 + ks * 32 + bCol;
                o ^= (o >> 3) & 0x30;
                ldsm_x4(bH[p], base + 2 * TILE_B + o);
                ldsm_x4(bL[p], base + 3 * TILE_B + o);
            }
            #pragma unroll
            for (int mt = 0; mt < 4; mt++) {
                uint32_t aH[4], aL[4];
                uint32_t o = (aRow + mt * 16) * 64 + ks * 32 + aKhalf;
                o ^= (o >> 3) & 0x30;
                ldsm_x4(aH, base + o);
                ldsm_x4(aL, base + TILE_B + o);
                #pragma unroll
                for (int nt = 0; nt < 4; nt++) {
                    int p = nt >> 1, q = (nt & 1) * 2;
                    mma16816(acc[mt][nt], aH, bH[p][q], bH[p][q + 1]);
                    mma16816(acc[mt][nt], aH, bL[p][q], bL[p][q + 1]);
                    mma16816(acc[mt][nt], aL, bH[p][q], bH[p][q + 1]);
                }
            }
        }
    }

    int sec  = n0 >> 10;
    int ncol = n0 & 1023;
    float* dst = (sec == 0) ? g_ND : ((sec == 1) ? g_A : g_Bm);
    int g = lane >> 2, tq = lane & 3;
    #pragma unroll
    for (int mt = 0; mt < 4; mt++) {
        int m = m0 + wm * 64 + mt * 16 + g;
        int r0 = g_rowmap[m];
        int r1 = g_rowmap[m + 8];
        #pragma unroll
        for (int nt = 0; nt < 4; nt++) {
            int n = ncol + wn * 32 + nt * 8 + tq * 2;
            float2 v0 = make_float2(acc[mt][nt][0], acc[mt][nt][1]);
            float2 v1 = make_float2(acc[mt][nt][2], acc[mt][nt][3]);
            if (sec == 0) {
                float b0 = bnd[n], b1 = bnd[n + 1];
                v0.x = tanhf(v0.x + b0); v0.y = tanhf(v0.y + b1);
                v1.x = tanhf(v1.x + b0); v1.y = tanhf(v1.y + b1);
            }
            if (r0 >= 0) *(float2*)(dst + (size_t)r0 * NH + n) = v0;
            if (r1 >= 0) *(float2*)(dst + (size_t)r1 * NH + n) = v1;
        }
    }
}

// ---------------- kernel: node logits + cls logits (warp per row, merged) ----------
__global__ __launch_bounds__(256) void k_alllogits(const float* __restrict__ Wno,
                                                   const float* __restrict__ bno,
                                                   const float* __restrict__ Wco,
                                                   const float* __restrict__ bco,
                                                   float* __restrict__ out) {
    int blk = blockIdx.x, t = threadIdx.x;
    int warp = t >> 5, lane = t & 31;
    const float4* X;
    const float4* W4;
    float add0, add1;
    float* o;
    if (blk < 208) {
        int r = blk * 8 + warp;
        int b = r / NM, m = r - b * NM;
        o = out + 128 + (size_t)r * 2;
        if (m > g_count[b]) {
            if (lane < 2) o[lane] = g_nlc[lane];
            return;
        }
        X = (const float4*)(g_ND + (size_t)r * NH);
        W4 = (const float4*)Wno;
        add0 = bno[0]; add1 = bno[1];
    } else {
        int b = (blk - 208) * 8 + warp;
        o = out + (size_t)b * 2;
        X = (const float4*)(g_cdact + (size_t)b * NH);
        W4 = (const float4*)Wco;
        add0 = bco[0]; add1 = bco[1];
    }
    float s0 = 0.f, s1 = 0.f;
    #pragma unroll
    for (int it = 0; it < 8; it++) {
        int h4 = it * 32 + lane;
        float4 x  = X[h4];
        float4 wa = W4[h4 * 2];
        float4 wb = W4[h4 * 2 + 1];
        s0 += x.x * wa.x + x.y * wa.z + x.z * wb.x + x.w * wb.z;
        s1 += x.x * wa.y + x.y * wa.w + x.z * wb.y + x.w * wb.w;
    }
    #pragma unroll
    for (int off = 16; off > 0; off >>= 1) {
        s0 += __shfl_down_sync(0xffffffffu, s0, off);
        s1 += __shfl_down_sync(0xffffffffu, s1, off);
    }
    if (lane == 0) { o[0] = s0 + add0; o[1] = s1 + add1; }
}

// ---------------- kernel: edge logits (warp per edge, tanh.approx) ----------------
__global__ __launch_bounds__(256) void k_edges(const float* __restrict__ bed,
                                               const float* __restrict__ Weo,
                                               const float* __restrict__ beo,
                                               float* __restrict__ out) {
    __shared__ __align__(16) float sbed[NH];
    __shared__ __align__(16) float sw0[NH];
    __shared__ __align__(16) float sw1[NH];
    int b = blockIdx.y, t = threadIdx.x;
    for (int h = t; h < NH; h += 256) {
        sbed[h] = bed[h];
        float2 ww = ((const float2*)Weo)[h];
        sw0[h] = ww.x; sw1[h] = ww.y;
    }
    __syncthreads();

    int warp = t >> 5, lane = t & 31;
    int k = blockIdx.x * 8 + warp;
    if (k >= NE) return;
    int n = g_count[b] + 1;
    float* o = out + 128 + NR * 2 + (size_t)(b * NE + k) * 2;
    if (k >= n * n) {
        if (lane < 2) o[lane] = g_cvec[lane];
        return;
    }
    int i = k / n, j = k % n;
    const float4* Ar = (const float4*)(g_A  + (size_t)(b * NM + j) * NH);
    const float4* Br = (const float4*)(g_Bm + (size_t)(b * NM + i) * NH);
    const float4* sb4 = (const float4*)sbed;
    const float4* w04 = (const float4*)sw0;
    const float4* w14 = (const float4*)sw1;
    float s0 = 0.f, s1 = 0.f;
    #pragma unroll
    for (int it = 0; it < 8; it++) {
        int h4 = it * 32 + lane;
        float4 a  = Ar[h4];
        float4 bb = Br[h4];
        float4 be = sb4[h4];
        float4 w0 = w04[h4];
        float4 w1 = w14[h4];
        float v0 = fast_tanh(a.x + bb.x + be.x);
        float v1 = fast_tanh(a.y + bb.y + be.y);
        float v2 = fast_tanh(a.z + bb.z + be.z);
        float v3 = fast_tanh(a.w + bb.w + be.w);
        s0 += v0 * w0.x + v1 * w0.y + v2 * w0.z + v3 * w0.w;
        s1 += v0 * w1.x + v1 * w1.y + v2 * w1.z + v3 * w1.w;
    }
    #pragma unroll
    for (int off = 16; off > 0; off >>= 1) {
        s0 += __shfl_down_sync(0xffffffffu, s0, off);
        s1 += __shfl_down_sync(0xffffffffu, s1, off);
    }
    if (lane == 0) { o[0] = s0 + beo[0]; o[1] = s1 + beo[1]; }
}

// ---------------- launch: multi-stream fork/join (graph-capture legal) -------------
extern "C" void kernel_launch(void* const* d_in, const int* in_sizes, int n_in,
                              void* d_out, int out_size) {
    const float* seq  = (const float*)d_in[0];
    const int*   po   = (const int*)  d_in[1];
    const float* Wnaf = (const float*)d_in[4];
    const float* bnaf = (const float*)d_in[5];
    const float* Wcd  = (const float*)d_in[6];
    const float* bcd  = (const float*)d_in[7];
    const float* Wco  = (const float*)d_in[8];
    const float* bco  = (const float*)d_in[9];
    const float* Wnd  = (const float*)d_in[10];
    const float* bnd  = (const float*)d_in[11];
    const float* Wno  = (const float*)d_in[12];
    const float* bno  = (const float*)d_in[13];
    const float* Wed  = (const float*)d_in[14];
    const float* bed  = (const float*)d_in[15];
    const float* Weo  = (const float*)d_in[16];
    const float* beo  = (const float*)d_in[17];
    float* out = (float*)d_out;

    static cudaStream_t s1 = nullptr, s2 = nullptr;
    static cudaEvent_t ev0, ev1, ev2, ev3, ev4;
    if (!s1) {
        cudaFuncSetAttribute(k_mmagemm, cudaFuncAttributeMaxDynamicSharedMemorySize, GEMM_SMEM);
        cudaStreamCreateWithFlags(&s1, cudaStreamNonBlocking);
        cudaStreamCreateWithFlags(&s2, cudaStreamNonBlocking);
        cudaEventCreateWithFlags(&ev0, cudaEventDisableTiming);
        cudaEventCreateWithFlags(&ev1, cudaEventDisableTiming);
        cudaEventCreateWithFlags(&ev2, cudaEventDisableTiming);
        cudaEventCreateWithFlags(&ev3, cudaEventDisableTiming);
        cudaEventCreateWithFlags(&ev4, cudaEventDisableTiming);
    }

    // root: offsets/counts/cls + constants (legacy stream)
    k_prep0<<<NB + 2, 256>>>(seq, po, bed, Weo, beo, bnd, Wno, bno);
    cudaEventRecord(ev0, 0);

    // branch 1 (s1): gemm1p -> gemm1r(+prefix)
    cudaStreamWaitEvent(s1, ev0, 0);
    k_gemm1p<<<dim3(32, KSPLIT), 256, 0, s1>>>(Wnaf, Wcd);
    k_gemm1r<<<513, 256, 0, s1>>>(bnaf, bcd);
    cudaEventRecord(ev1, s1);

    // branch 2 (s2): weight prep (independent)
    cudaStreamWaitEvent(s2, ev0, 0);
    k_prep_weights<<<dim3(96, 32), dim3(32, 8), 0, s2>>>(Wnd, Wed);
    cudaEventRecord(ev2, s2);

    // legacy: segment sums, then join branch1 -> finalize, join branch2 -> GEMM
    k_segsum<<<dim3(NST, NB, 4), 64>>>(seq);
    cudaStreamWaitEvent(0, ev1, 0);
    k_finalize<<<dim3(NM, NB), 256>>>();
    cudaStreamWaitEvent(0, ev2, 0);
    k_mmagemm<<<dim3(24, 13), 256, GEMM_SMEM>>>(bnd);
    cudaEventRecord(ev3, 0);

    // after GEMM: edges (legacy) || alllogits (s1)
    cudaStreamWaitEvent(s1, ev3, 0);
    k_alllogits<<<216, 256, 0, s1>>>(Wno, bno, Wco, bco, out);
    cudaEventRecord(ev4, s1);
    k_edges<<<dim3(85, NB), 256>>>(bed, Weo, beo, out);
    cudaStreamWaitEvent(0, ev4, 0);
}

// round 10
// speedup vs baseline: 3.9598x; 1.1041x over previous
#include <cuda_runtime.h>
#include <cuda_bf16.h>
#include <math.h>
#include <stdint.h>

#define NB 64
#define NS 512
#define NH 1024
#define NM 26
#define NE 676
#define NR (NB*NM)          // 1664 node rows total
#define NOFF (NM-1)         // 25 offsets per batch
#define NST 8               // S tiles of 64 rows
#define KSPLIT 16           // gemm1 K splits

// ---------------- scratch (device globals; no allocation allowed) ----------------
__device__ int   g_off[NB*NOFF];
__device__ int   g_count[NB];
__device__ int   g_rowstart[NB];
__device__ int   g_rowmap[NR];
__device__ int   g_ract;
__device__ __align__(16) float g_cls[NB*NH];
__device__ __align__(16) float g_cdact[NB*NH];
__device__ __align__(16) float g_g1p[KSPLIT*NB*2048];  // gemm1 split-K partials
__device__ __align__(16) float g_part[NB*NST*NM*NH];   // segment tile partials
__device__ __align__(16) float g_ND[NR*NH];            // tanh(node_full @ W_nd + b_nd)
__device__ __align__(16) float g_A[NR*NH];             // node_full @ (W1+W3)
__device__ __align__(16) float g_Bm[NR*NH];            // node_full @ (W2-W3)
__device__ float g_cvec[2];   // edge logits of all-zero edge row
__device__ float g_nlc[2];    // node logits of all-zero node row
// bf16 split operands for tensor-core GEMM (COMPACTED rows)
__device__ __align__(16) __nv_bfloat16 g_nodeH[NR*NH];
__device__ __align__(16) __nv_bfloat16 g_nodeL[NR*NH];
__device__ __align__(16) __nv_bfloat16 g_WTh[3072*NH];  // W^T (N-major, K cols), hi
__device__ __align__(16) __nv_bfloat16 g_WTl[3072*NH];  // lo

// ============================================================================
// portable PTX helpers (no sm_103a-only features)
// ============================================================================
__device__ __forceinline__ uint32_t smem_to_u32(const void* p) {
    uint32_t a;
    asm("{ .reg .u64 t; cvta.to.shared.u64 t, %1; cvt.u32.u64 %0, t; }" : "=r"(a) : "l"(p));
    return a;
}
__device__ __forceinline__ void ldsm_x4(uint32_t (&r)[4], uint32_t addr) {
    asm volatile("ldmatrix.sync.aligned.m8n8.x4.shared.b16 {%0,%1,%2,%3}, [%4];"
        : "=r"(r[0]), "=r"(r[1]), "=r"(r[2]), "=r"(r[3]) : "r"(addr));
}
__device__ __forceinline__ void mma16816(float (&c)[4], const uint32_t (&a)[4],
                                         uint32_t b0, uint32_t b1) {
    asm volatile("mma.sync.aligned.m16n8k16.row.col.f32.bf16.bf16.f32 "
        "{%0,%1,%2,%3}, {%4,%5,%6,%7}, {%8,%9}, {%0,%1,%2,%3};"
        : "+f"(c[0]), "+f"(c[1]), "+f"(c[2]), "+f"(c[3])
        : "r"(a[0]), "r"(a[1]), "r"(a[2]), "r"(a[3]), "r"(b0), "r"(b1));
}
__device__ __forceinline__ void cp16(uint32_t dst, const void* src) {
    asm volatile("cp.async.cg.shared.global [%0], [%1], 16;" :: "r"(dst), "l"(src));
}
#define CP_COMMIT() asm volatile("cp.async.commit_group;" ::: "memory")
#define CP_WAIT1()  asm volatile("cp.async.wait_group 1;" ::: "memory")
#define CP_WAIT0()  asm volatile("cp.async.wait_group 0;" ::: "memory")

__device__ __forceinline__ float fast_tanh(float x) {
    float y;
    asm("tanh.approx.f32 %0, %1;" : "=f"(y) : "f"(x));
    return y;
}

// ---------------- small helpers ----------------
__device__ __forceinline__ void block_reduce2_store(float s0, float s1,
                                                    float* o0, float* o1,
                                                    float add0, float add1) {
    __shared__ float red[16];
    #pragma unroll
    for (int o = 16; o > 0; o >>= 1) {
        s0 += __shfl_down_sync(0xffffffffu, s0, o);
        s1 += __shfl_down_sync(0xffffffffu, s1, o);
    }
    int t = threadIdx.x;
    if ((t & 31) == 0) { red[t >> 5] = s0; red[8 + (t >> 5)] = s1; }
    __syncthreads();
    if (t == 0) {
        float a = 0.f, b = 0.f;
        #pragma unroll
        for (int w = 0; w < 8; w++) { a += red[w]; b += red[8 + w]; }
        *o0 = a + add0;
        *o1 = b + add1;
    }
}

// ---------------- kernel: prep_cls (0-63) + consts (64-65) + prefix (66) ----------
__global__ void k_prep0(const float* __restrict__ seq, const int* __restrict__ po,
                        const float* __restrict__ bed, const float* __restrict__ Weo,
                        const float* __restrict__ beo, const float* __restrict__ bnd,
                        const float* __restrict__ Wno, const float* __restrict__ bno) {
    int blk = blockIdx.x, t = threadIdx.x;
    if (blk < NB) {
        int b = blk;
        bool wide = (po[1] == 0 && po[3] == 0);
        int val = 0;
        if (t < NOFF) {
            val = wide ? po[(b * NOFF + t) * 2] : po[b * NOFF + t];
            g_off[b * NOFF + t] = val;
        }
        if (t < 32) {
            unsigned mask = __ballot_sync(0xffffffffu, (t < NOFF) && (val > 0));
            if (t == 0) g_count[b] = __popc(mask);
        }
        ((float4*)(g_cls + (size_t)b * NH))[t] =
            ((const float4*)(seq + (size_t)b * NS * NH))[t];
    } else if (blk < NB + 2) {
        int which = blk - NB;               // 0: edge const, 1: node const
        const float*  bias = which ? bnd : bed;
        const float2* w    = which ? (const float2*)Wno : (const float2*)Weo;
        const float*  b2   = which ? bno : beo;
        float* dstp        = which ? g_nlc : g_cvec;
        float s0 = 0.f, s1 = 0.f;
        for (int h = t; h < NH; h += 256) {
            float v = tanhf(bias[h]);
            float2 ww = w[h];
            s0 += v * ww.x; s1 += v * ww.y;
        }
        block_reduce2_store(s0, s1, &dstp[0], &dstp[1], b2[0], b2[1]);
    } else {
        // prefix + rowmap: recompute counts straight from po (no inter-block dep)
        __shared__ int scnt[NB];
        __shared__ int sstart[NB];
        bool wide = (po[1] == 0 && po[3] == 0);
        if (t < NB) {
            int c = 0;
            #pragma unroll
            for (int m = 0; m < NOFF; m++) {
                int v = wide ? po[(t * NOFF + m) * 2] : po[t * NOFF + m];
                c += (v > 0);
            }
            scnt[t] = c;
        }
        __syncthreads();
        if (t == 0) {
            int acc = 0;
            for (int b = 0; b < NB; b++) {
                sstart[b] = acc;
                g_rowstart[b] = acc;
                acc += scnt[b] + 1;
            }
            g_ract = acc;
        }
        __syncthreads();
        for (int i = t; i < NR; i += 256) g_rowmap[i] = -1;
        __syncthreads();
        for (int i = t; i < NB * NM; i += 256) {
            int b = i / NM, m = i - b * NM;
            if (m <= scnt[b]) g_rowmap[sstart[b] + m] = i;
        }
    }
}

// ---------------- kernel: segment partial sums over 64-row S tiles (unroll 8) ------
__global__ void k_segsum(const float* __restrict__ seq) {
    int st = blockIdx.x;          // 0..7
    int b  = blockIdx.y;          // 0..63
    int hc = blockIdx.z;          // 0..3
    int t  = threadIdx.x;         // 0..63
    int s0 = st * 64;
    int sEnd = s0 + 63;
    int cnt = g_count[b];
    const float4* base = (const float4*)(seq + (size_t)b * NS * NH + hc * 256) + t;
    int prev = 0;
    for (int m = 0; m < cnt; m++) {
        int off = g_off[b * NOFF + m];
        int lo = prev + 1;
        if (lo < s0) lo = s0;
        int hi = off < sEnd ? off : sEnd;
        if (lo <= hi) {
            float4 a0 = make_float4(0.f,0.f,0.f,0.f), a1 = a0, a2 = a0, a3 = a0;
            int s = lo;
            for (; s + 7 <= hi; s += 8) {
                float4 v0 = base[(size_t)(s + 0) * 256];
                float4 v1 = base[(size_t)(s + 1) * 256];
                float4 v2 = base[(size_t)(s + 2) * 256];
                float4 v3 = base[(size_t)(s + 3) * 256];
                float4 v4 = base[(size_t)(s + 4) * 256];
                float4 v5 = base[(size_t)(s + 5) * 256];
                float4 v6 = base[(size_t)(s + 6) * 256];
                float4 v7 = base[(size_t)(s + 7) * 256];
                a0.x += v0.x + v4.x; a0.y += v0.y + v4.y; a0.z += v0.z + v4.z; a0.w += v0.w + v4.w;
                a1.x += v1.x + v5.x; a1.y += v1.y + v5.y; a1.z += v1.z + v5.z; a1.w += v1.w + v5.w;
                a2.x += v2.x + v6.x; a2.y += v2.y + v6.y; a2.z += v2.z + v6.z; a2.w += v2.w + v6.w;
                a3.x += v3.x + v7.x; a3.y += v3.y + v7.y; a3.z += v3.z + v7.z; a3.w += v3.w + v7.w;
            }
            for (; s + 3 <= hi; s += 4) {
                float4 v0 = base[(size_t)(s + 0) * 256];
                float4 v1 = base[(size_t)(s + 1) * 256];
                float4 v2 = base[(size_t)(s + 2) * 256];
                float4 v3 = base[(size_t)(s + 3) * 256];
                a0.x += v0.x; a0.y += v0.y; a0.z += v0.z; a0.w += v0.w;
                a1.x += v1.x; a1.y += v1.y; a1.z += v1.z; a1.w += v1.w;
                a2.x += v2.x; a2.y += v2.y; a2.z += v2.z; a2.w += v2.w;
                a3.x += v3.x; a3.y += v3.y; a3.z += v3.z; a3.w += v3.w;
            }
            for (; s <= hi; s++) {
                float4 v = base[(size_t)s * 256];
                a0.x += v.x; a0.y += v.y; a0.z += v.z; a0.w += v.w;
            }
            a0.x += a1.x + a2.x + a3.x;
            a0.y += a1.y + a2.y + a3.y;
            a0.z += a1.z + a2.z + a3.z;
            a0.w += a1.w + a2.w + a3.w;
            ((float4*)(g_part + (((size_t)(b * NST + st) * NM) + m) * NH + hc * 256))[t] = a0;
        }
        prev = off;
        if (prev >= sEnd) break;
    }
}

// ---------------- kernel: GEMM1 split-K partial ----------
__global__ __launch_bounds__(256) void k_gemm1p(const float* __restrict__ Wnaf,
                                                const float* __restrict__ Wcd) {
    __shared__ float Xs[64 * 68];      // [k][m], pad 4
    __shared__ float Ws[64 * 64];      // [k][n]
    int n0 = blockIdx.x * 64;                 // 0..2047
    int ks0 = blockIdx.y * 64;                // K chunk start
    const float* W = (n0 < 1024) ? Wnaf : Wcd;
    int nc0 = (n0 < 1024) ? n0 : n0 - 1024;
    int t = threadIdx.x;
    #pragma unroll
    for (int r = 0; r < 4; r++) {
        int f4 = t + r * 256;
        int row = f4 >> 4, q = f4 & 15;
        float4 x = *(const float4*)(g_cls + (size_t)row * NH + ks0 + q * 4);
        Xs[(q * 4 + 0) * 68 + row] = x.x;
        Xs[(q * 4 + 1) * 68 + row] = x.y;
        Xs[(q * 4 + 2) * 68 + row] = x.z;
        Xs[(q * 4 + 3) * 68 + row] = x.w;
        float4 w = *(const float4*)(W + (size_t)(ks0 + row) * 1024 + nc0 + q * 4);
        *(float4*)(Ws + row * 64 + q * 4) = w;
    }
    __syncthreads();
    int tx = t & 15, ty = t >> 4;
    float acc[4][4] = {};
    #pragma unroll 16
    for (int k = 0; k < 64; k++) {
        float a[4], bb[4];
        *(float4*)a  = *(const float4*)(Xs + k * 68 + ty * 4);
        *(float4*)bb = *(const float4*)(Ws + k * 64 + tx * 4);
        #pragma unroll
        for (int i = 0; i < 4; i++)
            #pragma unroll
            for (int j = 0; j < 4; j++)
                acc[i][j] += a[i] * bb[j];
    }
    float* dst = g_g1p + (size_t)blockIdx.y * NB * 2048;
    #pragma unroll
    for (int i = 0; i < 4; i++) {
        int m = ty * 4 + i;
        #pragma unroll
        for (int j = 0; j < 4; j++)
            dst[(size_t)m * 2048 + n0 + tx * 4 + j] = acc[i][j];
    }
}

// ---------------- kernel: GEMM1 reduce, cdact half only (off critical path) --------
__global__ void k_gemm1r_cd(const float* __restrict__ bcd) {
    int idx = blockIdx.x * 256 + threadIdx.x;   // 0 .. 64*1024-1
    int m = idx >> 10, c = idx & 1023;
    float s = 0.f;
    #pragma unroll
    for (int ks = 0; ks < KSPLIT; ks++)
        s += g_g1p[(size_t)ks * NB * 2048 + m * 2048 + 1024 + c];
    g_cdact[(size_t)m * NH + c] = tanhf(s + bcd[c]);
}

// ---------------- kernel: W^T build + bf16 split ----------------
__global__ void k_prep_weights(const float* __restrict__ Wnd,
                               const float* __restrict__ Wed) {
    __shared__ float tile[32][33];
    int n0 = blockIdx.x * 32;
    int k0 = blockIdx.y * 32;
    int tx = threadIdx.x, ty = threadIdx.y;
    #pragma unroll
    for (int kk = 0; kk < 32; kk += 8) {
        int k = k0 + kk + ty;
        int n = n0 + tx;
        float v;
        if (n < 1024) v = Wnd[(size_t)k * 1024 + n];
        else if (n < 2048) { int c = n - 1024; v = Wed[(size_t)k * 1024 + c] + Wed[(size_t)(2048 + k) * 1024 + c]; }
        else { int c = n - 2048; v = Wed[(size_t)(1024 + k) * 1024 + c] - Wed[(size_t)(2048 + k) * 1024 + c]; }
        tile[kk + ty][tx] = v;
    }
    __syncthreads();
    #pragma unroll
    for (int kk = 0; kk < 32; kk += 8) {
        int n = n0 + kk + ty;
        int k = k0 + tx;
        float v = tile[tx][kk + ty];
        __nv_bfloat16 h = __float2bfloat16(v);
        g_WTh[(size_t)n * NH + k] = h;
        g_WTl[(size_t)n * NH + k] = __float2bfloat16(v - __bfloat162float(h));
    }
}

// ---------------- kernel: finalize node rows (naf reduced inline), bf16 split ------
__global__ void k_finalize(const float* __restrict__ bnaf) {
    int m = blockIdx.x, b = blockIdx.y, t = threadIdx.x;
    int cnt = g_count[b];
    if (m > cnt) return;
    float4 o = make_float4(0.f, 0.f, 0.f, 0.f);
    if (m < cnt) {
        int off  = g_off[b * NOFF + m];
        int prev = (m == 0) ? 0 : g_off[b * NOFF + m - 1];
        int stLo = (prev + 1) >> 6, stHi = off >> 6;
        for (int st = stLo; st <= stHi; st++) {
            float4 p = ((const float4*)(g_part + (((size_t)(b * NST + st) * NM) + m) * NH))[t];
            o.x += p.x; o.y += p.y; o.z += p.z; o.w += p.w;
        }
        float sc = 1.f / (float)(off - prev);
        o.x *= sc; o.y *= sc; o.z *= sc; o.w *= sc;
    } else {
        // naf row: reduce gemm1 split-K partials directly (cols 0..1023)
        #pragma unroll
        for (int ks = 0; ks < KSPLIT; ks++) {
            float4 p = *(const float4*)(g_g1p + (size_t)ks * NB * 2048 + b * 2048 + t * 4);
            o.x += p.x; o.y += p.y; o.z += p.z; o.w += p.w;
        }
        float4 bn = *(const float4*)(bnaf + t * 4);
        o.x += bn.x; o.y += bn.y; o.z += bn.z; o.w += bn.w;
    }
    size_t row = (size_t)(g_rowstart[b] + m);
    __nv_bfloat16 h0 = __float2bfloat16(o.x), h1 = __float2bfloat16(o.y);
    __nv_bfloat16 h2 = __float2bfloat16(o.z), h3 = __float2bfloat16(o.w);
    __nv_bfloat16 l0 = __float2bfloat16(o.x - __bfloat162float(h0));
    __nv_bfloat16 l1 = __float2bfloat16(o.y - __bfloat162float(h1));
    __nv_bfloat16 l2 = __float2bfloat16(o.z - __bfloat162float(h2));
    __nv_bfloat16 l3 = __float2bfloat16(o.w - __bfloat162float(h3));
    __nv_bfloat162 hA = __halves2bfloat162(h0, h1), hB = __halves2bfloat162(h2, h3);
    __nv_bfloat162 lA = __halves2bfloat162(l0, l1), lB = __halves2bfloat162(l2, l3);
    uint2 hv, lv;
    hv.x = *(uint32_t*)&hA; hv.y = *(uint32_t*)&hB;
    lv.x = *(uint32_t*)&lA; lv.y = *(uint32_t*)&lB;
    ((uint2*)(g_nodeH + row * NH))[t] = hv;
    ((uint2*)(g_nodeL + row * NH))[t] = lv;
}

// ============================================================================
// HMMA GEMM on COMPACTED rows, M-tile 64 for SM load balance.
// CTA 64x128, K-tile 32, 3-stage cp.async, 24KB/stage (72KB -> 3 CTA/SM).
// 8 warps (2m x 4n), warp tile 32x32.
// ============================================================================
#define TB_A 4096
#define TB_B 8192
#define STG_B 24576
#define GEMM_SMEM (3*STG_B)

__global__ __launch_bounds__(256, 3) void k_mmagemm(const float* __restrict__ bnd) {
    const int m0 = blockIdx.y * 64, n0 = blockIdx.x * 128;
    if (m0 >= g_ract) return;
    extern __shared__ char smem[];
    uint32_t sb = smem_to_u32(smem);
    const int t = threadIdx.x;
    const int lane = t & 31, wid = t >> 5;
    const int wm = wid >> 2, wn = wid & 3;

    // copy geometry: A 1 chunk/thread per h|l, B 2 chunks/thread per h|l
    uint32_t rA = (uint32_t)t >> 2, cA = (uint32_t)t & 3;
    uint32_t oA = rA * 64 + cA * 16;
    uint32_t swoA = oA ^ ((oA >> 3) & 0x30);
    uint32_t gA = (uint32_t)(m0 + rA) * NH + cA * 8;
    uint32_t swoB[2], gB[2];
    #pragma unroll
    for (int j = 0; j < 2; j++) {
        int u = j * 256 + t;
        uint32_t rB = (uint32_t)u >> 2, cB = (uint32_t)u & 3;
        uint32_t o = rB * 64 + cB * 16;
        swoB[j] = o ^ ((o >> 3) & 0x30);
        gB[j] = (uint32_t)(n0 + rB) * NH + cB * 8;
    }

    auto issue = [&](int kc) {
        uint32_t kk = (uint32_t)kc * 32;
        uint32_t d = sb + (kc % 3) * STG_B;
        cp16(d + swoA,        g_nodeH + gA + kk);
        cp16(d + TB_A + swoA, g_nodeL + gA + kk);
        #pragma unroll
        for (int j = 0; j < 2; j++) {
            cp16(d + 2 * TB_A + swoB[j],        g_WTh + gB[j] + kk);
            cp16(d + 2 * TB_A + TB_B + swoB[j], g_WTl + gB[j] + kk);
        }
        CP_COMMIT();
    };

    float acc[2][4][4] = {};

    const uint32_t aRow = (uint32_t)(wm * 32 + (lane & 15));
    const uint32_t aKhalf = (uint32_t)((lane >> 4) * 16);
    const uint32_t bRowBase = (uint32_t)(wn * 32 + ((lane >> 4) & 1) * 8 + (lane & 7));
    const uint32_t bCol = (uint32_t)(((lane >> 3) & 1) * 16);

    issue(0);
    issue(1);

    for (int kc = 0; kc < 32; kc++) {
        if (kc == 31) { CP_WAIT0(); } else { CP_WAIT1(); }
        __syncthreads();
        if (kc + 2 < 32) issue(kc + 2);
        uint32_t base = sb + (kc % 3) * STG_B;

        #pragma unroll
        for (int ks = 0; ks < 2; ks++) {
            uint32_t bH[2][4], bL[2][4];
            #pragma unroll
            for (int p = 0; p < 2; p++) {
                uint32_t o = (bRowBase + p * 16) * 64 + ks * 32 + bCol;
                o ^= (o >> 3) & 0x30;
                ldsm_x4(bH[p], base + 2 * TB_A + o);
                ldsm_x4(bL[p], base + 2 * TB_A + TB_B + o);
            }
            #pragma unroll
            for (int mt = 0; mt < 2; mt++) {
                uint32_t aH[4], aL[4];
                uint32_t o = (aRow + mt * 16) * 64 + ks * 32 + aKhalf;
                o ^= (o >> 3) & 0x30;
                ldsm_x4(aH, base + o);
                ldsm_x4(aL, base + TB_A + o);
                #pragma unroll
                for (int nt = 0; nt < 4; nt++) {
                    int p = nt >> 1, q = (nt & 1) * 2;
                    mma16816(acc[mt][nt], aH, bH[p][q], bH[p][q + 1]);
                    mma16816(acc[mt][nt], aH, bL[p][q], bL[p][q + 1]);
                    mma16816(acc[mt][nt], aL, bH[p][q], bH[p][q + 1]);
                }
            }
        }
    }

    int sec  = n0 >> 10;
    int ncol = n0 & 1023;
    float* dst = (sec == 0) ? g_ND : ((sec == 1) ? g_A : g_Bm);
    int g = lane >> 2, tq = lane & 3;
    #pragma unroll
    for (int mt = 0; mt < 2; mt++) {
        int m = m0 + wm * 32 + mt * 16 + g;
        int r0 = g_rowmap[m];
        int r1 = g_rowmap[m + 8];
        #pragma unroll
        for (int nt = 0; nt < 4; nt++) {
            int n = ncol + wn * 32 + nt * 8 + tq * 2;
            float2 v0 = make_float2(acc[mt][nt][0], acc[mt][nt][1]);
            float2 v1 = make_float2(acc[mt][nt][2], acc[mt][nt][3]);
            if (sec == 0) {
                float b0 = bnd[n], b1 = bnd[n + 1];
                v0.x = tanhf(v0.x + b0); v0.y = tanhf(v0.y + b1);
                v1.x = tanhf(v1.x + b0); v1.y = tanhf(v1.y + b1);
            }
            if (r0 >= 0) *(float2*)(dst + (size_t)r0 * NH + n) = v0;
            if (r1 >= 0) *(float2*)(dst + (size_t)r1 * NH + n) = v1;
        }
    }
}

// ---------------- kernel: edges + node logits + cls logits (merged) ----------------
#define EB (NE + 7) / 8            // 85 edge blocks per batch
__global__ __launch_bounds__(256) void k_final(const float* __restrict__ bed,
                                               const float* __restrict__ Weo,
                                               const float* __restrict__ beo,
                                               const float* __restrict__ Wno,
                                               const float* __restrict__ bno,
                                               const float* __restrict__ Wco,
                                               const float* __restrict__ bco,
                                               float* __restrict__ out) {
    int blk = blockIdx.x, t = threadIdx.x;
    int warp = t >> 5, lane = t & 31;
    if (blk < 85 * NB) {
        // ---- edge logits, warp per edge ----
        __shared__ __align__(16) float sbed[NH];
        __shared__ __align__(16) float sw0[NH];
        __shared__ __align__(16) float sw1[NH];
        int b = blk / 85, kb = blk % 85;
        for (int h = t; h < NH; h += 256) {
            sbed[h] = bed[h];
            float2 ww = ((const float2*)Weo)[h];
            sw0[h] = ww.x; sw1[h] = ww.y;
        }
        __syncthreads();
        int k = kb * 8 + warp;
        if (k >= NE) return;
        int n = g_count[b] + 1;
        float* o = out + 128 + NR * 2 + (size_t)(b * NE + k) * 2;
        if (k >= n * n) {
            if (lane < 2) o[lane] = g_cvec[lane];
            return;
        }
        int i = k / n, j = k % n;
        const float4* Ar = (const float4*)(g_A  + (size_t)(b * NM + j) * NH);
        const float4* Br = (const float4*)(g_Bm + (size_t)(b * NM + i) * NH);
        const float4* sb4 = (const float4*)sbed;
        const float4* w04 = (const float4*)sw0;
        const float4* w14 = (const float4*)sw1;
        float s0 = 0.f, s1 = 0.f;
        #pragma unroll
        for (int it = 0; it < 8; it++) {
            int h4 = it * 32 + lane;
            float4 a  = Ar[h4];
            float4 bb = Br[h4];
            float4 be = sb4[h4];
            float4 w0 = w04[h4];
            float4 w1 = w14[h4];
            float v0 = fast_tanh(a.x + bb.x + be.x);
            float v1 = fast_tanh(a.y + bb.y + be.y);
            float v2 = fast_tanh(a.z + bb.z + be.z);
            float v3 = fast_tanh(a.w + bb.w + be.w);
            s0 += v0 * w0.x + v1 * w0.y + v2 * w0.z + v3 * w0.w;
            s1 += v0 * w1.x + v1 * w1.y + v2 * w1.z + v3 * w1.w;
        }
        #pragma unroll
        for (int off = 16; off > 0; off >>= 1) {
            s0 += __shfl_down_sync(0xffffffffu, s0, off);
            s1 += __shfl_down_sync(0xffffffffu, s1, off);
        }
        if (lane == 0) { o[0] = s0 + beo[0]; o[1] = s1 + beo[1]; }
    } else {
        // ---- node + cls logits, warp per row ----
        int ablk = blk - 85 * NB;           // 0..215
        const float4* X;
        const float4* W4;
        float add0, add1;
        float* o;
        if (ablk < 208) {
            int r = ablk * 8 + warp;
            int b = r / NM, m = r - b * NM;
            o = out + 128 + (size_t)r * 2;
            if (m > g_count[b]) {
                if (lane < 2) o[lane] = g_nlc[lane];
                return;
            }
            X = (const float4*)(g_ND + (size_t)r * NH);
            W4 = (const float4*)Wno;
            add0 = bno[0]; add1 = bno[1];
        } else {
            int b = (ablk - 208) * 8 + warp;
            o = out + (size_t)b * 2;
            X = (const float4*)(g_cdact + (size_t)b * NH);
            W4 = (const float4*)Wco;
            add0 = bco[0]; add1 = bco[1];
        }
        float s0 = 0.f, s1 = 0.f;
        #pragma unroll
        for (int it = 0; it < 8; it++) {
            int h4 = it * 32 + lane;
            float4 x  = X[h4];
            float4 wa = W4[h4 * 2];
            float4 wb = W4[h4 * 2 + 1];
            s0 += x.x * wa.x + x.y * wa.z + x.z * wb.x + x.w * wb.z;
            s1 += x.x * wa.y + x.y * wa.w + x.z * wb.y + x.w * wb.w;
        }
        #pragma unroll
        for (int off = 16; off > 0; off >>= 1) {
            s0 += __shfl_down_sync(0xffffffffu, s0, off);
            s1 += __shfl_down_sync(0xffffffffu, s1, off);
        }
        if (lane == 0) { o[0] = s0 + add0; o[1] = s1 + add1; }
    }
}

// ---------------- launch: multi-stream fork/join (graph-capture legal) -------------
extern "C" void kernel_launch(void* const* d_in, const int* in_sizes, int n_in,
                              void* d_out, int out_size) {
    const float* seq  = (const float*)d_in[0];
    const int*   po   = (const int*)  d_in[1];
    const float* Wnaf = (const float*)d_in[4];
    const float* bnaf = (const float*)d_in[5];
    const float* Wcd  = (const float*)d_in[6];
    const float* bcd  = (const float*)d_in[7];
    const float* Wco  = (const float*)d_in[8];
    const float* bco  = (const float*)d_in[9];
    const float* Wnd  = (const float*)d_in[10];
    const float* bnd  = (const float*)d_in[11];
    const float* Wno  = (const float*)d_in[12];
    const float* bno  = (const float*)d_in[13];
    const float* Wed  = (const float*)d_in[14];
    const float* bed  = (const float*)d_in[15];
    const float* Weo  = (const float*)d_in[16];
    const float* beo  = (const float*)d_in[17];
    float* out = (float*)d_out;

    static cudaStream_t s1 = nullptr, s2 = nullptr;
    static cudaEvent_t ev0, ev1, ev2, evR;
    if (!s1) {
        cudaFuncSetAttribute(k_mmagemm, cudaFuncAttributeMaxDynamicSharedMemorySize, GEMM_SMEM);
        cudaStreamCreateWithFlags(&s1, cudaStreamNonBlocking);
        cudaStreamCreateWithFlags(&s2, cudaStreamNonBlocking);
        cudaEventCreateWithFlags(&ev0, cudaEventDisableTiming);
        cudaEventCreateWithFlags(&ev1, cudaEventDisableTiming);
        cudaEventCreateWithFlags(&ev2, cudaEventDisableTiming);
        cudaEventCreateWithFlags(&evR, cudaEventDisableTiming);
    }

    // 1: root (offsets/counts/cls/consts/prefix)
    k_prep0<<<NB + 3, 256>>>(seq, po, bed, Weo, beo, bnd, Wno, bno);
    cudaEventRecord(ev0, 0);

    // 2 (s1): gemm1p
    cudaStreamWaitEvent(s1, ev0, 0);
    k_gemm1p<<<dim3(32, KSPLIT), 256, 0, s1>>>(Wnaf, Wcd);
    cudaEventRecord(ev1, s1);

    // 3 (s2): weight prep
    cudaStreamWaitEvent(s2, ev0, 0);
    k_prep_weights<<<dim3(96, 32), dim3(32, 8), 0, s2>>>(Wnd, Wed);
    cudaEventRecord(ev2, s2);

    // 4 (legacy): segment sums  <- profiled slot
    k_segsum<<<dim3(NST, NB, 4), 64>>>(seq);

    // 5 (s1): cdact reduce, off critical path
    k_gemm1r_cd<<<256, 256, 0, s1>>>(bcd);
    cudaEventRecord(evR, s1);

    // 6 (legacy): finalize (needs segsum + gemm1p partials)
    cudaStreamWaitEvent(0, ev1, 0);
    k_finalize<<<dim3(NM, NB), 256>>>(bnaf);

    // 7 (legacy): tensor GEMM (needs weights too)
    cudaStreamWaitEvent(0, ev2, 0);
    k_mmagemm<<<dim3(24, 26), 256, GEMM_SMEM>>>(bnd);

    // 8 (legacy): fused epilogue (edges + node/cls logits; needs cdact)
    cudaStreamWaitEvent(0, evR, 0);
    k_final<<<85 * NB + 216, 256>>>(bed, Weo, beo, Wno, bno, Wco, bco, out);
}

// round 11
// speedup vs baseline: 4.1447x; 1.0467x over previous
#include <cuda_runtime.h>
#include <cuda_bf16.h>
#include <math.h>
#include <stdint.h>

#define NB 64
#define NS 512
#define NH 1024
#define NM 26
#define NE 676
#define NR (NB*NM)          // 1664 node rows total
#define NOFF (NM-1)         // 25 offsets per batch
#define NST 16              // S tiles of 32 rows
#define KSPLIT 16           // gemm1 K splits

// ---------------- scratch (device globals; no allocation allowed) ----------------
__device__ int   g_off[NB*NOFF];
__device__ int   g_count[NB];
__device__ int   g_rowstart[NB];
__device__ int   g_rowmap[NR];
__device__ int   g_ract;
__device__ __align__(16) float g_cls[NB*NH];
__device__ __align__(16) float g_cdact[NB*NH];
__device__ __align__(16) float g_g1p[KSPLIT*NB*2048];  // gemm1 split-K partials
__device__ __align__(16) float g_part[NB*NST*NM*NH];   // segment tile partials (~104MB)
__device__ __align__(16) float g_ND[NR*NH];            // tanh(node_full @ W_nd + b_nd)
__device__ __align__(16) float g_A[NR*NH];             // node_full @ (W1+W3) + b_ed
__device__ __align__(16) float g_Bm[NR*NH];            // node_full @ (W2-W3)
__device__ float g_cvec[2];   // edge logits of all-zero edge row
__device__ float g_nlc[2];    // node logits of all-zero node row
// bf16 split operands for tensor-core GEMM (COMPACTED rows)
__device__ __align__(16) __nv_bfloat16 g_nodeH[NR*NH];
__device__ __align__(16) __nv_bfloat16 g_nodeL[NR*NH];
__device__ __align__(16) __nv_bfloat16 g_WTh[3072*NH];  // W^T (N-major, K cols), hi
__device__ __align__(16) __nv_bfloat16 g_WTl[3072*NH];  // lo

// ============================================================================
// portable PTX helpers (no sm_103a-only features)
// ============================================================================
__device__ __forceinline__ uint32_t smem_to_u32(const void* p) {
    uint32_t a;
    asm("{ .reg .u64 t; cvta.to.shared.u64 t, %1; cvt.u32.u64 %0, t; }" : "=r"(a) : "l"(p));
    return a;
}
__device__ __forceinline__ void ldsm_x4(uint32_t (&r)[4], uint32_t addr) {
    asm volatile("ldmatrix.sync.aligned.m8n8.x4.shared.b16 {%0,%1,%2,%3}, [%4];"
        : "=r"(r[0]), "=r"(r[1]), "=r"(r[2]), "=r"(r[3]) : "r"(addr));
}
__device__ __forceinline__ void mma16816(float (&c)[4], const uint32_t (&a)[4],
                                         uint32_t b0, uint32_t b1) {
    asm volatile("mma.sync.aligned.m16n8k16.row.col.f32.bf16.bf16.f32 "
        "{%0,%1,%2,%3}, {%4,%5,%6,%7}, {%8,%9}, {%0,%1,%2,%3};"
        : "+f"(c[0]), "+f"(c[1]), "+f"(c[2]), "+f"(c[3])
        : "r"(a[0]), "r"(a[1]), "r"(a[2]), "r"(a[3]), "r"(b0), "r"(b1));
}
__device__ __forceinline__ void cp16(uint32_t dst, const void* src) {
    asm volatile("cp.async.cg.shared.global [%0], [%1], 16;" :: "r"(dst), "l"(src));
}
#define CP_COMMIT() asm volatile("cp.async.commit_group;" ::: "memory")
#define CP_WAIT1()  asm volatile("cp.async.wait_group 1;" ::: "memory")
#define CP_WAIT0()  asm volatile("cp.async.wait_group 0;" ::: "memory")

__device__ __forceinline__ float fast_tanh(float x) {
    float y;
    asm("tanh.approx.f32 %0, %1;" : "=f"(y) : "f"(x));
    return y;
}

// ---------------- small helpers ----------------
__device__ __forceinline__ void block_reduce2_store(float s0, float s1,
                                                    float* o0, float* o1,
                                                    float add0, float add1) {
    __shared__ float red[16];
    #pragma unroll
    for (int o = 16; o > 0; o >>= 1) {
        s0 += __shfl_down_sync(0xffffffffu, s0, o);
        s1 += __shfl_down_sync(0xffffffffu, s1, o);
    }
    int t = threadIdx.x;
    if ((t & 31) == 0) { red[t >> 5] = s0; red[8 + (t >> 5)] = s1; }
    __syncthreads();
    if (t == 0) {
        float a = 0.f, b = 0.f;
        #pragma unroll
        for (int w = 0; w < 8; w++) { a += red[w]; b += red[8 + w]; }
        *o0 = a + add0;
        *o1 = b + add1;
    }
}

// ---------------- kernel: prep_cls (0-63) + consts (64-65) + prefix (66) ----------
__global__ void k_prep0(const float* __restrict__ seq, const int* __restrict__ po,
                        const float* __restrict__ bed, const float* __restrict__ Weo,
                        const float* __restrict__ beo, const float* __restrict__ bnd,
                        const float* __restrict__ Wno, const float* __restrict__ bno) {
    int blk = blockIdx.x, t = threadIdx.x;
    if (blk < NB) {
        int b = blk;
        bool wide = (po[1] == 0 && po[3] == 0);
        int val = 0;
        if (t < NOFF) {
            val = wide ? po[(b * NOFF + t) * 2] : po[b * NOFF + t];
            g_off[b * NOFF + t] = val;
        }
        if (t < 32) {
            unsigned mask = __ballot_sync(0xffffffffu, (t < NOFF) && (val > 0));
            if (t == 0) g_count[b] = __popc(mask);
        }
        ((float4*)(g_cls + (size_t)b * NH))[t] =
            ((const float4*)(seq + (size_t)b * NS * NH))[t];
    } else if (blk < NB + 2) {
        int which = blk - NB;               // 0: edge const, 1: node const
        const float*  bias = which ? bnd : bed;
        const float2* w    = which ? (const float2*)Wno : (const float2*)Weo;
        const float*  b2   = which ? bno : beo;
        float* dstp        = which ? g_nlc : g_cvec;
        float s0 = 0.f, s1 = 0.f;
        for (int h = t; h < NH; h += 256) {
            float v = tanhf(bias[h]);
            float2 ww = w[h];
            s0 += v * ww.x; s1 += v * ww.y;
        }
        block_reduce2_store(s0, s1, &dstp[0], &dstp[1], b2[0], b2[1]);
    } else {
        // prefix + rowmap: recompute counts straight from po (no inter-block dep)
        __shared__ int scnt[NB];
        __shared__ int sstart[NB];
        bool wide = (po[1] == 0 && po[3] == 0);
        if (t < NB) {
            int c = 0;
            #pragma unroll
            for (int m = 0; m < NOFF; m++) {
                int v = wide ? po[(t * NOFF + m) * 2] : po[t * NOFF + m];
                c += (v > 0);
            }
            scnt[t] = c;
        }
        __syncthreads();
        if (t == 0) {
            int acc = 0;
            for (int b = 0; b < NB; b++) {
                sstart[b] = acc;
                g_rowstart[b] = acc;
                acc += scnt[b] + 1;
            }
            g_ract = acc;
        }
        __syncthreads();
        for (int i = t; i < NR; i += 256) g_rowmap[i] = -1;
        __syncthreads();
        for (int i = t; i < NB * NM; i += 256) {
            int b = i / NM, m = i - b * NM;
            if (m <= scnt[b]) g_rowmap[sstart[b] + m] = i;
        }
    }
}

// ---------------- kernel: segment partial sums over 32-row S tiles ----------------
__global__ void k_segsum(const float* __restrict__ seq) {
    int st = blockIdx.x;          // 0..15
    int b  = blockIdx.y;          // 0..63
    int hc = blockIdx.z;          // 0..3
    int t  = threadIdx.x;         // 0..63
    int s0 = st * 32;
    int sEnd = s0 + 31;
    int cnt = g_count[b];
    const float4* base = (const float4*)(seq + (size_t)b * NS * NH + hc * 256) + t;
    int prev = 0;
    for (int m = 0; m < cnt; m++) {
        int off = g_off[b * NOFF + m];
        int lo = prev + 1;
        if (lo < s0) lo = s0;
        int hi = off < sEnd ? off : sEnd;
        if (lo <= hi) {
            float4 a0 = make_float4(0.f,0.f,0.f,0.f), a1 = a0, a2 = a0, a3 = a0;
            int s = lo;
            for (; s + 3 <= hi; s += 4) {
                float4 v0 = base[(size_t)(s + 0) * 256];
                float4 v1 = base[(size_t)(s + 1) * 256];
                float4 v2 = base[(size_t)(s + 2) * 256];
                float4 v3 = base[(size_t)(s + 3) * 256];
                a0.x += v0.x; a0.y += v0.y; a0.z += v0.z; a0.w += v0.w;
                a1.x += v1.x; a1.y += v1.y; a1.z += v1.z; a1.w += v1.w;
                a2.x += v2.x; a2.y += v2.y; a2.z += v2.z; a2.w += v2.w;
                a3.x += v3.x; a3.y += v3.y; a3.z += v3.z; a3.w += v3.w;
            }
            for (; s <= hi; s++) {
                float4 v = base[(size_t)s * 256];
                a0.x += v.x; a0.y += v.y; a0.z += v.z; a0.w += v.w;
            }
            a0.x += a1.x + a2.x + a3.x;
            a0.y += a1.y + a2.y + a3.y;
            a0.z += a1.z + a2.z + a3.z;
            a0.w += a1.w + a2.w + a3.w;
            ((float4*)(g_part + (((size_t)(b * NST + st) * NM) + m) * NH + hc * 256))[t] = a0;
        }
        prev = off;
        if (prev >= sEnd) break;
    }
}

// ---------------- kernel: GEMM1 split-K partial ----------
__global__ __launch_bounds__(256) void k_gemm1p(const float* __restrict__ Wnaf,
                                                const float* __restrict__ Wcd) {
    __shared__ float Xs[64 * 68];      // [k][m], pad 4
    __shared__ float Ws[64 * 64];      // [k][n]
    int n0 = blockIdx.x * 64;                 // 0..2047
    int ks0 = blockIdx.y * 64;                // K chunk start
    const float* W = (n0 < 1024) ? Wnaf : Wcd;
    int nc0 = (n0 < 1024) ? n0 : n0 - 1024;
    int t = threadIdx.x;
    #pragma unroll
    for (int r = 0; r < 4; r++) {
        int f4 = t + r * 256;
        int row = f4 >> 4, q = f4 & 15;
        float4 x = *(const float4*)(g_cls + (size_t)row * NH + ks0 + q * 4);
        Xs[(q * 4 + 0) * 68 + row] = x.x;
        Xs[(q * 4 + 1) * 68 + row] = x.y;
        Xs[(q * 4 + 2) * 68 + row] = x.z;
        Xs[(q * 4 + 3) * 68 + row] = x.w;
        float4 w = *(const float4*)(W + (size_t)(ks0 + row) * 1024 + nc0 + q * 4);
        *(float4*)(Ws + row * 64 + q * 4) = w;
    }
    __syncthreads();
    int tx = t & 15, ty = t >> 4;
    float acc[4][4] = {};
    #pragma unroll 16
    for (int k = 0; k < 64; k++) {
        float a[4], bb[4];
        *(float4*)a  = *(const float4*)(Xs + k * 68 + ty * 4);
        *(float4*)bb = *(const float4*)(Ws + k * 64 + tx * 4);
        #pragma unroll
        for (int i = 0; i < 4; i++)
            #pragma unroll
            for (int j = 0; j < 4; j++)
                acc[i][j] += a[i] * bb[j];
    }
    float* dst = g_g1p + (size_t)blockIdx.y * NB * 2048;
    #pragma unroll
    for (int i = 0; i < 4; i++) {
        int m = ty * 4 + i;
        #pragma unroll
        for (int j = 0; j < 4; j++)
            dst[(size_t)m * 2048 + n0 + tx * 4 + j] = acc[i][j];
    }
}

// ---------------- kernel: GEMM1 reduce, cdact half only (off critical path) --------
__global__ void k_gemm1r_cd(const float* __restrict__ bcd) {
    int idx = blockIdx.x * 256 + threadIdx.x;   // 0 .. 64*1024-1
    int m = idx >> 10, c = idx & 1023;
    float s = 0.f;
    #pragma unroll
    for (int ks = 0; ks < KSPLIT; ks++)
        s += g_g1p[(size_t)ks * NB * 2048 + m * 2048 + 1024 + c];
    g_cdact[(size_t)m * NH + c] = tanhf(s + bcd[c]);
}

// ---------------- kernel: W^T build + bf16 split ----------------
__global__ void k_prep_weights(const float* __restrict__ Wnd,
                               const float* __restrict__ Wed) {
    __shared__ float tile[32][33];
    int n0 = blockIdx.x * 32;
    int k0 = blockIdx.y * 32;
    int tx = threadIdx.x, ty = threadIdx.y;
    #pragma unroll
    for (int kk = 0; kk < 32; kk += 8) {
        int k = k0 + kk + ty;
        int n = n0 + tx;
        float v;
        if (n < 1024) v = Wnd[(size_t)k * 1024 + n];
        else if (n < 2048) { int c = n - 1024; v = Wed[(size_t)k * 1024 + c] + Wed[(size_t)(2048 + k) * 1024 + c]; }
        else { int c = n - 2048; v = Wed[(size_t)(1024 + k) * 1024 + c] - Wed[(size_t)(2048 + k) * 1024 + c]; }
        tile[kk + ty][tx] = v;
    }
    __syncthreads();
    #pragma unroll
    for (int kk = 0; kk < 32; kk += 8) {
        int n = n0 + kk + ty;
        int k = k0 + tx;
        float v = tile[tx][kk + ty];
        __nv_bfloat16 h = __float2bfloat16(v);
        g_WTh[(size_t)n * NH + k] = h;
        g_WTl[(size_t)n * NH + k] = __float2bfloat16(v - __bfloat162float(h));
    }
}

// ---------------- kernel: finalize node rows (naf reduced inline), bf16 split ------
__global__ void k_finalize(const float* __restrict__ bnaf) {
    int m = blockIdx.x, b = blockIdx.y, t = threadIdx.x;
    int cnt = g_count[b];
    if (m > cnt) return;
    float4 o = make_float4(0.f, 0.f, 0.f, 0.f);
    if (m < cnt) {
        int off  = g_off[b * NOFF + m];
        int prev = (m == 0) ? 0 : g_off[b * NOFF + m - 1];
        int stLo = (prev + 1) >> 5, stHi = off >> 5;
        for (int st = stLo; st <= stHi; st++) {
            float4 p = ((const float4*)(g_part + (((size_t)(b * NST + st) * NM) + m) * NH))[t];
            o.x += p.x; o.y += p.y; o.z += p.z; o.w += p.w;
        }
        float sc = 1.f / (float)(off - prev);
        o.x *= sc; o.y *= sc; o.z *= sc; o.w *= sc;
    } else {
        // naf row: reduce gemm1 split-K partials directly (cols 0..1023)
        #pragma unroll
        for (int ks = 0; ks < KSPLIT; ks++) {
            float4 p = *(const float4*)(g_g1p + (size_t)ks * NB * 2048 + b * 2048 + t * 4);
            o.x += p.x; o.y += p.y; o.z += p.z; o.w += p.w;
        }
        float4 bn = *(const float4*)(bnaf + t * 4);
        o.x += bn.x; o.y += bn.y; o.z += bn.z; o.w += bn.w;
    }
    size_t row = (size_t)(g_rowstart[b] + m);
    __nv_bfloat16 h0 = __float2bfloat16(o.x), h1 = __float2bfloat16(o.y);
    __nv_bfloat16 h2 = __float2bfloat16(o.z), h3 = __float2bfloat16(o.w);
    __nv_bfloat16 l0 = __float2bfloat16(o.x - __bfloat162float(h0));
    __nv_bfloat16 l1 = __float2bfloat16(o.y - __bfloat162float(h1));
    __nv_bfloat16 l2 = __float2bfloat16(o.z - __bfloat162float(h2));
    __nv_bfloat16 l3 = __float2bfloat16(o.w - __bfloat162float(h3));
    __nv_bfloat162 hA = __halves2bfloat162(h0, h1), hB = __halves2bfloat162(h2, h3);
    __nv_bfloat162 lA = __halves2bfloat162(l0, l1), lB = __halves2bfloat162(l2, l3);
    uint2 hv, lv;
    hv.x = *(uint32_t*)&hA; hv.y = *(uint32_t*)&hB;
    lv.x = *(uint32_t*)&lA; lv.y = *(uint32_t*)&lB;
    ((uint2*)(g_nodeH + row * NH))[t] = hv;
    ((uint2*)(g_nodeL + row * NH))[t] = lv;
}

// ============================================================================
// HMMA GEMM on COMPACTED rows, M-tile 64. CTA 64x128, K-tile 32, 3-stage
// cp.async, 24KB/stage (72KB -> 3 CTA/SM). 8 warps (2m x 4n), warp 32x32.
// Epilogue: sec0 tanh(+bnd) -> g_ND; sec1 +bed -> g_A; sec2 -> g_Bm.
// ============================================================================
#define TB_A 4096
#define TB_B 8192
#define STG_B 24576
#define GEMM_SMEM (3*STG_B)

__global__ __launch_bounds__(256, 3) void k_mmagemm(const float* __restrict__ bnd,
                                                    const float* __restrict__ bed) {
    const int m0 = blockIdx.y * 64, n0 = blockIdx.x * 128;
    if (m0 >= g_ract) return;
    extern __shared__ char smem[];
    uint32_t sb = smem_to_u32(smem);
    const int t = threadIdx.x;
    const int lane = t & 31, wid = t >> 5;
    const int wm = wid >> 2, wn = wid & 3;

    uint32_t rA = (uint32_t)t >> 2, cA = (uint32_t)t & 3;
    uint32_t oA = rA * 64 + cA * 16;
    uint32_t swoA = oA ^ ((oA >> 3) & 0x30);
    uint32_t gA = (uint32_t)(m0 + rA) * NH + cA * 8;
    uint32_t swoB[2], gB[2];
    #pragma unroll
    for (int j = 0; j < 2; j++) {
        int u = j * 256 + t;
        uint32_t rB = (uint32_t)u >> 2, cB = (uint32_t)u & 3;
        uint32_t o = rB * 64 + cB * 16;
        swoB[j] = o ^ ((o >> 3) & 0x30);
        gB[j] = (uint32_t)(n0 + rB) * NH + cB * 8;
    }

    auto issue = [&](int kc) {
        uint32_t kk = (uint32_t)kc * 32;
        uint32_t d = sb + (kc % 3) * STG_B;
        cp16(d + swoA,        g_nodeH + gA + kk);
        cp16(d + TB_A + swoA, g_nodeL + gA + kk);
        #pragma unroll
        for (int j = 0; j < 2; j++) {
            cp16(d + 2 * TB_A + swoB[j],        g_WTh + gB[j] + kk);
            cp16(d + 2 * TB_A + TB_B + swoB[j], g_WTl + gB[j] + kk);
        }
        CP_COMMIT();
    };

    float acc[2][4][4] = {};

    const uint32_t aRow = (uint32_t)(wm * 32 + (lane & 15));
    const uint32_t aKhalf = (uint32_t)((lane >> 4) * 16);
    const uint32_t bRowBase = (uint32_t)(wn * 32 + ((lane >> 4) & 1) * 8 + (lane & 7));
    const uint32_t bCol = (uint32_t)(((lane >> 3) & 1) * 16);

    issue(0);
    issue(1);

    for (int kc = 0; kc < 32; kc++) {
        if (kc == 31) { CP_WAIT0(); } else { CP_WAIT1(); }
        __syncthreads();
        if (kc + 2 < 32) issue(kc + 2);
        uint32_t base = sb + (kc % 3) * STG_B;

        #pragma unroll
        for (int ks = 0; ks < 2; ks++) {
            uint32_t bH[2][4], bL[2][4];
            #pragma unroll
            for (int p = 0; p < 2; p++) {
                uint32_t o = (bRowBase + p * 16) * 64 + ks * 32 + bCol;
                o ^= (o >> 3) & 0x30;
                ldsm_x4(bH[p], base + 2 * TB_A + o);
                ldsm_x4(bL[p], base + 2 * TB_A + TB_B + o);
            }
            #pragma unroll
            for (int mt = 0; mt < 2; mt++) {
                uint32_t aH[4], aL[4];
                uint32_t o = (aRow + mt * 16) * 64 + ks * 32 + aKhalf;
                o ^= (o >> 3) & 0x30;
                ldsm_x4(aH, base + o);
                ldsm_x4(aL, base + TB_A + o);
                #pragma unroll
                for (int nt = 0; nt < 4; nt++) {
                    int p = nt >> 1, q = (nt & 1) * 2;
                    mma16816(acc[mt][nt], aH, bH[p][q], bH[p][q + 1]);
                    mma16816(acc[mt][nt], aH, bL[p][q], bL[p][q + 1]);
                    mma16816(acc[mt][nt], aL, bH[p][q], bH[p][q + 1]);
                }
            }
        }
    }

    int sec  = n0 >> 10;
    int ncol = n0 & 1023;
    float* dst = (sec == 0) ? g_ND : ((sec == 1) ? g_A : g_Bm);
    int g = lane >> 2, tq = lane & 3;
    #pragma unroll
    for (int mt = 0; mt < 2; mt++) {
        int m = m0 + wm * 32 + mt * 16 + g;
        int r0 = g_rowmap[m];
        int r1 = g_rowmap[m + 8];
        #pragma unroll
        for (int nt = 0; nt < 4; nt++) {
            int n = ncol + wn * 32 + nt * 8 + tq * 2;
            float2 v0 = make_float2(acc[mt][nt][0], acc[mt][nt][1]);
            float2 v1 = make_float2(acc[mt][nt][2], acc[mt][nt][3]);
            if (sec == 0) {
                float b0 = bnd[n], b1 = bnd[n + 1];
                v0.x = tanhf(v0.x + b0); v0.y = tanhf(v0.y + b1);
                v1.x = tanhf(v1.x + b0); v1.y = tanhf(v1.y + b1);
            } else if (sec == 1) {
                float b0 = bed[n], b1 = bed[n + 1];
                v0.x += b0; v0.y += b1;
                v1.x += b0; v1.y += b1;
            }
            if (r0 >= 0) *(float2*)(dst + (size_t)r0 * NH + n) = v0;
            if (r1 >= 0) *(float2*)(dst + (size_t)r1 * NH + n) = v1;
        }
    }
}

// ---------------- kernel: edges + node logits + cls logits (merged) ----------------
__global__ __launch_bounds__(256) void k_final(const float* __restrict__ Weo,
                                               const float* __restrict__ beo,
                                               const float* __restrict__ Wno,
                                               const float* __restrict__ bno,
                                               const float* __restrict__ Wco,
                                               const float* __restrict__ bco,
                                               float* __restrict__ out) {
    int blk = blockIdx.x, t = threadIdx.x;
    int warp = t >> 5, lane = t & 31;
    if (blk < 85 * NB) {
        // ---- edge logits, warp per edge; bed pre-folded into g_A ----
        int b = blk / 85, kb = blk % 85;
        int n = g_count[b] + 1;
        int nn = n * n;
        int kbase = kb * 8;
        if (kbase >= nn) {
            // whole block invalid: constants only, no smem staging
            int k = kbase + warp;
            if (k < NE && lane < 2)
                out[128 + NR * 2 + (size_t)(b * NE + k) * 2 + lane] = g_cvec[lane];
            return;
        }
        __shared__ __align__(16) float sw0[NH];
        __shared__ __align__(16) float sw1[NH];
        for (int h = t; h < NH; h += 256) {
            float2 ww = ((const float2*)Weo)[h];
            sw0[h] = ww.x; sw1[h] = ww.y;
        }
        __syncthreads();
        int k = kbase + warp;
        if (k >= NE) return;
        float* o = out + 128 + NR * 2 + (size_t)(b * NE + k) * 2;
        if (k >= nn) {
            if (lane < 2) o[lane] = g_cvec[lane];
            return;
        }
        int i = k / n, j = k % n;
        const float4* Ar = (const float4*)(g_A  + (size_t)(b * NM + j) * NH);
        const float4* Br = (const float4*)(g_Bm + (size_t)(b * NM + i) * NH);
        const float4* w04 = (const float4*)sw0;
        const float4* w14 = (const float4*)sw1;
        float s0 = 0.f, s1 = 0.f;
        #pragma unroll
        for (int it = 0; it < 8; it++) {
            int h4 = it * 32 + lane;
            float4 a  = Ar[h4];
            float4 bb = Br[h4];
            float4 w0 = w04[h4];
            float4 w1 = w14[h4];
            float v0 = fast_tanh(a.x + bb.x);
            float v1 = fast_tanh(a.y + bb.y);
            float v2 = fast_tanh(a.z + bb.z);
            float v3 = fast_tanh(a.w + bb.w);
            s0 += v0 * w0.x + v1 * w0.y + v2 * w0.z + v3 * w0.w;
            s1 += v0 * w1.x + v1 * w1.y + v2 * w1.z + v3 * w1.w;
        }
        #pragma unroll
        for (int off = 16; off > 0; off >>= 1) {
            s0 += __shfl_down_sync(0xffffffffu, s0, off);
            s1 += __shfl_down_sync(0xffffffffu, s1, off);
        }
        if (lane == 0) { o[0] = s0 + beo[0]; o[1] = s1 + beo[1]; }
    } else {
        // ---- node + cls logits, warp per row ----
        int ablk = blk - 85 * NB;           // 0..215
        const float4* X;
        const float4* W4;
        float add0, add1;
        float* o;
        if (ablk < 208) {
            int r = ablk * 8 + warp;
            int b = r / NM, m = r - b * NM;
            o = out + 128 + (size_t)r * 2;
            if (m > g_count[b]) {
                if (lane < 2) o[lane] = g_nlc[lane];
                return;
            }
            X = (const float4*)(g_ND + (size_t)r * NH);
            W4 = (const float4*)Wno;
            add0 = bno[0]; add1 = bno[1];
        } else {
            int b = (ablk - 208) * 8 + warp;
            o = out + (size_t)b * 2;
            X = (const float4*)(g_cdact + (size_t)b * NH);
            W4 = (const float4*)Wco;
            add0 = bco[0]; add1 = bco[1];
        }
        float s0 = 0.f, s1 = 0.f;
        #pragma unroll
        for (int it = 0; it < 8; it++) {
            int h4 = it * 32 + lane;
            float4 x  = X[h4];
            float4 wa = W4[h4 * 2];
            float4 wb = W4[h4 * 2 + 1];
            s0 += x.x * wa.x + x.y * wa.z + x.z * wb.x + x.w * wb.z;
            s1 += x.x * wa.y + x.y * wa.w + x.z * wb.y + x.w * wb.w;
        }
        #pragma unroll
        for (int off = 16; off > 0; off >>= 1) {
            s0 += __shfl_down_sync(0xffffffffu, s0, off);
            s1 += __shfl_down_sync(0xffffffffu, s1, off);
        }
        if (lane == 0) { o[0] = s0 + add0; o[1] = s1 + add1; }
    }
}

// ---------------- launch: multi-stream fork/join (graph-capture legal) -------------
extern "C" void kernel_launch(void* const* d_in, const int* in_sizes, int n_in,
                              void* d_out, int out_size) {
    const float* seq  = (const float*)d_in[0];
    const int*   po   = (const int*)  d_in[1];
    const float* Wnaf = (const float*)d_in[4];
    const float* bnaf = (const float*)d_in[5];
    const float* Wcd  = (const float*)d_in[6];
    const float* bcd  = (const float*)d_in[7];
    const float* Wco  = (const float*)d_in[8];
    const float* bco  = (const float*)d_in[9];
    const float* Wnd  = (const float*)d_in[10];
    const float* bnd  = (const float*)d_in[11];
    const float* Wno  = (const float*)d_in[12];
    const float* bno  = (const float*)d_in[13];
    const float* Wed  = (const float*)d_in[14];
    const float* bed  = (const float*)d_in[15];
    const float* Weo  = (const float*)d_in[16];
    const float* beo  = (const float*)d_in[17];
    float* out = (float*)d_out;

    static cudaStream_t s1 = nullptr, s2 = nullptr;
    static cudaEvent_t ev0, ev1, ev2, evR;
    if (!s1) {
        cudaFuncSetAttribute(k_mmagemm, cudaFuncAttributeMaxDynamicSharedMemorySize, GEMM_SMEM);
        cudaStreamCreateWithFlags(&s1, cudaStreamNonBlocking);
        cudaStreamCreateWithFlags(&s2, cudaStreamNonBlocking);
        cudaEventCreateWithFlags(&ev0, cudaEventDisableTiming);
        cudaEventCreateWithFlags(&ev1, cudaEventDisableTiming);
        cudaEventCreateWithFlags(&ev2, cudaEventDisableTiming);
        cudaEventCreateWithFlags(&evR, cudaEventDisableTiming);
    }

    // 1: root (offsets/counts/cls/consts/prefix)
    k_prep0<<<NB + 3, 256>>>(seq, po, bed, Weo, beo, bnd, Wno, bno);
    cudaEventRecord(ev0, 0);

    // 2 (s1): gemm1p
    cudaStreamWaitEvent(s1, ev0, 0);
    k_gemm1p<<<dim3(32, KSPLIT), 256, 0, s1>>>(Wnaf, Wcd);
    cudaEventRecord(ev1, s1);

    // 3 (s2): weight prep
    cudaStreamWaitEvent(s2, ev0, 0);
    k_prep_weights<<<dim3(96, 32), dim3(32, 8), 0, s2>>>(Wnd, Wed);
    cudaEventRecord(ev2, s2);

    // 4 (legacy): segment sums  <- profiled slot
    k_segsum<<<dim3(NST, NB, 4), 64>>>(seq);

    // 5 (s1): cdact reduce, off critical path
    k_gemm1r_cd<<<256, 256, 0, s1>>>(bcd);
    cudaEventRecord(evR, s1);

    // 6 (legacy): finalize (needs segsum + gemm1p partials)
    cudaStreamWaitEvent(0, ev1, 0);
    k_finalize<<<dim3(NM, NB), 256>>>(bnaf);

    // 7 (legacy): tensor GEMM (needs weights too)
    cudaStreamWaitEvent(0, ev2, 0);
    k_mmagemm<<<dim3(24, 26), 256, GEMM_SMEM>>>(bnd, bed);

    // 8 (legacy): fused epilogue (edges + node/cls logits; needs cdact)
    cudaStreamWaitEvent(0, evR, 0);
    k_final<<<85 * NB + 216, 256>>>(Weo, beo, Wno, bno, Wco, bco, out);
}

// round 12
// speedup vs baseline: 4.3634x; 1.0528x over previous
#include <cuda_runtime.h>
#include <cuda_bf16.h>
#include <math.h>
#include <stdint.h>

#define NB 64
#define NS 512
#define NH 1024
#define NM 26
#define NE 676
#define NR (NB*NM)          // 1664 node rows total
#define NOFF (NM-1)         // 25 offsets per batch
#define NST 16              // S tiles of 32 rows
#define KSPLIT 16           // gemm1 K splits

// ---------------- scratch (device globals; no allocation allowed) ----------------
__device__ int   g_off[NB*NOFF];
__device__ int   g_count[NB];
__device__ int   g_rowstart[NB];
__device__ int   g_rowmap[NR];
__device__ int   g_ract;
__device__ __align__(16) float g_cls[NB*NH];
__device__ __align__(16) float g_cdact[NB*NH];
__device__ __align__(16) float g_g1p[KSPLIT*NB*2048];  // gemm1 split-K partials
__device__ __align__(16) float g_part[NB*NST*NM*NH];   // segment tile partials
__device__ __align__(16) float g_ND[NR*NH];            // tanh(node_full @ W_nd + b_nd)
__device__ __align__(16) float g_A[NR*NH];             // node_full @ (W1+W3) + b_ed
__device__ __align__(16) float g_Bm[NR*NH];            // node_full @ (W2-W3)
__device__ float g_cvec[2];   // edge logits of all-zero edge row
__device__ float g_nlc[2];    // node logits of all-zero node row
// bf16 split operands for tensor-core GEMM (COMPACTED rows)
__device__ __align__(16) __nv_bfloat16 g_nodeH[NR*NH];
__device__ __align__(16) __nv_bfloat16 g_nodeL[NR*NH];
__device__ __align__(16) __nv_bfloat16 g_WTh[3072*NH];  // W^T (N-major, K cols), hi
__device__ __align__(16) __nv_bfloat16 g_WTl[3072*NH];  // lo

// ============================================================================
// portable PTX helpers (no sm_103a-only features)
// ============================================================================
__device__ __forceinline__ uint32_t smem_to_u32(const void* p) {
    uint32_t a;
    asm("{ .reg .u64 t; cvta.to.shared.u64 t, %1; cvt.u32.u64 %0, t; }" : "=r"(a) : "l"(p));
    return a;
}
__device__ __forceinline__ void ldsm_x4(uint32_t (&r)[4], uint32_t addr) {
    asm volatile("ldmatrix.sync.aligned.m8n8.x4.shared.b16 {%0,%1,%2,%3}, [%4];"
        : "=r"(r[0]), "=r"(r[1]), "=r"(r[2]), "=r"(r[3]) : "r"(addr));
}
__device__ __forceinline__ void mma16816(float (&c)[4], const uint32_t (&a)[4],
                                         uint32_t b0, uint32_t b1) {
    asm volatile("mma.sync.aligned.m16n8k16.row.col.f32.bf16.bf16.f32 "
        "{%0,%1,%2,%3}, {%4,%5,%6,%7}, {%8,%9}, {%0,%1,%2,%3};"
        : "+f"(c[0]), "+f"(c[1]), "+f"(c[2]), "+f"(c[3])
        : "r"(a[0]), "r"(a[1]), "r"(a[2]), "r"(a[3]), "r"(b0), "r"(b1));
}
__device__ __forceinline__ void cp16(uint32_t dst, const void* src) {
    asm volatile("cp.async.cg.shared.global [%0], [%1], 16;" :: "r"(dst), "l"(src));
}
#define CP_COMMIT() asm volatile("cp.async.commit_group;" ::: "memory")
#define CP_WAIT1()  asm volatile("cp.async.wait_group 1;" ::: "memory")
#define CP_WAIT0()  asm volatile("cp.async.wait_group 0;" ::: "memory")

__device__ __forceinline__ float fast_tanh(float x) {
    float y;
    asm("tanh.approx.f32 %0, %1;" : "=f"(y) : "f"(x));
    return y;
}

// ---------------- small helpers ----------------
__device__ __forceinline__ void block_reduce2_store(float s0, float s1,
                                                    float* o0, float* o1,
                                                    float add0, float add1) {
    __shared__ float red[16];
    #pragma unroll
    for (int o = 16; o > 0; o >>= 1) {
        s0 += __shfl_down_sync(0xffffffffu, s0, o);
        s1 += __shfl_down_sync(0xffffffffu, s1, o);
    }
    int t = threadIdx.x;
    if ((t & 31) == 0) { red[t >> 5] = s0; red[8 + (t >> 5)] = s1; }
    __syncthreads();
    if (t == 0) {
        float a = 0.f, b = 0.f;
        #pragma unroll
        for (int w = 0; w < 8; w++) { a += red[w]; b += red[8 + w]; }
        *o0 = a + add0;
        *o1 = b + add1;
    }
}

// ---------------- kernel: prep_cls (0-63) + consts (64-65) + prefix (66) ----------
__global__ void k_prep0(const float* __restrict__ seq, const int* __restrict__ po,
                        const float* __restrict__ bed, const float* __restrict__ Weo,
                        const float* __restrict__ beo, const float* __restrict__ bnd,
                        const float* __restrict__ Wno, const float* __restrict__ bno) {
    int blk = blockIdx.x, t = threadIdx.x;
    if (blk < NB) {
        int b = blk;
        bool wide = (po[1] == 0 && po[3] == 0);
        int val = 0;
        if (t < NOFF) {
            val = wide ? po[(b * NOFF + t) * 2] : po[b * NOFF + t];
            g_off[b * NOFF + t] = val;
        }
        if (t < 32) {
            unsigned mask = __ballot_sync(0xffffffffu, (t < NOFF) && (val > 0));
            if (t == 0) g_count[b] = __popc(mask);
        }
        ((float4*)(g_cls + (size_t)b * NH))[t] =
            ((const float4*)(seq + (size_t)b * NS * NH))[t];
    } else if (blk < NB + 2) {
        int which = blk - NB;               // 0: edge const, 1: node const
        const float*  bias = which ? bnd : bed;
        const float2* w    = which ? (const float2*)Wno : (const float2*)Weo;
        const float*  b2   = which ? bno : beo;
        float* dstp        = which ? g_nlc : g_cvec;
        float s0 = 0.f, s1 = 0.f;
        for (int h = t; h < NH; h += 256) {
            float v = tanhf(bias[h]);
            float2 ww = w[h];
            s0 += v * ww.x; s1 += v * ww.y;
        }
        block_reduce2_store(s0, s1, &dstp[0], &dstp[1], b2[0], b2[1]);
    } else {
        // prefix + rowmap: recompute counts straight from po (no inter-block dep)
        __shared__ int scnt[NB];
        __shared__ int sstart[NB];
        bool wide = (po[1] == 0 && po[3] == 0);
        if (t < NB) {
            int c = 0;
            #pragma unroll
            for (int m = 0; m < NOFF; m++) {
                int v = wide ? po[(t * NOFF + m) * 2] : po[t * NOFF + m];
                c += (v > 0);
            }
            scnt[t] = c;
        }
        __syncthreads();
        if (t == 0) {
            int acc = 0;
            for (int b = 0; b < NB; b++) {
                sstart[b] = acc;
                g_rowstart[b] = acc;
                acc += scnt[b] + 1;
            }
            g_ract = acc;
        }
        __syncthreads();
        for (int i = t; i < NR; i += 256) g_rowmap[i] = -1;
        __syncthreads();
        for (int i = t; i < NB * NM; i += 256) {
            int b = i / NM, m = i - b * NM;
            if (m <= scnt[b]) g_rowmap[sstart[b] + m] = i;
        }
    }
}

// ---------------- kernel: segment partial sums over 32-row S tiles ----------------
__global__ void k_segsum(const float* __restrict__ seq) {
    int st = blockIdx.x;          // 0..15
    int b  = blockIdx.y;          // 0..63
    int hc = blockIdx.z;          // 0..3
    int t  = threadIdx.x;         // 0..63
    int s0 = st * 32;
    int sEnd = s0 + 31;
    int cnt = g_count[b];
    if (s0 > g_off[b * NOFF + cnt - 1]) return;   // past the last segment: no work
    const float4* base = (const float4*)(seq + (size_t)b * NS * NH + hc * 256) + t;
    int prev = 0;
    for (int m = 0; m < cnt; m++) {
        int off = g_off[b * NOFF + m];
        int lo = prev + 1;
        if (lo < s0) lo = s0;
        int hi = off < sEnd ? off : sEnd;
        if (lo <= hi) {
            float4 a0 = make_float4(0.f,0.f,0.f,0.f), a1 = a0, a2 = a0, a3 = a0;
            int s = lo;
            for (; s + 3 <= hi; s += 4) {
                float4 v0 = base[(size_t)(s + 0) * 256];
                float4 v1 = base[(size_t)(s + 1) * 256];
                float4 v2 = base[(size_t)(s + 2) * 256];
                float4 v3 = base[(size_t)(s + 3) * 256];
                a0.x += v0.x; a0.y += v0.y; a0.z += v0.z; a0.w += v0.w;
                a1.x += v1.x; a1.y += v1.y; a1.z += v1.z; a1.w += v1.w;
                a2.x += v2.x; a2.y += v2.y; a2.z += v2.z; a2.w += v2.w;
                a3.x += v3.x; a3.y += v3.y; a3.z += v3.z; a3.w += v3.w;
            }
            for (; s <= hi; s++) {
                float4 v = base[(size_t)s * 256];
                a0.x += v.x; a0.y += v.y; a0.z += v.z; a0.w += v.w;
            }
            a0.x += a1.x + a2.x + a3.x;
            a0.y += a1.y + a2.y + a3.y;
            a0.z += a1.z + a2.z + a3.z;
            a0.w += a1.w + a2.w + a3.w;
            ((float4*)(g_part + (((size_t)(b * NST + st) * NM) + m) * NH + hc * 256))[t] = a0;
        }
        prev = off;
        if (prev >= sEnd) break;
    }
}

// ---------------- kernel: GEMM1 split-K partial ----------
__global__ __launch_bounds__(256) void k_gemm1p(const float* __restrict__ Wnaf,
                                                const float* __restrict__ Wcd) {
    __shared__ float Xs[64 * 68];      // [k][m], pad 4
    __shared__ float Ws[64 * 64];      // [k][n]
    int n0 = blockIdx.x * 64;                 // 0..2047
    int ks0 = blockIdx.y * 64;                // K chunk start
    const float* W = (n0 < 1024) ? Wnaf : Wcd;
    int nc0 = (n0 < 1024) ? n0 : n0 - 1024;
    int t = threadIdx.x;
    #pragma unroll
    for (int r = 0; r < 4; r++) {
        int f4 = t + r * 256;
        int row = f4 >> 4, q = f4 & 15;
        float4 x = *(const float4*)(g_cls + (size_t)row * NH + ks0 + q * 4);
        Xs[(q * 4 + 0) * 68 + row] = x.x;
        Xs[(q * 4 + 1) * 68 + row] = x.y;
        Xs[(q * 4 + 2) * 68 + row] = x.z;
        Xs[(q * 4 + 3) * 68 + row] = x.w;
        float4 w = *(const float4*)(W + (size_t)(ks0 + row) * 1024 + nc0 + q * 4);
        *(float4*)(Ws + row * 64 + q * 4) = w;
    }
    __syncthreads();
    int tx = t & 15, ty = t >> 4;
    float acc[4][4] = {};
    #pragma unroll 16
    for (int k = 0; k < 64; k++) {
        float a[4], bb[4];
        *(float4*)a  = *(const float4*)(Xs + k * 68 + ty * 4);
        *(float4*)bb = *(const float4*)(Ws + k * 64 + tx * 4);
        #pragma unroll
        for (int i = 0; i < 4; i++)
            #pragma unroll
            for (int j = 0; j < 4; j++)
                acc[i][j] += a[i] * bb[j];
    }
    float* dst = g_g1p + (size_t)blockIdx.y * NB * 2048;
    #pragma unroll
    for (int i = 0; i < 4; i++) {
        int m = ty * 4 + i;
        #pragma unroll
        for (int j = 0; j < 4; j++)
            dst[(size_t)m * 2048 + n0 + tx * 4 + j] = acc[i][j];
    }
}

// ---------------- kernel: GEMM1 reduce, cdact half only (off critical path) --------
__global__ void k_gemm1r_cd(const float* __restrict__ bcd) {
    int idx = blockIdx.x * 256 + threadIdx.x;   // 0 .. 64*1024-1
    int m = idx >> 10, c = idx & 1023;
    float s = 0.f;
    #pragma unroll
    for (int ks = 0; ks < KSPLIT; ks++)
        s += g_g1p[(size_t)ks * NB * 2048 + m * 2048 + 1024 + c];
    g_cdact[(size_t)m * NH + c] = tanhf(s + bcd[c]);
}

// ---------------- kernel: W^T build + bf16 split ----------------
__global__ void k_prep_weights(const float* __restrict__ Wnd,
                               const float* __restrict__ Wed) {
    __shared__ float tile[32][33];
    int n0 = blockIdx.x * 32;
    int k0 = blockIdx.y * 32;
    int tx = threadIdx.x, ty = threadIdx.y;
    #pragma unroll
    for (int kk = 0; kk < 32; kk += 8) {
        int k = k0 + kk + ty;
        int n = n0 + tx;
        float v;
        if (n < 1024) v = Wnd[(size_t)k * 1024 + n];
        else if (n < 2048) { int c = n - 1024; v = Wed[(size_t)k * 1024 + c] + Wed[(size_t)(2048 + k) * 1024 + c]; }
        else { int c = n - 2048; v = Wed[(size_t)(1024 + k) * 1024 + c] - Wed[(size_t)(2048 + k) * 1024 + c]; }
        tile[kk + ty][tx] = v;
    }
    __syncthreads();
    #pragma unroll
    for (int kk = 0; kk < 32; kk += 8) {
        int n = n0 + kk + ty;
        int k = k0 + tx;
        float v = tile[tx][kk + ty];
        __nv_bfloat16 h = __float2bfloat16(v);
        g_WTh[(size_t)n * NH + k] = h;
        g_WTl[(size_t)n * NH + k] = __float2bfloat16(v - __bfloat162float(h));
    }
}

// ---------------- kernel: finalize node rows (naf reduced inline), bf16 split ------
__global__ void k_finalize(const float* __restrict__ bnaf) {
    int m = blockIdx.x, b = blockIdx.y, t = threadIdx.x;
    int cnt = g_count[b];
    if (m > cnt) return;
    float4 o = make_float4(0.f, 0.f, 0.f, 0.f);
    if (m < cnt) {
        int off  = g_off[b * NOFF + m];
        int prev = (m == 0) ? 0 : g_off[b * NOFF + m - 1];
        int stLo = (prev + 1) >> 5, stHi = off >> 5;
        for (int st = stLo; st <= stHi; st++) {
            float4 p = ((const float4*)(g_part + (((size_t)(b * NST + st) * NM) + m) * NH))[t];
            o.x += p.x; o.y += p.y; o.z += p.z; o.w += p.w;
        }
        float sc = 1.f / (float)(off - prev);
        o.x *= sc; o.y *= sc; o.z *= sc; o.w *= sc;
    } else {
        // naf row: reduce gemm1 split-K partials directly (cols 0..1023)
        #pragma unroll
        for (int ks = 0; ks < KSPLIT; ks++) {
            float4 p = *(const float4*)(g_g1p + (size_t)ks * NB * 2048 + b * 2048 + t * 4);
            o.x += p.x; o.y += p.y; o.z += p.z; o.w += p.w;
        }
        float4 bn = *(const float4*)(bnaf + t * 4);
        o.x += bn.x; o.y += bn.y; o.z += bn.z; o.w += bn.w;
    }
    size_t row = (size_t)(g_rowstart[b] + m);
    __nv_bfloat16 h0 = __float2bfloat16(o.x), h1 = __float2bfloat16(o.y);
    __nv_bfloat16 h2 = __float2bfloat16(o.z), h3 = __float2bfloat16(o.w);
    __nv_bfloat16 l0 = __float2bfloat16(o.x - __bfloat162float(h0));
    __nv_bfloat16 l1 = __float2bfloat16(o.y - __bfloat162float(h1));
    __nv_bfloat16 l2 = __float2bfloat16(o.z - __bfloat162float(h2));
    __nv_bfloat16 l3 = __float2bfloat16(o.w - __bfloat162float(h3));
    __nv_bfloat162 hA = __halves2bfloat162(h0, h1), hB = __halves2bfloat162(h2, h3);
    __nv_bfloat162 lA = __halves2bfloat162(l0, l1), lB = __halves2bfloat162(l2, l3);
    uint2 hv, lv;
    hv.x = *(uint32_t*)&hA; hv.y = *(uint32_t*)&hB;
    lv.x = *(uint32_t*)&lA; lv.y = *(uint32_t*)&lB;
    ((uint2*)(g_nodeH + row * NH))[t] = hv;
    ((uint2*)(g_nodeL + row * NH))[t] = lv;
}

// ============================================================================
// HMMA GEMM on COMPACTED rows, M-tile 64. CTA 64x128, K-tile 32, 3-stage
// cp.async, 24KB/stage (72KB -> 3 CTA/SM). 8 warps (2m x 4n), warp 32x32.
// nxoff selects the n-tile window: 0..7 = ND section, 8..23 = A/B sections.
// ============================================================================
#define TB_A 4096
#define TB_B 8192
#define STG_B 24576
#define GEMM_SMEM (3*STG_B)

__global__ __launch_bounds__(256, 3) void k_mmagemm(const float* __restrict__ bnd,
                                                    const float* __restrict__ bed,
                                                    int nxoff) {
    const int m0 = blockIdx.y * 64, n0 = (blockIdx.x + nxoff) * 128;
    if (m0 >= g_ract) return;
    extern __shared__ char smem[];
    uint32_t sb = smem_to_u32(smem);
    const int t = threadIdx.x;
    const int lane = t & 31, wid = t >> 5;
    const int wm = wid >> 2, wn = wid & 3;

    uint32_t rA = (uint32_t)t >> 2, cA = (uint32_t)t & 3;
    uint32_t oA = rA * 64 + cA * 16;
    uint32_t swoA = oA ^ ((oA >> 3) & 0x30);
    uint32_t gA = (uint32_t)(m0 + rA) * NH + cA * 8;
    uint32_t swoB[2], gB[2];
    #pragma unroll
    for (int j = 0; j < 2; j++) {
        int u = j * 256 + t;
        uint32_t rB = (uint32_t)u >> 2, cB = (uint32_t)u & 3;
        uint32_t o = rB * 64 + cB * 16;
        swoB[j] = o ^ ((o >> 3) & 0x30);
        gB[j] = (uint32_t)(n0 + rB) * NH + cB * 8;
    }

    auto issue = [&](int kc) {
        uint32_t kk = (uint32_t)kc * 32;
        uint32_t d = sb + (kc % 3) * STG_B;
        cp16(d + swoA,        g_nodeH + gA + kk);
        cp16(d + TB_A + swoA, g_nodeL + gA + kk);
        #pragma unroll
        for (int j = 0; j < 2; j++) {
            cp16(d + 2 * TB_A + swoB[j],        g_WTh + gB[j] + kk);
            cp16(d + 2 * TB_A + TB_B + swoB[j], g_WTl + gB[j] + kk);
        }
        CP_COMMIT();
    };

    float acc[2][4][4] = {};

    const uint32_t aRow = (uint32_t)(wm * 32 + (lane & 15));
    const uint32_t aKhalf = (uint32_t)((lane >> 4) * 16);
    const uint32_t bRowBase = (uint32_t)(wn * 32 + ((lane >> 4) & 1) * 8 + (lane & 7));
    const uint32_t bCol = (uint32_t)(((lane >> 3) & 1) * 16);

    issue(0);
    issue(1);

    for (int kc = 0; kc < 32; kc++) {
        if (kc == 31) { CP_WAIT0(); } else { CP_WAIT1(); }
        __syncthreads();
        if (kc + 2 < 32) issue(kc + 2);
        uint32_t base = sb + (kc % 3) * STG_B;

        #pragma unroll
        for (int ks = 0; ks < 2; ks++) {
            uint32_t bH[2][4], bL[2][4];
            #pragma unroll
            for (int p = 0; p < 2; p++) {
                uint32_t o = (bRowBase + p * 16) * 64 + ks * 32 + bCol;
                o ^= (o >> 3) & 0x30;
                ldsm_x4(bH[p], base + 2 * TB_A + o);
                ldsm_x4(bL[p], base + 2 * TB_A + TB_B + o);
            }
            #pragma unroll
            for (int mt = 0; mt < 2; mt++) {
                uint32_t aH[4], aL[4];
                uint32_t o = (aRow + mt * 16) * 64 + ks * 32 + aKhalf;
                o ^= (o >> 3) & 0x30;
                ldsm_x4(aH, base + o);
                ldsm_x4(aL, base + TB_A + o);
                #pragma unroll
                for (int nt = 0; nt < 4; nt++) {
                    int p = nt >> 1, q = (nt & 1) * 2;
                    mma16816(acc[mt][nt], aH, bH[p][q], bH[p][q + 1]);
                    mma16816(acc[mt][nt], aH, bL[p][q], bL[p][q + 1]);
                    mma16816(acc[mt][nt], aL, bH[p][q], bH[p][q + 1]);
                }
            }
        }
    }

    int sec  = n0 >> 10;
    int ncol = n0 & 1023;
    float* dst = (sec == 0) ? g_ND : ((sec == 1) ? g_A : g_Bm);
    int g = lane >> 2, tq = lane & 3;
    #pragma unroll
    for (int mt = 0; mt < 2; mt++) {
        int m = m0 + wm * 32 + mt * 16 + g;
        int r0 = g_rowmap[m];
        int r1 = g_rowmap[m + 8];
        #pragma unroll
        for (int nt = 0; nt < 4; nt++) {
            int n = ncol + wn * 32 + nt * 8 + tq * 2;
            float2 v0 = make_float2(acc[mt][nt][0], acc[mt][nt][1]);
            float2 v1 = make_float2(acc[mt][nt][2], acc[mt][nt][3]);
            if (sec == 0) {
                float b0 = bnd[n], b1 = bnd[n + 1];
                v0.x = tanhf(v0.x + b0); v0.y = tanhf(v0.y + b1);
                v1.x = tanhf(v1.x + b0); v1.y = tanhf(v1.y + b1);
            } else if (sec == 1) {
                float b0 = bed[n], b1 = bed[n + 1];
                v0.x += b0; v0.y += b1;
                v1.x += b0; v1.y += b1;
            }
            if (r0 >= 0) *(float2*)(dst + (size_t)r0 * NH + n) = v0;
            if (r1 >= 0) *(float2*)(dst + (size_t)r1 * NH + n) = v1;
        }
    }
}

// ---------------- kernel: edge logits (warp per edge; bed folded into g_A) --------
__global__ __launch_bounds__(256) void k_edges(const float* __restrict__ Weo,
                                               const float* __restrict__ beo,
                                               float* __restrict__ out) {
    int blk = blockIdx.x, t = threadIdx.x;
    int warp = t >> 5, lane = t & 31;
    int b = blk / 85, kb = blk % 85;
    int n = g_count[b] + 1;
    int nn = n * n;
    int kbase = kb * 8;
    if (kbase >= nn) {
        int k = kbase + warp;
        if (k < NE && lane < 2)
            out[128 + NR * 2 + (size_t)(b * NE + k) * 2 + lane] = g_cvec[lane];
        return;
    }
    __shared__ __align__(16) float sw0[NH];
    __shared__ __align__(16) float sw1[NH];
    for (int h = t; h < NH; h += 256) {
        float2 ww = ((const float2*)Weo)[h];
        sw0[h] = ww.x; sw1[h] = ww.y;
    }
    __syncthreads();
    int k = kbase + warp;
    if (k >= NE) return;
    float* o = out + 128 + NR * 2 + (size_t)(b * NE + k) * 2;
    if (k >= nn) {
        if (lane < 2) o[lane] = g_cvec[lane];
        return;
    }
    int i = k / n, j = k % n;
    const float4* Ar = (const float4*)(g_A  + (size_t)(b * NM + j) * NH);
    const float4* Br = (const float4*)(g_Bm + (size_t)(b * NM + i) * NH);
    const float4* w04 = (const float4*)sw0;
    const float4* w14 = (const float4*)sw1;
    float s0 = 0.f, s1 = 0.f;
    #pragma unroll
    for (int it = 0; it < 8; it++) {
        int h4 = it * 32 + lane;
        float4 a  = Ar[h4];
        float4 bb = Br[h4];
        float4 w0 = w04[h4];
        float4 w1 = w14[h4];
        float v0 = fast_tanh(a.x + bb.x);
        float v1 = fast_tanh(a.y + bb.y);
        float v2 = fast_tanh(a.z + bb.z);
        float v3 = fast_tanh(a.w + bb.w);
        s0 += v0 * w0.x + v1 * w0.y + v2 * w0.z + v3 * w0.w;
        s1 += v0 * w1.x + v1 * w1.y + v2 * w1.z + v3 * w1.w;
    }
    #pragma unroll
    for (int off = 16; off > 0; off >>= 1) {
        s0 += __shfl_down_sync(0xffffffffu, s0, off);
        s1 += __shfl_down_sync(0xffffffffu, s1, off);
    }
    if (lane == 0) { o[0] = s0 + beo[0]; o[1] = s1 + beo[1]; }
}

// ---------------- kernel: node logits + cls logits (warp per row) ------------------
__global__ __launch_bounds__(256) void k_nodelogits(const float* __restrict__ Wno,
                                                    const float* __restrict__ bno,
                                                    const float* __restrict__ Wco,
                                                    const float* __restrict__ bco,
                                                    float* __restrict__ out) {
    int blk = blockIdx.x, t = threadIdx.x;
    int warp = t >> 5, lane = t & 31;
    const float4* X;
    const float4* W4;
    float add0, add1;
    float* o;
    if (blk < 208) {
        int r = blk * 8 + warp;
        int b = r / NM, m = r - b * NM;
        o = out + 128 + (size_t)r * 2;
        if (m > g_count[b]) {
            if (lane < 2) o[lane] = g_nlc[lane];
            return;
        }
        X = (const float4*)(g_ND + (size_t)r * NH);
        W4 = (const float4*)Wno;
        add0 = bno[0]; add1 = bno[1];
    } else {
        int b = (blk - 208) * 8 + warp;
        o = out + (size_t)b * 2;
        X = (const float4*)(g_cdact + (size_t)b * NH);
        W4 = (const float4*)Wco;
        add0 = bco[0]; add1 = bco[1];
    }
    float s0 = 0.f, s1 = 0.f;
    #pragma unroll
    for (int it = 0; it < 8; it++) {
        int h4 = it * 32 + lane;
        float4 x  = X[h4];
        float4 wa = W4[h4 * 2];
        float4 wb = W4[h4 * 2 + 1];
        s0 += x.x * wa.x + x.y * wa.z + x.z * wb.x + x.w * wb.z;
        s1 += x.x * wa.y + x.y * wa.w + x.z * wb.y + x.w * wb.w;
    }
    #pragma unroll
    for (int off = 16; off > 0; off >>= 1) {
        s0 += __shfl_down_sync(0xffffffffu, s0, off);
        s1 += __shfl_down_sync(0xffffffffu, s1, off);
    }
    if (lane == 0) { o[0] = s0 + add0; o[1] = s1 + add1; }
}

// ---------------- launch: multi-stream fork/join (graph-capture legal) -------------
extern "C" void kernel_launch(void* const* d_in, const int* in_sizes, int n_in,
                              void* d_out, int out_size) {
    const float* seq  = (const float*)d_in[0];
    const int*   po   = (const int*)  d_in[1];
    const float* Wnaf = (const float*)d_in[4];
    const float* bnaf = (const float*)d_in[5];
    const float* Wcd  = (const float*)d_in[6];
    const float* bcd  = (const float*)d_in[7];
    const float* Wco  = (const float*)d_in[8];
    const float* bco  = (const float*)d_in[9];
    const float* Wnd  = (const float*)d_in[10];
    const float* bnd  = (const float*)d_in[11];
    const float* Wno  = (const float*)d_in[12];
    const float* bno  = (const float*)d_in[13];
    const float* Wed  = (const float*)d_in[14];
    const float* bed  = (const float*)d_in[15];
    const float* Weo  = (const float*)d_in[16];
    const float* beo  = (const float*)d_in[17];
    float* out = (float*)d_out;

    static cudaStream_t s1 = nullptr, s2 = nullptr;
    static cudaEvent_t ev0, ev1, ev2, evR, evF, evN;
    if (!s1) {
        cudaFuncSetAttribute(k_mmagemm, cudaFuncAttributeMaxDynamicSharedMemorySize, GEMM_SMEM);
        cudaStreamCreateWithFlags(&s1, cudaStreamNonBlocking);
        cudaStreamCreateWithFlags(&s2, cudaStreamNonBlocking);
        cudaEventCreateWithFlags(&ev0, cudaEventDisableTiming);
        cudaEventCreateWithFlags(&ev1, cudaEventDisableTiming);
        cudaEventCreateWithFlags(&ev2, cudaEventDisableTiming);
        cudaEventCreateWithFlags(&evR, cudaEventDisableTiming);
        cudaEventCreateWithFlags(&evF, cudaEventDisableTiming);
        cudaEventCreateWithFlags(&evN, cudaEventDisableTiming);
    }

    // 1: root (offsets/counts/cls/consts/prefix)
    k_prep0<<<NB + 3, 256>>>(seq, po, bed, Weo, beo, bnd, Wno, bno);
    cudaEventRecord(ev0, 0);

    // 2 (s1): gemm1p -> cdact reduce
    cudaStreamWaitEvent(s1, ev0, 0);
    k_gemm1p<<<dim3(32, KSPLIT), 256, 0, s1>>>(Wnaf, Wcd);
    cudaEventRecord(ev1, s1);
    k_gemm1r_cd<<<256, 256, 0, s1>>>(bcd);
    cudaEventRecord(evR, s1);

    // 3 (s2): weight prep
    cudaStreamWaitEvent(s2, ev0, 0);
    k_prep_weights<<<dim3(96, 32), dim3(32, 8), 0, s2>>>(Wnd, Wed);
    cudaEventRecord(ev2, s2);

    // 4 (legacy): segment sums  <- profiled slot
    k_segsum<<<dim3(NST, NB, 4), 64>>>(seq);

    // 5 (legacy): finalize (needs segsum + gemm1p partials)
    cudaStreamWaitEvent(0, ev1, 0);
    k_finalize<<<dim3(NM, NB), 256>>>(bnaf);
    cudaEventRecord(evF, 0);

    // 6 (legacy): A/B sections of the GEMM (n-tiles 8..23), then edges
    cudaStreamWaitEvent(0, ev2, 0);
    k_mmagemm<<<dim3(16, 26), 256, GEMM_SMEM>>>(bnd, bed, 8);
    k_edges<<<85 * NB, 256>>>(Weo, beo, out);

    // 7 (s1): ND section (n-tiles 0..7), then node+cls logits (needs cdact in-stream)
    cudaStreamWaitEvent(s1, evF, 0);
    cudaStreamWaitEvent(s1, ev2, 0);
    k_mmagemm<<<dim3(8, 26), 256, GEMM_SMEM, s1>>>(bnd, bed, 0);
    k_nodelogits<<<216, 256, 0, s1>>>(Wno, bno, Wco, bco, out);
    cudaEventRecord(evN, s1);

    // join
    cudaStreamWaitEvent(0, evN, 0);
}